// round 1
// baseline (speedup 1.0000x reference)
#include <cuda_runtime.h>

#define BB 8
#define TT 2048
#define CC 512
#define HH 64
#define SCALE 0.044194173824159216f   // 512^-0.5

// Scratch (device globals: allocation-free per harness rules)
__device__ float g_q[BB * TT * HH];
__device__ float g_k[BB * TT * HH];
__device__ float g_v[BB * TT * HH];
__device__ float g_l[BB * TT];

// ---------------------------------------------------------------------------
// K1: QKV projection.  grid = (B*T/64, 3), block = 256.
// Each block computes a 64x64 output tile of q/k/v = x[16384,512] @ W[512,64].
// ---------------------------------------------------------------------------
__global__ __launch_bounds__(256) void qkv_kernel(
    const float* __restrict__ x, const float* __restrict__ Wq,
    const float* __restrict__ Wk, const float* __restrict__ Wv) {
  __shared__ float xs[64 * 64];
  __shared__ float ws[64 * 64];

  const float* W;
  float* outp;
  if (blockIdx.y == 0)      { W = Wq; outp = g_q; }
  else if (blockIdx.y == 1) { W = Wk; outp = g_k; }
  else                      { W = Wv; outp = g_v; }

  const int row0 = blockIdx.x * 64;
  const int t = threadIdx.x;
  const int ty = t >> 4, tx = t & 15;

  float acc[4][4] = {};

  for (int kc = 0; kc < CC; kc += 64) {
#pragma unroll
    for (int e = 0; e < 4; e++) {
      int idx = t + e * 256;          // 0..1023 float4 slots
      int r = idx >> 4, q = idx & 15;
      *(float4*)&xs[r * 64 + q * 4] =
          *(const float4*)(x + (size_t)(row0 + r) * CC + kc + q * 4);
      *(float4*)&ws[r * 64 + q * 4] =
          *(const float4*)(W + (size_t)(kc + r) * HH + q * 4);
    }
    __syncthreads();

#pragma unroll 16
    for (int k = 0; k < 64; k++) {
      float xv[4];
#pragma unroll
      for (int r = 0; r < 4; r++) xv[r] = xs[(4 * ty + r) * 64 + k];
      float4 wv = *(float4*)&ws[k * 64 + 4 * tx];
#pragma unroll
      for (int r = 0; r < 4; r++) {
        acc[r][0] += xv[r] * wv.x;
        acc[r][1] += xv[r] * wv.y;
        acc[r][2] += xv[r] * wv.z;
        acc[r][3] += xv[r] * wv.w;
      }
    }
    __syncthreads();
  }

#pragma unroll
  for (int r = 0; r < 4; r++) {
    float4 o = make_float4(acc[r][0], acc[r][1], acc[r][2], acc[r][3]);
    *(float4*)(outp + (size_t)(row0 + 4 * ty + r) * HH + 4 * tx) = o;
  }
}

// ---------------------------------------------------------------------------
// K2: attention core.  grid = (T/64, B), block = 256, dynamic smem 49408 B.
// Block owns a 64-row tile; loops causal 64-col tiles.  Writes UNNORMALIZED
// exp-scores to the attention output, accumulates row sums l and O = P@V,
// then writes the normalized O directly.
// Smem layout: Qs[64][64] | KPs[64][65] (K tile, later reused for staged P)
//            | Vs[64][64]
// ---------------------------------------------------------------------------
__global__ __launch_bounds__(256) void attn_kernel(float* __restrict__ out) {
  extern __shared__ float smem[];
  float* Qs  = smem;                 // 4096 floats
  float* KPs = smem + 64 * 64;       // 4160 floats (pad 65 -> no bank conflicts)
  float* Vs  = KPs + 64 * 65;        // 4096 floats

  const int b  = blockIdx.y;
  const int rt = (TT / 64 - 1) - blockIdx.x;  // heaviest tiles launch first
  const int i0 = rt * 64;
  const int t = threadIdx.x;
  const int ty = t >> 4, tx = t & 15;

  const float* qb = g_q + (size_t)b * TT * HH;
  const float* kb = g_k + (size_t)b * TT * HH;
  const float* vb = g_v + (size_t)b * TT * HH;
  float* att = out + (size_t)BB * TT * HH + (size_t)b * TT * TT;

#pragma unroll
  for (int e = 0; e < 4; e++) {
    int idx = t + e * 256;
    int r = idx >> 4, q = idx & 15;
    *(float4*)&Qs[r * 64 + q * 4] =
        *(const float4*)(qb + (size_t)(i0 + r) * HH + q * 4);
  }

  float accO[4][4] = {};
  float lpart[4] = {};
  __syncthreads();

  for (int jt = 0; jt <= rt; jt++) {
    const int j0 = jt * 64;

    // Load K tile (padded-65 rows) and V tile
#pragma unroll
    for (int e = 0; e < 4; e++) {
      int idx = t + e * 256;
      int r = idx >> 4, q = idx & 15;
      float4 kk = *(const float4*)(kb + (size_t)(j0 + r) * HH + q * 4);
      KPs[r * 65 + q * 4 + 0] = kk.x;
      KPs[r * 65 + q * 4 + 1] = kk.y;
      KPs[r * 65 + q * 4 + 2] = kk.z;
      KPs[r * 65 + q * 4 + 3] = kk.w;
      *(float4*)&Vs[r * 64 + q * 4] =
          *(const float4*)(vb + (size_t)(j0 + r) * HH + q * 4);
    }
    __syncthreads();

    // S = Q @ K^T  (64x64x64)
    float accS[4][4] = {};
#pragma unroll 8
    for (int h = 0; h < 64; h++) {
      float qv[4], kv[4];
#pragma unroll
      for (int r = 0; r < 4; r++) qv[r] = Qs[(4 * ty + r) * 64 + h];
#pragma unroll
      for (int c = 0; c < 4; c++) kv[c] = KPs[(4 * tx + c) * 65 + h];
#pragma unroll
      for (int r = 0; r < 4; r++)
#pragma unroll
        for (int c = 0; c < 4; c++) accS[r][c] += qv[r] * kv[c];
    }
    __syncthreads();  // everyone done reading K before overwriting with P

    // P = exp((S + alibi)*scale) with causal mask; write unnormalized to gmem,
    // accumulate row-sum partials, stage P into KPs for the O GEMM.
#pragma unroll
    for (int r = 0; r < 4; r++) {
      const int i = i0 + 4 * ty + r;
      float pv[4];
#pragma unroll
      for (int c = 0; c < 4; c++) {
        const int j = j0 + 4 * tx + c;
        float v = 0.0f;
        if (j <= i) v = __expf((accS[r][c] + (float)(j - i)) * SCALE);
        pv[c] = v;
        lpart[r] += v;
      }
      *(float4*)(att + (size_t)i * TT + j0 + 4 * tx) =
          make_float4(pv[0], pv[1], pv[2], pv[3]);
      KPs[(4 * ty + r) * 65 + 4 * tx + 0] = pv[0];
      KPs[(4 * ty + r) * 65 + 4 * tx + 1] = pv[1];
      KPs[(4 * ty + r) * 65 + 4 * tx + 2] = pv[2];
      KPs[(4 * ty + r) * 65 + 4 * tx + 3] = pv[3];
    }
    __syncthreads();

    // O += P @ V  (64x64x64)
#pragma unroll 8
    for (int k = 0; k < 64; k++) {
      float4 vv = *(float4*)&Vs[k * 64 + 4 * tx];
#pragma unroll
      for (int r = 0; r < 4; r++) {
        float p = KPs[(4 * ty + r) * 65 + k];
        accO[r][0] += p * vv.x;
        accO[r][1] += p * vv.y;
        accO[r][2] += p * vv.z;
        accO[r][3] += p * vv.w;
      }
    }
    __syncthreads();  // before next iteration reloads KPs/Vs
  }

  // Reduce row-sum partials across the 16 tx lanes (butterfly -> all lanes)
#pragma unroll
  for (int r = 0; r < 4; r++) {
    float s = lpart[r];
#pragma unroll
    for (int off = 8; off >= 1; off >>= 1)
      s += __shfl_xor_sync(0xffffffffu, s, off);
    lpart[r] = s;
  }

  if (tx == 0) {
#pragma unroll
    for (int r = 0; r < 4; r++)
      g_l[(size_t)b * TT + i0 + 4 * ty + r] = lpart[r];
  }

  // Normalized output head: out[b, i, :] = O_row / l_row
#pragma unroll
  for (int r = 0; r < 4; r++) {
    float inv = 1.0f / lpart[r];
    float4 o = make_float4(accO[r][0] * inv, accO[r][1] * inv,
                           accO[r][2] * inv, accO[r][3] * inv);
    *(float4*)(out + (size_t)(b * TT + i0 + 4 * ty + r) * HH + 4 * tx) = o;
  }
}

// ---------------------------------------------------------------------------
// K3: normalize attention matrix in place (divide by row sum), and zero the
// upper triangle (those tiles were never written; d_out is poisoned).
// One float4 per thread over B*T*T elements.
// ---------------------------------------------------------------------------
__global__ __launch_bounds__(256) void norm_kernel(float* __restrict__ out) {
  size_t gi = (size_t)blockIdx.x * 256 + threadIdx.x;  // float4 index
  size_t row = gi >> 9;                                // / (T/4 = 512)
  int jq = (int)(gi & 511);
  int i = (int)(row & (TT - 1));
  float inv = 1.0f / g_l[row];
  float4* att = (float4*)(out + (size_t)BB * TT * HH);
  float4 v = att[gi];
  int j = jq * 4;
  v.x = (j     <= i) ? v.x * inv : 0.0f;
  v.y = (j + 1 <= i) ? v.y * inv : 0.0f;
  v.z = (j + 2 <= i) ? v.z * inv : 0.0f;
  v.w = (j + 3 <= i) ? v.w * inv : 0.0f;
  att[gi] = v;
}

// ---------------------------------------------------------------------------
extern "C" void kernel_launch(void* const* d_in, const int* in_sizes, int n_in,
                              void* d_out, int out_size) {
  const float* x  = (const float*)d_in[0];
  const float* Wq = (const float*)d_in[1];
  const float* Wk = (const float*)d_in[2];
  const float* Wv = (const float*)d_in[3];
  float* out = (float*)d_out;

  // K1: QKV projections
  qkv_kernel<<<dim3(BB * TT / 64, 3), 256>>>(x, Wq, Wk, Wv);

  // K2: attention core (49408 B dynamic smem > 48K default)
  const int smem_bytes = (64 * 64 + 64 * 65 + 64 * 64) * (int)sizeof(float);
  cudaFuncSetAttribute(attn_kernel, cudaFuncAttributeMaxDynamicSharedMemorySize,
                       smem_bytes);
  attn_kernel<<<dim3(TT / 64, BB), 256, smem_bytes>>>(out);

  // K3: normalize attention + zero upper triangle
  const int n_f4 = BB * TT * (TT / 4);        // 16M float4
  norm_kernel<<<n_f4 / 256, 256>>>(out);
}

// round 2
// speedup vs baseline: 1.0001x; 1.0001x over previous
#include <cuda_runtime.h>

#define BB 8
#define TT 2048
#define CC 512
#define HH 64
#define SCALE 0.044194173824159216f   // 512^-0.5

// Scratch (device globals: allocation-free per harness rules)
__device__ float g_q[BB * TT * HH];
__device__ float g_k[BB * TT * HH];
__device__ float g_v[BB * TT * HH];
__device__ float g_l[BB * TT];

// ---------------------------------------------------------------------------
// K1: QKV projection.  grid = (B*T/64, 3), block = 256.
// Each block computes a 64x64 output tile of q/k/v = x[16384,512] @ W[512,64].
// ---------------------------------------------------------------------------
__global__ __launch_bounds__(256) void qkv_kernel(
    const float* __restrict__ x, const float* __restrict__ Wq,
    const float* __restrict__ Wk, const float* __restrict__ Wv) {
  __shared__ float xs[64 * 64];
  __shared__ float ws[64 * 64];

  const float* W;
  float* outp;
  if (blockIdx.y == 0)      { W = Wq; outp = g_q; }
  else if (blockIdx.y == 1) { W = Wk; outp = g_k; }
  else                      { W = Wv; outp = g_v; }

  const int row0 = blockIdx.x * 64;
  const int t = threadIdx.x;
  const int ty = t >> 4, tx = t & 15;

  float acc[4][4] = {};

  for (int kc = 0; kc < CC; kc += 64) {
#pragma unroll
    for (int e = 0; e < 4; e++) {
      int idx = t + e * 256;          // 0..1023 float4 slots
      int r = idx >> 4, q = idx & 15;
      *(float4*)&xs[r * 64 + q * 4] =
          *(const float4*)(x + (size_t)(row0 + r) * CC + kc + q * 4);
      *(float4*)&ws[r * 64 + q * 4] =
          *(const float4*)(W + (size_t)(kc + r) * HH + q * 4);
    }
    __syncthreads();

#pragma unroll 16
    for (int k = 0; k < 64; k++) {
      float xv[4];
#pragma unroll
      for (int r = 0; r < 4; r++) xv[r] = xs[(4 * ty + r) * 64 + k];
      float4 wv = *(float4*)&ws[k * 64 + 4 * tx];
#pragma unroll
      for (int r = 0; r < 4; r++) {
        acc[r][0] += xv[r] * wv.x;
        acc[r][1] += xv[r] * wv.y;
        acc[r][2] += xv[r] * wv.z;
        acc[r][3] += xv[r] * wv.w;
      }
    }
    __syncthreads();
  }

#pragma unroll
  for (int r = 0; r < 4; r++) {
    float4 o = make_float4(acc[r][0], acc[r][1], acc[r][2], acc[r][3]);
    *(float4*)(outp + (size_t)(row0 + 4 * ty + r) * HH + 4 * tx) = o;
  }
}

// ---------------------------------------------------------------------------
// K2: attention core.  grid = (T/64, B), block = 256, dynamic smem 49408 B.
// Block owns a 64-row tile; loops causal 64-col tiles.  Writes UNNORMALIZED
// exp-scores to the attention output, accumulates row sums l and O = P@V,
// then writes the normalized O directly.
// Smem layout: Qs[64][64] | KPs[64][65] (K tile, later reused for staged P)
//            | Vs[64][64]
// ---------------------------------------------------------------------------
__global__ __launch_bounds__(256) void attn_kernel(float* __restrict__ out) {
  extern __shared__ float smem[];
  float* Qs  = smem;                 // 4096 floats
  float* KPs = smem + 64 * 64;       // 4160 floats (pad 65 -> no bank conflicts)
  float* Vs  = KPs + 64 * 65;        // 4096 floats

  const int b  = blockIdx.y;
  const int rt = (TT / 64 - 1) - blockIdx.x;  // heaviest tiles launch first
  const int i0 = rt * 64;
  const int t = threadIdx.x;
  const int ty = t >> 4, tx = t & 15;

  const float* qb = g_q + (size_t)b * TT * HH;
  const float* kb = g_k + (size_t)b * TT * HH;
  const float* vb = g_v + (size_t)b * TT * HH;
  float* att = out + (size_t)BB * TT * HH + (size_t)b * TT * TT;

#pragma unroll
  for (int e = 0; e < 4; e++) {
    int idx = t + e * 256;
    int r = idx >> 4, q = idx & 15;
    *(float4*)&Qs[r * 64 + q * 4] =
        *(const float4*)(qb + (size_t)(i0 + r) * HH + q * 4);
  }

  float accO[4][4] = {};
  float lpart[4] = {};
  __syncthreads();

  for (int jt = 0; jt <= rt; jt++) {
    const int j0 = jt * 64;

    // Load K tile (padded-65 rows) and V tile
#pragma unroll
    for (int e = 0; e < 4; e++) {
      int idx = t + e * 256;
      int r = idx >> 4, q = idx & 15;
      float4 kk = *(const float4*)(kb + (size_t)(j0 + r) * HH + q * 4);
      KPs[r * 65 + q * 4 + 0] = kk.x;
      KPs[r * 65 + q * 4 + 1] = kk.y;
      KPs[r * 65 + q * 4 + 2] = kk.z;
      KPs[r * 65 + q * 4 + 3] = kk.w;
      *(float4*)&Vs[r * 64 + q * 4] =
          *(const float4*)(vb + (size_t)(j0 + r) * HH + q * 4);
    }
    __syncthreads();

    // S = Q @ K^T  (64x64x64)
    float accS[4][4] = {};
#pragma unroll 8
    for (int h = 0; h < 64; h++) {
      float qv[4], kv[4];
#pragma unroll
      for (int r = 0; r < 4; r++) qv[r] = Qs[(4 * ty + r) * 64 + h];
#pragma unroll
      for (int c = 0; c < 4; c++) kv[c] = KPs[(4 * tx + c) * 65 + h];
#pragma unroll
      for (int r = 0; r < 4; r++)
#pragma unroll
        for (int c = 0; c < 4; c++) accS[r][c] += qv[r] * kv[c];
    }
    __syncthreads();  // everyone done reading K before overwriting with P

    // P = exp((S + alibi)*scale) with causal mask; write unnormalized to gmem,
    // accumulate row-sum partials, stage P into KPs for the O GEMM.
#pragma unroll
    for (int r = 0; r < 4; r++) {
      const int i = i0 + 4 * ty + r;
      float pv[4];
#pragma unroll
      for (int c = 0; c < 4; c++) {
        const int j = j0 + 4 * tx + c;
        float v = 0.0f;
        if (j <= i) v = __expf((accS[r][c] + (float)(j - i)) * SCALE);
        pv[c] = v;
        lpart[r] += v;
      }
      *(float4*)(att + (size_t)i * TT + j0 + 4 * tx) =
          make_float4(pv[0], pv[1], pv[2], pv[3]);
      KPs[(4 * ty + r) * 65 + 4 * tx + 0] = pv[0];
      KPs[(4 * ty + r) * 65 + 4 * tx + 1] = pv[1];
      KPs[(4 * ty + r) * 65 + 4 * tx + 2] = pv[2];
      KPs[(4 * ty + r) * 65 + 4 * tx + 3] = pv[3];
    }
    __syncthreads();

    // O += P @ V  (64x64x64)
#pragma unroll 8
    for (int k = 0; k < 64; k++) {
      float4 vv = *(float4*)&Vs[k * 64 + 4 * tx];
#pragma unroll
      for (int r = 0; r < 4; r++) {
        float p = KPs[(4 * ty + r) * 65 + k];
        accO[r][0] += p * vv.x;
        accO[r][1] += p * vv.y;
        accO[r][2] += p * vv.z;
        accO[r][3] += p * vv.w;
      }
    }
    __syncthreads();  // before next iteration reloads KPs/Vs
  }

  // Reduce row-sum partials across the 16 tx lanes (butterfly -> all lanes)
#pragma unroll
  for (int r = 0; r < 4; r++) {
    float s = lpart[r];
#pragma unroll
    for (int off = 8; off >= 1; off >>= 1)
      s += __shfl_xor_sync(0xffffffffu, s, off);
    lpart[r] = s;
  }

  if (tx == 0) {
#pragma unroll
    for (int r = 0; r < 4; r++)
      g_l[(size_t)b * TT + i0 + 4 * ty + r] = lpart[r];
  }

  // Normalized output head: out[b, i, :] = O_row / l_row
#pragma unroll
  for (int r = 0; r < 4; r++) {
    float inv = 1.0f / lpart[r];
    float4 o = make_float4(accO[r][0] * inv, accO[r][1] * inv,
                           accO[r][2] * inv, accO[r][3] * inv);
    *(float4*)(out + (size_t)(b * TT + i0 + 4 * ty + r) * HH + 4 * tx) = o;
  }
}

// ---------------------------------------------------------------------------
// K3: normalize attention matrix in place (divide by row sum), and zero the
// upper triangle (those tiles were never written; d_out is poisoned).
// One float4 per thread over B*T*T elements.
// ---------------------------------------------------------------------------
__global__ __launch_bounds__(256) void norm_kernel(float* __restrict__ out) {
  size_t gi = (size_t)blockIdx.x * 256 + threadIdx.x;  // float4 index
  size_t row = gi >> 9;                                // / (T/4 = 512)
  int jq = (int)(gi & 511);
  int i = (int)(row & (TT - 1));
  float inv = 1.0f / g_l[row];
  float4* att = (float4*)(out + (size_t)BB * TT * HH);
  float4 v = att[gi];
  int j = jq * 4;
  v.x = (j     <= i) ? v.x * inv : 0.0f;
  v.y = (j + 1 <= i) ? v.y * inv : 0.0f;
  v.z = (j + 2 <= i) ? v.z * inv : 0.0f;
  v.w = (j + 3 <= i) ? v.w * inv : 0.0f;
  att[gi] = v;
}

// ---------------------------------------------------------------------------
extern "C" void kernel_launch(void* const* d_in, const int* in_sizes, int n_in,
                              void* d_out, int out_size) {
  const float* x  = (const float*)d_in[0];
  const float* Wq = (const float*)d_in[1];
  const float* Wk = (const float*)d_in[2];
  const float* Wv = (const float*)d_in[3];
  float* out = (float*)d_out;

  // K1: QKV projections
  qkv_kernel<<<dim3(BB * TT / 64, 3), 256>>>(x, Wq, Wk, Wv);

  // K2: attention core (49408 B dynamic smem > 48K default)
  const int smem_bytes = (64 * 64 + 64 * 65 + 64 * 64) * (int)sizeof(float);
  cudaFuncSetAttribute(attn_kernel, cudaFuncAttributeMaxDynamicSharedMemorySize,
                       smem_bytes);
  attn_kernel<<<dim3(TT / 64, BB), 256, smem_bytes>>>(out);

  // K3: normalize attention + zero upper triangle
  const int n_f4 = BB * TT * (TT / 4);        // 16M float4
  norm_kernel<<<n_f4 / 256, 256>>>(out);
}

// round 4
// speedup vs baseline: 2.1946x; 2.1944x over previous
#include <cuda_runtime.h>
#include <cuda_bf16.h>
#include <stdint.h>

#define BB 8
#define TT 2048
#define CC 512
#define HH 64
#define SCALEF 0.044194173824159216f   // 512^-0.5

// ---------------- scratch (device globals: allocation-free) ----------------
__device__ __nv_bfloat16 g_qhi[BB*TT*HH], g_qlo[BB*TT*HH];
__device__ __nv_bfloat16 g_khi[BB*TT*HH], g_klo[BB*TT*HH];
__device__ __nv_bfloat16 g_vhi[BB*TT*HH], g_vlo[BB*TT*HH];
__device__ __nv_bfloat16 g_wthi[3*HH*CC], g_wtlo[3*HH*CC];   // [w][h][c]
__device__ float g_opar[2ll*BB*TT*HH];
__device__ float g_lpar[2*BB*TT];
__device__ float g_l[BB*TT];

// ---------------- helpers ----------------
__device__ __forceinline__ uint32_t su(const void* p) {
  uint32_t a;
  asm("{ .reg .u64 t; cvta.to.shared.u64 t, %1; cvt.u32.u64 %0, t; }" : "=r"(a) : "l"(p));
  return a;
}
__device__ __forceinline__ void ldsm4(uint32_t* r, uint32_t a) {
  asm volatile("ldmatrix.sync.aligned.m8n8.x4.shared.b16 {%0,%1,%2,%3}, [%4];"
    : "=r"(r[0]), "=r"(r[1]), "=r"(r[2]), "=r"(r[3]) : "r"(a));
}
__device__ __forceinline__ void ldsm4t(uint32_t* r, uint32_t a) {
  asm volatile("ldmatrix.sync.aligned.m8n8.x4.trans.shared.b16 {%0,%1,%2,%3}, [%4];"
    : "=r"(r[0]), "=r"(r[1]), "=r"(r[2]), "=r"(r[3]) : "r"(a));
}
__device__ __forceinline__ void mma16816(float* d, const uint32_t* a, uint32_t b0, uint32_t b1) {
  asm volatile("mma.sync.aligned.m16n8k16.row.col.f32.bf16.bf16.f32 "
    "{%0,%1,%2,%3}, {%4,%5,%6,%7}, {%8,%9}, {%0,%1,%2,%3};"
    : "+f"(d[0]), "+f"(d[1]), "+f"(d[2]), "+f"(d[3])
    : "r"(a[0]), "r"(a[1]), "r"(a[2]), "r"(a[3]), "r"(b0), "r"(b1));
}
__device__ __forceinline__ void split_pack(float a, float b, uint32_t& hi, uint32_t& lo) {
  __nv_bfloat162 h = __floats2bfloat162_rn(a, b);
  __nv_bfloat162 l = __floats2bfloat162_rn(a - __bfloat162float(h.x),
                                           b - __bfloat162float(h.y));
  hi = *reinterpret_cast<uint32_t*>(&h);
  lo = *reinterpret_cast<uint32_t*>(&l);
}

// ---------------- K0: weight transpose + split ----------------
__global__ void k0(const float* __restrict__ Wq, const float* __restrict__ Wk,
                   const float* __restrict__ Wv) {
  int idx = blockIdx.x * 256 + threadIdx.x;          // < 3*64*512
  int w = idx >> 15, rem = idx & 32767, h = rem >> 9, c = rem & 511;
  const float* W = (w == 0) ? Wq : ((w == 1) ? Wk : Wv);
  float v = W[(size_t)c * HH + h];
  __nv_bfloat16 hi = __float2bfloat16(v);
  g_wthi[idx] = hi;
  g_wtlo[idx] = __float2bfloat16(v - __bfloat162float(hi));
}

// ---------------- K1: fused QKV on HMMA. grid=128, block=256 ----------------
// smem: Xh[128][72] Xl[128][72] at 0/18432; per o: Wh[64][72]+Wl at 36864+o*18432
__global__ __launch_bounds__(256, 1) void qkv(const float* __restrict__ x) {
  extern __shared__ char S[];
  const uint32_t XH = 0, XL = 18432, WB = 36864;
  const int t = threadIdx.x, w = t >> 5, lane = t & 31;
  const int g = lane >> 2, tq = lane & 3;
  const int row0 = blockIdx.x * 128;
  const uint32_t sb = su(S);
  const uint32_t arow = 16 * w + (lane & 15), aoff8 = (lane >> 4) * 8;
  const uint32_t brow = (lane & 7) + ((lane >> 4) & 1) * 8;
  const uint32_t boff8 = ((lane >> 3) & 1) * 8;

  float acc[3][8][4] = {};

  for (int kci = 0; kci < 8; kci++) {
    __syncthreads();
#pragma unroll
    for (int e = 0; e < 16; e++) {
      int idx = t + e * 256, r = idx >> 5, cp = idx & 31;
      float2 xv = *(const float2*)(x + (size_t)(row0 + r) * CC + kci * 64 + cp * 2);
      uint32_t hi, lo; split_pack(xv.x, xv.y, hi, lo);
      uint32_t off = (uint32_t)(r * 144 + cp * 4);
      *(uint32_t*)(S + XH + off) = hi;
      *(uint32_t*)(S + XL + off) = lo;
    }
#pragma unroll
    for (int e = 0; e < 24; e++) {
      int idx = t + e * 256;                 // < 6144
      int o = idx >> 11, r2 = idx & 2047, h = r2 >> 5, cp = r2 & 31;
      uint32_t gi = (uint32_t)(o * 16384 + h * 256 + kci * 32 + cp);
      uint32_t off = WB + o * 18432 + h * 144 + cp * 4;
      *(uint32_t*)(S + off)        = ((const uint32_t*)g_wthi)[gi];
      *(uint32_t*)(S + off + 9216) = ((const uint32_t*)g_wtlo)[gi];
    }
    __syncthreads();

#pragma unroll
    for (int s = 0; s < 4; s++) {
      uint32_t ah[4], al[4];
      uint32_t qa = sb + XH + arow * 144 + (s * 16 + aoff8) * 2;
      ldsm4(ah, qa);
      ldsm4(al, qa + XL);
#pragma unroll
      for (int o = 0; o < 3; o++) {
        uint32_t base = sb + WB + o * 18432;
#pragma unroll
        for (int p = 0; p < 3 + 1; p++) {
          uint32_t bh[4], bl[4];
          uint32_t ka = base + (p * 16 + brow) * 144 + (s * 16 + boff8) * 2;
          ldsm4(bh, ka);
          ldsm4(bl, ka + 9216);
          mma16816(acc[o][2*p],   ah, bh[0], bh[1]);
          mma16816(acc[o][2*p],   al, bh[0], bh[1]);
          mma16816(acc[o][2*p],   ah, bl[0], bl[1]);
          mma16816(acc[o][2*p+1], ah, bh[2], bh[3]);
          mma16816(acc[o][2*p+1], al, bh[2], bh[3]);
          mma16816(acc[o][2*p+1], ah, bl[2], bl[3]);
        }
      }
    }
  }

  const size_t ra = (size_t)(row0 + 16 * w + g), rb = ra + 8;
#pragma unroll
  for (int o = 0; o < 3; o++) {
    uint32_t* dh = (uint32_t*)(o == 0 ? g_qhi : (o == 1 ? g_khi : g_vhi));
    uint32_t* dl = (uint32_t*)(o == 0 ? g_qlo : (o == 1 ? g_klo : g_vlo));
#pragma unroll
    for (int nf = 0; nf < 8; nf++) {
      uint32_t hi, lo;
      split_pack(acc[o][nf][0], acc[o][nf][1], hi, lo);
      dh[ra * 32 + nf * 4 + tq] = hi;
      dl[ra * 32 + nf * 4 + tq] = lo;
      split_pack(acc[o][nf][2], acc[o][nf][3], hi, lo);
      dh[rb * 32 + nf * 4 + tq] = hi;
      dl[rb * 32 + nf * 4 + tq] = lo;
    }
  }
}

// ---------------- K2: attention core. grid=(32,8), block=256 ----------------
// smem: Qh[128][72]@0 Ql@18432 Kh[64][72]@36864 Kl@46080 Vh@55296 Vl@64512
__global__ __launch_bounds__(256, 2) void attn(float* __restrict__ out) {
  extern __shared__ char S[];
  const uint32_t QH = 0, QL = 18432, KH = 36864, VH = 55296;
  const int t = threadIdx.x, w = t >> 5, lane = t & 31;
  const int g = lane >> 2, tq = lane & 3;
  const int xi = blockIdx.x, b = blockIdx.y;
  const int rt = 15 - (xi >> 1), par = xi & 1;
  const int i0 = rt * 128;
  const uint32_t sb = su(S);

  // load Q tile
#pragma unroll
  for (int e = 0; e < 16; e++) {
    int idx = t + e * 256, r = idx >> 5, cp = idx & 31;
    size_t gi = (size_t)(b * TT + i0 + r) * 32 + cp;
    uint32_t off = (uint32_t)(r * 144 + cp * 4);
    *(uint32_t*)(S + QH + off) = ((const uint32_t*)g_qhi)[gi];
    *(uint32_t*)(S + QL + off) = ((const uint32_t*)g_qlo)[gi];
  }

  float oa[8][4] = {};
  float la = 0.0f, lb = 0.0f;
  const int ia = i0 + 16 * w + g, ib = ia + 8;
  float* att = out + (size_t)BB * TT * HH + (size_t)b * TT * TT;

  const uint32_t arow = 16 * w + (lane & 15), aoff8 = (lane >> 4) * 8;
  const uint32_t brow = (lane & 7) + ((lane >> 4) & 1) * 8;   // non-trans B
  const uint32_t boff8 = ((lane >> 3) & 1) * 8;
  const uint32_t vrow = (lane & 7) + ((lane >> 3) & 1) * 8;   // trans B
  const uint32_t voff8 = ((lane >> 4) & 1) * 8;

  for (int jt = par; jt <= 2 * rt + 1; jt += 2) {
    const int j0 = jt * 64;
    __syncthreads();
#pragma unroll
    for (int e = 0; e < 8; e++) {
      int idx = t + e * 256, r = idx >> 5, cp = idx & 31;
      size_t gi = (size_t)(b * TT + j0 + r) * 32 + cp;
      uint32_t off = (uint32_t)(r * 144 + cp * 4);
      *(uint32_t*)(S + KH + off)        = ((const uint32_t*)g_khi)[gi];
      *(uint32_t*)(S + KH + off + 9216) = ((const uint32_t*)g_klo)[gi];
      *(uint32_t*)(S + VH + off)        = ((const uint32_t*)g_vhi)[gi];
      *(uint32_t*)(S + VH + off + 9216) = ((const uint32_t*)g_vlo)[gi];
    }
    __syncthreads();

    // ---- S = Q K^T (3-term bf16 split) ----
    float sa[8][4] = {};
#pragma unroll
    for (int s = 0; s < 4; s++) {
      uint32_t ah[4], al[4];
      uint32_t qa = sb + QH + arow * 144 + (s * 16 + aoff8) * 2;
      ldsm4(ah, qa);
      ldsm4(al, qa + QL);
#pragma unroll
      for (int p = 0; p < 4; p++) {
        uint32_t bh[4], bl[4];
        uint32_t ka = sb + KH + (p * 16 + brow) * 144 + (s * 16 + boff8) * 2;
        ldsm4(bh, ka);
        ldsm4(bl, ka + 9216);
        mma16816(sa[2*p],   ah, bh[0], bh[1]);
        mma16816(sa[2*p],   al, bh[0], bh[1]);
        mma16816(sa[2*p],   ah, bl[0], bl[1]);
        mma16816(sa[2*p+1], ah, bh[2], bh[3]);
        mma16816(sa[2*p+1], al, bh[2], bh[3]);
        mma16816(sa[2*p+1], ah, bl[2], bl[3]);
      }
    }

    // ---- epilogue: exp + ALiBi + causal mask; write unnormalized att ----
#pragma unroll
    for (int nf = 0; nf < 8; nf++) {
      int j = j0 + nf * 8 + tq * 2;
      float p00 = (j     <= ia) ? __expf((sa[nf][0] + (float)(j     - ia)) * SCALEF) : 0.0f;
      float p01 = (j + 1 <= ia) ? __expf((sa[nf][1] + (float)(j + 1 - ia)) * SCALEF) : 0.0f;
      float p10 = (j     <= ib) ? __expf((sa[nf][2] + (float)(j     - ib)) * SCALEF) : 0.0f;
      float p11 = (j + 1 <= ib) ? __expf((sa[nf][3] + (float)(j + 1 - ib)) * SCALEF) : 0.0f;
      *(float2*)(att + (size_t)ia * TT + j) = make_float2(p00, p01);
      *(float2*)(att + (size_t)ib * TT + j) = make_float2(p10, p11);
      la += p00 + p01;
      lb += p10 + p11;
      sa[nf][0] = p00; sa[nf][1] = p01; sa[nf][2] = p10; sa[nf][3] = p11;
    }

    // ---- O += P V (P fragments built in registers from sa) ----
#pragma unroll
    for (int s2 = 0; s2 < 4; s2++) {
      uint32_t ah[4], al[4];
      split_pack(sa[2*s2][0],   sa[2*s2][1],   ah[0], al[0]);
      split_pack(sa[2*s2][2],   sa[2*s2][3],   ah[1], al[1]);
      split_pack(sa[2*s2+1][0], sa[2*s2+1][1], ah[2], al[2]);
      split_pack(sa[2*s2+1][2], sa[2*s2+1][3], ah[3], al[3]);
#pragma unroll
      for (int p = 0; p < 4; p++) {
        uint32_t bh[4], bl[4];
        uint32_t va = sb + VH + (s2 * 16 + vrow) * 144 + (p * 16 + voff8) * 2;
        ldsm4t(bh, va);
        ldsm4t(bl, va + 9216);
        mma16816(oa[2*p],   ah, bh[0], bh[1]);
        mma16816(oa[2*p],   al, bh[0], bh[1]);
        mma16816(oa[2*p],   ah, bl[0], bl[1]);
        mma16816(oa[2*p+1], ah, bh[2], bh[3]);
        mma16816(oa[2*p+1], al, bh[2], bh[3]);
        mma16816(oa[2*p+1], ah, bl[2], bl[3]);
      }
    }
  }

  // quad-reduce row sums (tq lanes 0..3 share a row)
  la += __shfl_xor_sync(0xffffffffu, la, 1);
  la += __shfl_xor_sync(0xffffffffu, la, 2);
  lb += __shfl_xor_sync(0xffffffffu, lb, 1);
  lb += __shfl_xor_sync(0xffffffffu, lb, 2);
  if (tq == 0) {
    g_lpar[par * BB * TT + b * TT + ia] = la;
    g_lpar[par * BB * TT + b * TT + ib] = lb;
  }
  float* op = g_opar + (size_t)par * BB * TT * HH;
#pragma unroll
  for (int nf = 0; nf < 8; nf++) {
    int c = nf * 8 + tq * 2;
    *(float2*)(op + ((size_t)b * TT + ia) * HH + c) = make_float2(oa[nf][0], oa[nf][1]);
    *(float2*)(op + ((size_t)b * TT + ib) * HH + c) = make_float2(oa[nf][2], oa[nf][3]);
  }
}

// ---------------- Kc: combine parities, normalize O, emit row sums ----------
__global__ void kc(float* __restrict__ out) {
  int idx = blockIdx.x * 256 + threadIdx.x;   // float4 index < 262144
  int row = idx >> 4;
  float l = g_lpar[row] + g_lpar[BB * TT + row];
  float inv = 1.0f / l;
  float4 a = ((const float4*)g_opar)[idx];
  float4 c = ((const float4*)g_opar)[(BB * TT * HH / 4) + idx];
  ((float4*)out)[idx] = make_float4((a.x + c.x) * inv, (a.y + c.y) * inv,
                                    (a.z + c.z) * inv, (a.w + c.w) * inv);
  if ((idx & 15) == 0) g_l[row] = l;
}

// ---------------- K3: normalize att lower triangle, zero upper --------------
__global__ __launch_bounds__(256) void k3(float* __restrict__ out) {
  const int rt = 15 - (int)(blockIdx.x >> 2), sl = blockIdx.x & 3, b = blockIdx.y;
  __shared__ float linv[128];
  if (threadIdx.x < 128)
    linv[threadIdx.x] = 1.0f / g_l[b * TT + rt * 128 + threadIdx.x];
  __syncthreads();
  float4* att = (float4*)(out + (size_t)BB * TT * HH + (size_t)b * TT * TT);
  const int cend = (rt + 1) * 32;             // f4 columns that were written
  for (int idx = threadIdx.x; idx < 128 * 128; idx += 256) {
    int r = idx >> 7, c = (idx & 127) + sl * 128;
    size_t gi = (size_t)(rt * 128 + r) * 512 + c;
    float4 v;
    if (c < cend) {
      v = att[gi];
      float iv = linv[r];
      v.x *= iv; v.y *= iv; v.z *= iv; v.w *= iv;
    } else {
      v = make_float4(0, 0, 0, 0);
    }
    att[gi] = v;
  }
}

// ---------------------------------------------------------------------------
extern "C" void kernel_launch(void* const* d_in, const int* in_sizes, int n_in,
                              void* d_out, int out_size) {
  const float* x  = (const float*)d_in[0];
  const float* Wq = (const float*)d_in[1];
  const float* Wk = (const float*)d_in[2];
  const float* Wv = (const float*)d_in[3];
  float* out = (float*)d_out;

  k0<<<384, 256>>>(Wq, Wk, Wv);

  cudaFuncSetAttribute(qkv, cudaFuncAttributeMaxDynamicSharedMemorySize, 92160);
  qkv<<<128, 256, 92160>>>(x);

  cudaFuncSetAttribute(attn, cudaFuncAttributeMaxDynamicSharedMemorySize, 73728);
  attn<<<dim3(32, 8), 256, 73728>>>(out);

  kc<<<1024, 256>>>(out);
  k3<<<dim3(64, 8), 256>>>(out);
}

// round 5
// speedup vs baseline: 2.5336x; 1.1545x over previous
#include <cuda_runtime.h>
#include <cuda_bf16.h>
#include <stdint.h>

#define BB 8
#define TT 2048
#define CC 512
#define HH 64
#define SCALEF 0.044194173824159216f   // 512^-0.5

// ---------------- scratch (device globals: allocation-free) ----------------
__device__ __nv_bfloat16 g_qhi[BB*TT*HH], g_qlo[BB*TT*HH];
__device__ __nv_bfloat16 g_khi[BB*TT*HH], g_klo[BB*TT*HH];
__device__ __nv_bfloat16 g_vhi[BB*TT*HH], g_vlo[BB*TT*HH];
__device__ __nv_bfloat16 g_wthi[3*HH*CC], g_wtlo[3*HH*CC];   // [w][h][c]
__device__ float g_opar[4ll*BB*TT*HH];
__device__ float g_lpar[4*BB*TT];
__device__ float g_l[BB*TT];

// ---------------- helpers ----------------
__device__ __forceinline__ uint32_t su(const void* p) {
  uint32_t a;
  asm("{ .reg .u64 t; cvta.to.shared.u64 t, %1; cvt.u32.u64 %0, t; }" : "=r"(a) : "l"(p));
  return a;
}
__device__ __forceinline__ void ldsm4(uint32_t* r, uint32_t a) {
  asm volatile("ldmatrix.sync.aligned.m8n8.x4.shared.b16 {%0,%1,%2,%3}, [%4];"
    : "=r"(r[0]), "=r"(r[1]), "=r"(r[2]), "=r"(r[3]) : "r"(a));
}
__device__ __forceinline__ void ldsm4t(uint32_t* r, uint32_t a) {
  asm volatile("ldmatrix.sync.aligned.m8n8.x4.trans.shared.b16 {%0,%1,%2,%3}, [%4];"
    : "=r"(r[0]), "=r"(r[1]), "=r"(r[2]), "=r"(r[3]) : "r"(a));
}
__device__ __forceinline__ void mma16816(float* d, const uint32_t* a, uint32_t b0, uint32_t b1) {
  asm volatile("mma.sync.aligned.m16n8k16.row.col.f32.bf16.bf16.f32 "
    "{%0,%1,%2,%3}, {%4,%5,%6,%7}, {%8,%9}, {%0,%1,%2,%3};"
    : "+f"(d[0]), "+f"(d[1]), "+f"(d[2]), "+f"(d[3])
    : "r"(a[0]), "r"(a[1]), "r"(a[2]), "r"(a[3]), "r"(b0), "r"(b1));
}
__device__ __forceinline__ void split_pack(float a, float b, uint32_t& hi, uint32_t& lo) {
  __nv_bfloat162 h = __floats2bfloat162_rn(a, b);
  __nv_bfloat162 l = __floats2bfloat162_rn(a - __bfloat162float(h.x),
                                           b - __bfloat162float(h.y));
  hi = *reinterpret_cast<uint32_t*>(&h);
  lo = *reinterpret_cast<uint32_t*>(&l);
}
__device__ __forceinline__ void cpa16(uint32_t s, const void* g) {
  asm volatile("cp.async.cg.shared.global [%0], [%1], 16;" :: "r"(s), "l"(g) : "memory");
}
#define CP_COMMIT() asm volatile("cp.async.commit_group;" ::: "memory")
#define CP_WAIT0()  asm volatile("cp.async.wait_group 0;" ::: "memory")

// ---------------- K0: weight transpose + split ----------------
__global__ void k0(const float* __restrict__ Wq, const float* __restrict__ Wk,
                   const float* __restrict__ Wv) {
  int idx = blockIdx.x * 256 + threadIdx.x;          // < 3*64*512
  int w = idx >> 15, rem = idx & 32767, h = rem >> 9, c = rem & 511;
  const float* W = (w == 0) ? Wq : ((w == 1) ? Wk : Wv);
  float v = W[(size_t)c * HH + h];
  __nv_bfloat16 hi = __float2bfloat16(v);
  g_wthi[idx] = hi;
  g_wtlo[idx] = __float2bfloat16(v - __bfloat162float(hi));
}

// ---------------- K1: fused QKV on HMMA. grid=128, block=256 ----------------
__global__ __launch_bounds__(256, 1) void qkv(const float* __restrict__ x) {
  extern __shared__ char S[];
  const uint32_t XH = 0, XL = 18432, WB = 36864;
  const int t = threadIdx.x, w = t >> 5, lane = t & 31;
  const int g = lane >> 2, tq = lane & 3;
  const int row0 = blockIdx.x * 128;
  const uint32_t sb = su(S);
  const uint32_t arow = 16 * w + (lane & 15), aoff8 = (lane >> 4) * 8;
  const uint32_t brow = (lane & 7) + ((lane >> 4) & 1) * 8;
  const uint32_t boff8 = ((lane >> 3) & 1) * 8;

  float acc[3][8][4] = {};

  for (int kci = 0; kci < 8; kci++) {
    __syncthreads();
#pragma unroll
    for (int e = 0; e < 16; e++) {
      int idx = t + e * 256, r = idx >> 5, cp = idx & 31;
      float2 xv = *(const float2*)(x + (size_t)(row0 + r) * CC + kci * 64 + cp * 2);
      uint32_t hi, lo; split_pack(xv.x, xv.y, hi, lo);
      uint32_t off = (uint32_t)(r * 144 + cp * 4);
      *(uint32_t*)(S + XH + off) = hi;
      *(uint32_t*)(S + XL + off) = lo;
    }
#pragma unroll
    for (int e = 0; e < 24; e++) {
      int idx = t + e * 256;                 // < 6144
      int o = idx >> 11, r2 = idx & 2047, h = r2 >> 5, cp = r2 & 31;
      uint32_t gi = (uint32_t)(o * 16384 + h * 256 + kci * 32 + cp);
      uint32_t off = WB + o * 18432 + h * 144 + cp * 4;
      *(uint32_t*)(S + off)        = ((const uint32_t*)g_wthi)[gi];
      *(uint32_t*)(S + off + 9216) = ((const uint32_t*)g_wtlo)[gi];
    }
    __syncthreads();

#pragma unroll
    for (int s = 0; s < 4; s++) {
      uint32_t ah[4], al[4];
      uint32_t qa = sb + XH + arow * 144 + (s * 16 + aoff8) * 2;
      ldsm4(ah, qa);
      ldsm4(al, qa + XL);
#pragma unroll
      for (int o = 0; o < 3; o++) {
        uint32_t base = sb + WB + o * 18432;
#pragma unroll
        for (int p = 0; p < 4; p++) {
          uint32_t bh[4], bl[4];
          uint32_t ka = base + (p * 16 + brow) * 144 + (s * 16 + boff8) * 2;
          ldsm4(bh, ka);
          ldsm4(bl, ka + 9216);
          mma16816(acc[o][2*p],   ah, bh[0], bh[1]);
          mma16816(acc[o][2*p],   al, bh[0], bh[1]);
          mma16816(acc[o][2*p],   ah, bl[0], bl[1]);
          mma16816(acc[o][2*p+1], ah, bh[2], bh[3]);
          mma16816(acc[o][2*p+1], al, bh[2], bh[3]);
          mma16816(acc[o][2*p+1], ah, bl[2], bl[3]);
        }
      }
    }
  }

  const size_t ra = (size_t)(row0 + 16 * w + g), rb = ra + 8;
#pragma unroll
  for (int o = 0; o < 3; o++) {
    uint32_t* dh = (uint32_t*)(o == 0 ? g_qhi : (o == 1 ? g_khi : g_vhi));
    uint32_t* dl = (uint32_t*)(o == 0 ? g_qlo : (o == 1 ? g_klo : g_vlo));
#pragma unroll
    for (int nf = 0; nf < 8; nf++) {
      uint32_t hi, lo;
      split_pack(acc[o][nf][0], acc[o][nf][1], hi, lo);
      dh[ra * 32 + nf * 4 + tq] = hi;
      dl[ra * 32 + nf * 4 + tq] = lo;
      split_pack(acc[o][nf][2], acc[o][nf][3], hi, lo);
      dh[rb * 32 + nf * 4 + tq] = hi;
      dl[rb * 32 + nf * 4 + tq] = lo;
    }
  }
}

// ---------------- K2: attention core. grid=(40,8), block=256 ----------------
// Chunked causal work: block -> (rt, chunk of <=8 jt tiles); heavy rt first.
// smem: Qh[128][72]@0 Ql@18432 | KV buf0@36864 buf1@73728
//   each KV buf: Kh@+0 Kl@+9216 Vh@+18432 Vl@+27648  (64 rows x 144B)
__global__ __launch_bounds__(256, 1) void attn(float* __restrict__ out) {
  extern __shared__ char S[];
  const uint32_t QH = 0, QL = 18432, KV0 = 36864, KVSZ = 36864;
  const int t = threadIdx.x, w = t >> 5, lane = t & 31;
  const int g = lane >> 2, tq = lane & 3;
  const int b = blockIdx.y;

  // map blockIdx.x -> (rt, chunk), rt=15 first
  int bx = blockIdx.x, rt = 15;
  for (;; rt--) { int nc = (2 * rt + 9) >> 3; if (bx < nc) break; bx -= nc; }
  const int chunk = bx;
  const int jt0 = chunk * 8;
  const int ntiles = min(8, 2 * rt + 2 - jt0);
  const int i0 = rt * 128;
  const uint32_t sb = su(S);

  // async-load Q tile (2048 x 16B chunks across both arrays)
#pragma unroll
  for (int e = 0; e < 4; e++) {
    int idx = t + e * 256, r = idx >> 3, c8 = idx & 7;   // idx < 1024
    size_t gb = ((size_t)(b * TT + i0 + r) * 64 + c8 * 8) * 2;
    uint32_t off = (uint32_t)(r * 144 + c8 * 16);
    cpa16(sb + QH + off, (const char*)g_qhi + gb);
    cpa16(sb + QL + off, (const char*)g_qlo + gb);
  }
  // prefetch first KV tile into buf0
  {
    const int j0 = jt0 * 64;
#pragma unroll
    for (int e = 0; e < 2; e++) {
      int idx = t + e * 256, r = idx >> 3, c8 = idx & 7;  // idx < 512
      size_t gb = ((size_t)(b * TT + j0 + r) * 64 + c8 * 8) * 2;
      uint32_t off = KV0 + (uint32_t)(r * 144 + c8 * 16);
      cpa16(sb + off,         (const char*)g_khi + gb);
      cpa16(sb + off + 9216,  (const char*)g_klo + gb);
      cpa16(sb + off + 18432, (const char*)g_vhi + gb);
      cpa16(sb + off + 27648, (const char*)g_vlo + gb);
    }
  }
  CP_COMMIT();

  float oa[8][4] = {};
  float la = 0.0f, lb = 0.0f;
  const int ia = i0 + 16 * w + g, ib = ia + 8;
  float* att = out + (size_t)BB * TT * HH + (size_t)b * TT * TT;

  const uint32_t arow = 16 * w + (lane & 15), aoff8 = (lane >> 4) * 8;
  const uint32_t brow = (lane & 7) + ((lane >> 4) & 1) * 8;   // non-trans B
  const uint32_t boff8 = ((lane >> 3) & 1) * 8;
  const uint32_t vrow = (lane & 7) + ((lane >> 3) & 1) * 8;   // trans B
  const uint32_t voff8 = ((lane >> 4) & 1) * 8;

  for (int ti = 0; ti < ntiles; ti++) {
    const int j0 = (jt0 + ti) * 64;
    CP_WAIT0();
    __syncthreads();

    // prefetch next tile into other buffer
    if (ti + 1 < ntiles) {
      const int jn = (jt0 + ti + 1) * 64;
      const uint32_t nb = KV0 + ((ti + 1) & 1) * KVSZ;
#pragma unroll
      for (int e = 0; e < 2; e++) {
        int idx = t + e * 256, r = idx >> 3, c8 = idx & 7;
        size_t gb = ((size_t)(b * TT + jn + r) * 64 + c8 * 8) * 2;
        uint32_t off = nb + (uint32_t)(r * 144 + c8 * 16);
        cpa16(sb + off,         (const char*)g_khi + gb);
        cpa16(sb + off + 9216,  (const char*)g_klo + gb);
        cpa16(sb + off + 18432, (const char*)g_vhi + gb);
        cpa16(sb + off + 27648, (const char*)g_vlo + gb);
      }
    }
    CP_COMMIT();

    const uint32_t KB = KV0 + (ti & 1) * KVSZ;        // Khi base
    const uint32_t VB = KB + 18432;                    // Vhi base

    // ---- S = Q K^T (3-term bf16 split) ----
    float sa[8][4] = {};
#pragma unroll
    for (int s = 0; s < 4; s++) {
      uint32_t ah[4], al[4];
      uint32_t qa = sb + QH + arow * 144 + (s * 16 + aoff8) * 2;
      ldsm4(ah, qa);
      ldsm4(al, qa + QL);
#pragma unroll
      for (int p = 0; p < 4; p++) {
        uint32_t bh[4], bl[4];
        uint32_t ka = sb + KB + (p * 16 + brow) * 144 + (s * 16 + boff8) * 2;
        ldsm4(bh, ka);
        ldsm4(bl, ka + 9216);
        mma16816(sa[2*p],   ah, bh[0], bh[1]);
        mma16816(sa[2*p],   al, bh[0], bh[1]);
        mma16816(sa[2*p],   ah, bl[0], bl[1]);
        mma16816(sa[2*p+1], ah, bh[2], bh[3]);
        mma16816(sa[2*p+1], al, bh[2], bh[3]);
        mma16816(sa[2*p+1], ah, bl[2], bl[3]);
      }
    }

    // ---- epilogue: exp + ALiBi + causal mask; write unnormalized att ----
#pragma unroll
    for (int nf = 0; nf < 8; nf++) {
      int j = j0 + nf * 8 + tq * 2;
      float p00 = (j     <= ia) ? __expf((sa[nf][0] + (float)(j     - ia)) * SCALEF) : 0.0f;
      float p01 = (j + 1 <= ia) ? __expf((sa[nf][1] + (float)(j + 1 - ia)) * SCALEF) : 0.0f;
      float p10 = (j     <= ib) ? __expf((sa[nf][2] + (float)(j     - ib)) * SCALEF) : 0.0f;
      float p11 = (j + 1 <= ib) ? __expf((sa[nf][3] + (float)(j + 1 - ib)) * SCALEF) : 0.0f;
      *(float2*)(att + (size_t)ia * TT + j) = make_float2(p00, p01);
      *(float2*)(att + (size_t)ib * TT + j) = make_float2(p10, p11);
      la += p00 + p01;
      lb += p10 + p11;
      sa[nf][0] = p00; sa[nf][1] = p01; sa[nf][2] = p10; sa[nf][3] = p11;
    }

    // ---- O += P V (P fragments built in registers) ----
#pragma unroll
    for (int s2 = 0; s2 < 4; s2++) {
      uint32_t ah[4], al[4];
      split_pack(sa[2*s2][0],   sa[2*s2][1],   ah[0], al[0]);
      split_pack(sa[2*s2][2],   sa[2*s2][3],   ah[1], al[1]);
      split_pack(sa[2*s2+1][0], sa[2*s2+1][1], ah[2], al[2]);
      split_pack(sa[2*s2+1][2], sa[2*s2+1][3], ah[3], al[3]);
#pragma unroll
      for (int p = 0; p < 4; p++) {
        uint32_t bh[4], bl[4];
        uint32_t va = sb + VB + (s2 * 16 + vrow) * 144 + (p * 16 + voff8) * 2;
        ldsm4t(bh, va);
        ldsm4t(bl, va + 9216);
        mma16816(oa[2*p],   ah, bh[0], bh[1]);
        mma16816(oa[2*p],   al, bh[0], bh[1]);
        mma16816(oa[2*p],   ah, bl[0], bl[1]);
        mma16816(oa[2*p+1], ah, bh[2], bh[3]);
        mma16816(oa[2*p+1], al, bh[2], bh[3]);
        mma16816(oa[2*p+1], ah, bl[2], bl[3]);
      }
    }
  }

  // quad-reduce row sums (tq lanes 0..3 share a row)
  la += __shfl_xor_sync(0xffffffffu, la, 1);
  la += __shfl_xor_sync(0xffffffffu, la, 2);
  lb += __shfl_xor_sync(0xffffffffu, lb, 1);
  lb += __shfl_xor_sync(0xffffffffu, lb, 2);
  if (tq == 0) {
    g_lpar[chunk * BB * TT + b * TT + ia] = la;
    g_lpar[chunk * BB * TT + b * TT + ib] = lb;
  }
  float* op = g_opar + (size_t)chunk * BB * TT * HH;
#pragma unroll
  for (int nf = 0; nf < 8; nf++) {
    int c = nf * 8 + tq * 2;
    *(float2*)(op + ((size_t)b * TT + ia) * HH + c) = make_float2(oa[nf][0], oa[nf][1]);
    *(float2*)(op + ((size_t)b * TT + ib) * HH + c) = make_float2(oa[nf][2], oa[nf][3]);
  }
}

// ---------------- Kc: combine live chunk slots, normalize O, emit l ---------
__global__ void kc(float* __restrict__ out) {
  int idx = blockIdx.x * 256 + threadIdx.x;   // float4 index < 262144
  int row = idx >> 4;
  int i = row & (TT - 1);
  int nc = (2 * (i >> 7) + 9) >> 3;           // live slots for this row-tile
  float l = 0.0f;
  float4 s = make_float4(0, 0, 0, 0);
  for (int c = 0; c < nc; c++) {
    l += g_lpar[c * BB * TT + row];
    float4 a = ((const float4*)g_opar)[(size_t)c * (BB * TT * HH / 4) + idx];
    s.x += a.x; s.y += a.y; s.z += a.z; s.w += a.w;
  }
  float inv = 1.0f / l;
  ((float4*)out)[idx] = make_float4(s.x * inv, s.y * inv, s.z * inv, s.w * inv);
  if ((idx & 15) == 0) g_l[row] = l;
}

// ---------------- K3: normalize att lower triangle, zero upper --------------
__global__ __launch_bounds__(256) void k3(float* __restrict__ out) {
  const int rt = 15 - (int)(blockIdx.x >> 2), sl = blockIdx.x & 3, b = blockIdx.y;
  __shared__ float linv[128];
  if (threadIdx.x < 128)
    linv[threadIdx.x] = 1.0f / g_l[b * TT + rt * 128 + threadIdx.x];
  __syncthreads();
  float4* att = (float4*)(out + (size_t)BB * TT * HH + (size_t)b * TT * TT);
  const int cend = (rt + 1) * 32;             // f4 columns that were written
  for (int idx = threadIdx.x; idx < 128 * 128; idx += 256) {
    int r = idx >> 7, c = (idx & 127) + sl * 128;
    size_t gi = (size_t)(rt * 128 + r) * 512 + c;
    float4 v;
    if (c < cend) {
      v = att[gi];
      float iv = linv[r];
      v.x *= iv; v.y *= iv; v.z *= iv; v.w *= iv;
    } else {
      v = make_float4(0, 0, 0, 0);
    }
    att[gi] = v;
  }
}

// ---------------------------------------------------------------------------
extern "C" void kernel_launch(void* const* d_in, const int* in_sizes, int n_in,
                              void* d_out, int out_size) {
  const float* x  = (const float*)d_in[0];
  const float* Wq = (const float*)d_in[1];
  const float* Wk = (const float*)d_in[2];
  const float* Wv = (const float*)d_in[3];
  float* out = (float*)d_out;

  k0<<<384, 256>>>(Wq, Wk, Wv);

  cudaFuncSetAttribute(qkv, cudaFuncAttributeMaxDynamicSharedMemorySize, 92160);
  qkv<<<128, 256, 92160>>>(x);

  cudaFuncSetAttribute(attn, cudaFuncAttributeMaxDynamicSharedMemorySize, 110592);
  attn<<<dim3(40, 8), 256, 110592>>>(out);

  kc<<<1024, 256>>>(out);
  k3<<<dim3(64, 8), 256>>>(out);
}

// round 6
// speedup vs baseline: 2.7425x; 1.0824x over previous
#include <cuda_runtime.h>
#include <cuda_bf16.h>
#include <stdint.h>

#define BB 8
#define TT 2048
#define CC 512
#define HH 64
#define SCALEF 0.044194173824159216f   // 512^-0.5

// ---------------- scratch (device globals: allocation-free) ----------------
__device__ __nv_bfloat16 g_qhi[BB*TT*HH], g_qlo[BB*TT*HH];
__device__ __nv_bfloat16 g_khi[BB*TT*HH], g_klo[BB*TT*HH];
__device__ __nv_bfloat16 g_vhi[BB*TT*HH], g_vlo[BB*TT*HH];
__device__ __nv_bfloat16 g_wthi[3*HH*CC], g_wtlo[3*HH*CC];   // [w][h][c]
__device__ float g_opar[4ll*BB*TT*HH];
__device__ float g_lpar[4*BB*TT];
__device__ float g_l[BB*TT];

// ---------------- helpers ----------------
__device__ __forceinline__ uint32_t su(const void* p) {
  uint32_t a;
  asm("{ .reg .u64 t; cvta.to.shared.u64 t, %1; cvt.u32.u64 %0, t; }" : "=r"(a) : "l"(p));
  return a;
}
__device__ __forceinline__ void ldsm4(uint32_t* r, uint32_t a) {
  asm volatile("ldmatrix.sync.aligned.m8n8.x4.shared.b16 {%0,%1,%2,%3}, [%4];"
    : "=r"(r[0]), "=r"(r[1]), "=r"(r[2]), "=r"(r[3]) : "r"(a));
}
__device__ __forceinline__ void ldsm4t(uint32_t* r, uint32_t a) {
  asm volatile("ldmatrix.sync.aligned.m8n8.x4.trans.shared.b16 {%0,%1,%2,%3}, [%4];"
    : "=r"(r[0]), "=r"(r[1]), "=r"(r[2]), "=r"(r[3]) : "r"(a));
}
__device__ __forceinline__ void mma16816(float* d, const uint32_t* a, uint32_t b0, uint32_t b1) {
  asm volatile("mma.sync.aligned.m16n8k16.row.col.f32.bf16.bf16.f32 "
    "{%0,%1,%2,%3}, {%4,%5,%6,%7}, {%8,%9}, {%0,%1,%2,%3};"
    : "+f"(d[0]), "+f"(d[1]), "+f"(d[2]), "+f"(d[3])
    : "r"(a[0]), "r"(a[1]), "r"(a[2]), "r"(a[3]), "r"(b0), "r"(b1));
}
__device__ __forceinline__ void split_pack(float a, float b, uint32_t& hi, uint32_t& lo) {
  __nv_bfloat162 h = __floats2bfloat162_rn(a, b);
  __nv_bfloat162 l = __floats2bfloat162_rn(a - __bfloat162float(h.x),
                                           b - __bfloat162float(h.y));
  hi = *reinterpret_cast<uint32_t*>(&h);
  lo = *reinterpret_cast<uint32_t*>(&l);
}
__device__ __forceinline__ void cpa16(uint32_t s, const void* g) {
  asm volatile("cp.async.cg.shared.global [%0], [%1], 16;" :: "r"(s), "l"(g) : "memory");
}
#define CP_COMMIT() asm volatile("cp.async.commit_group;" ::: "memory")
#define CP_WAIT0()  asm volatile("cp.async.wait_group 0;" ::: "memory")

// ---------------- K0: weight transpose + split ----------------
__global__ void k0(const float* __restrict__ Wq, const float* __restrict__ Wk,
                   const float* __restrict__ Wv) {
  int idx = blockIdx.x * 256 + threadIdx.x;          // < 3*64*512
  int w = idx >> 15, rem = idx & 32767, h = rem >> 9, c = rem & 511;
  const float* W = (w == 0) ? Wq : ((w == 1) ? Wk : Wv);
  float v = W[(size_t)c * HH + h];
  __nv_bfloat16 hi = __float2bfloat16(v);
  g_wthi[idx] = hi;
  g_wtlo[idx] = __float2bfloat16(v - __bfloat162float(hi));
}

// ---------------- K1: fused QKV on HMMA. grid=128, block=256 ----------------
__global__ __launch_bounds__(256, 1) void qkv(const float* __restrict__ x) {
  extern __shared__ char S[];
  const uint32_t XH = 0, XL = 18432, WB = 36864;
  const int t = threadIdx.x, w = t >> 5, lane = t & 31;
  const int g = lane >> 2, tq = lane & 3;
  const int row0 = blockIdx.x * 128;
  const uint32_t sb = su(S);
  const uint32_t arow = 16 * w + (lane & 15), aoff8 = (lane >> 4) * 8;
  const uint32_t brow = (lane & 7) + ((lane >> 4) & 1) * 8;
  const uint32_t boff8 = ((lane >> 3) & 1) * 8;

  float acc[3][8][4] = {};

  for (int kci = 0; kci < 8; kci++) {
    __syncthreads();
#pragma unroll
    for (int e = 0; e < 16; e++) {
      int idx = t + e * 256, r = idx >> 5, cp = idx & 31;
      float2 xv = *(const float2*)(x + (size_t)(row0 + r) * CC + kci * 64 + cp * 2);
      uint32_t hi, lo; split_pack(xv.x, xv.y, hi, lo);
      uint32_t off = (uint32_t)(r * 144 + cp * 4);
      *(uint32_t*)(S + XH + off) = hi;
      *(uint32_t*)(S + XL + off) = lo;
    }
#pragma unroll
    for (int e = 0; e < 24; e++) {
      int idx = t + e * 256;                 // < 6144
      int o = idx >> 11, r2 = idx & 2047, h = r2 >> 5, cp = r2 & 31;
      uint32_t gi = (uint32_t)(o * 16384 + h * 256 + kci * 32 + cp);
      uint32_t off = WB + o * 18432 + h * 144 + cp * 4;
      *(uint32_t*)(S + off)        = ((const uint32_t*)g_wthi)[gi];
      *(uint32_t*)(S + off + 9216) = ((const uint32_t*)g_wtlo)[gi];
    }
    __syncthreads();

#pragma unroll
    for (int s = 0; s < 4; s++) {
      uint32_t ah[4], al[4];
      uint32_t qa = sb + XH + arow * 144 + (s * 16 + aoff8) * 2;
      ldsm4(ah, qa);
      ldsm4(al, qa + XL);
#pragma unroll
      for (int o = 0; o < 3; o++) {
        uint32_t base = sb + WB + o * 18432;
#pragma unroll
        for (int p = 0; p < 4; p++) {
          uint32_t bh[4], bl[4];
          uint32_t ka = base + (p * 16 + brow) * 144 + (s * 16 + boff8) * 2;
          ldsm4(bh, ka);
          ldsm4(bl, ka + 9216);
          mma16816(acc[o][2*p],   ah, bh[0], bh[1]);
          mma16816(acc[o][2*p],   al, bh[0], bh[1]);
          mma16816(acc[o][2*p],   ah, bl[0], bl[1]);
          mma16816(acc[o][2*p+1], ah, bh[2], bh[3]);
          mma16816(acc[o][2*p+1], al, bh[2], bh[3]);
          mma16816(acc[o][2*p+1], ah, bl[2], bl[3]);
        }
      }
    }
  }

  const size_t ra = (size_t)(row0 + 16 * w + g), rb = ra + 8;
#pragma unroll
  for (int o = 0; o < 3; o++) {
    uint32_t* dh = (uint32_t*)(o == 0 ? g_qhi : (o == 1 ? g_khi : g_vhi));
    uint32_t* dl = (uint32_t*)(o == 0 ? g_qlo : (o == 1 ? g_klo : g_vlo));
#pragma unroll
    for (int nf = 0; nf < 8; nf++) {
      uint32_t hi, lo;
      split_pack(acc[o][nf][0], acc[o][nf][1], hi, lo);
      dh[ra * 32 + nf * 4 + tq] = hi;
      dl[ra * 32 + nf * 4 + tq] = lo;
      split_pack(acc[o][nf][2], acc[o][nf][3], hi, lo);
      dh[rb * 32 + nf * 4 + tq] = hi;
      dl[rb * 32 + nf * 4 + tq] = lo;
    }
  }
}

// ---------------- K2: attention core. grid=(40,8), block=256 ----------------
// Chunked causal work: block -> (rt, chunk of <=8 jt tiles); heavy rt first.
// smem: Qh[128][72]@0 Ql@18432 | KV buf0@36864 buf1@73728  (110592 B total)
// 2 CTAs/SM resident: 221184 B smem, regs capped at 128.
__global__ __launch_bounds__(256, 2) void attn(float* __restrict__ out) {
  extern __shared__ char S[];
  const uint32_t QH = 0, QL = 18432, KV0 = 36864, KVSZ = 36864;
  const int t = threadIdx.x, w = t >> 5, lane = t & 31;
  const int g = lane >> 2, tq = lane & 3;
  const int b = blockIdx.y;

  // map blockIdx.x -> (rt, chunk), rt=15 first
  int bx = blockIdx.x, rt = 15;
  for (;; rt--) { int nc = (2 * rt + 9) >> 3; if (bx < nc) break; bx -= nc; }
  const int chunk = bx;
  const int jt0 = chunk * 8;
  const int ntiles = min(8, 2 * rt + 2 - jt0);
  const int i0 = rt * 128;
  const uint32_t sb = su(S);

  // async-load Q tile
#pragma unroll
  for (int e = 0; e < 4; e++) {
    int idx = t + e * 256, r = idx >> 3, c8 = idx & 7;   // idx < 1024
    size_t gb = ((size_t)(b * TT + i0 + r) * 64 + c8 * 8) * 2;
    uint32_t off = (uint32_t)(r * 144 + c8 * 16);
    cpa16(sb + QH + off, (const char*)g_qhi + gb);
    cpa16(sb + QL + off, (const char*)g_qlo + gb);
  }
  // prefetch first KV tile into buf0
  {
    const int j0 = jt0 * 64;
#pragma unroll
    for (int e = 0; e < 2; e++) {
      int idx = t + e * 256, r = idx >> 3, c8 = idx & 7;  // idx < 512
      size_t gb = ((size_t)(b * TT + j0 + r) * 64 + c8 * 8) * 2;
      uint32_t off = KV0 + (uint32_t)(r * 144 + c8 * 16);
      cpa16(sb + off,         (const char*)g_khi + gb);
      cpa16(sb + off + 9216,  (const char*)g_klo + gb);
      cpa16(sb + off + 18432, (const char*)g_vhi + gb);
      cpa16(sb + off + 27648, (const char*)g_vlo + gb);
    }
  }
  CP_COMMIT();

  float oa[8][4] = {};
  float la = 0.0f, lb = 0.0f;
  const int ia = i0 + 16 * w + g, ib = ia + 8;
  float* att = out + (size_t)BB * TT * HH + (size_t)b * TT * TT;

  const uint32_t arow = 16 * w + (lane & 15), aoff8 = (lane >> 4) * 8;
  const uint32_t brow = (lane & 7) + ((lane >> 4) & 1) * 8;   // non-trans B
  const uint32_t boff8 = ((lane >> 3) & 1) * 8;
  const uint32_t vrow = (lane & 7) + ((lane >> 3) & 1) * 8;   // trans B
  const uint32_t voff8 = ((lane >> 4) & 1) * 8;

  for (int ti = 0; ti < ntiles; ti++) {
    const int j0 = (jt0 + ti) * 64;
    CP_WAIT0();
    __syncthreads();

    // prefetch next tile into other buffer
    if (ti + 1 < ntiles) {
      const int jn = (jt0 + ti + 1) * 64;
      const uint32_t nb = KV0 + ((ti + 1) & 1) * KVSZ;
#pragma unroll
      for (int e = 0; e < 2; e++) {
        int idx = t + e * 256, r = idx >> 3, c8 = idx & 7;
        size_t gb = ((size_t)(b * TT + jn + r) * 64 + c8 * 8) * 2;
        uint32_t off = nb + (uint32_t)(r * 144 + c8 * 16);
        cpa16(sb + off,         (const char*)g_khi + gb);
        cpa16(sb + off + 9216,  (const char*)g_klo + gb);
        cpa16(sb + off + 18432, (const char*)g_vhi + gb);
        cpa16(sb + off + 27648, (const char*)g_vlo + gb);
      }
    }
    CP_COMMIT();

    const uint32_t KB = KV0 + (ti & 1) * KVSZ;        // Khi base
    const uint32_t VB = KB + 18432;                    // Vhi base

    // ---- S = Q K^T (3-term bf16 split) ----
    float sa[8][4] = {};
#pragma unroll
    for (int s = 0; s < 4; s++) {
      uint32_t ah[4], al[4];
      uint32_t qa = sb + QH + arow * 144 + (s * 16 + aoff8) * 2;
      ldsm4(ah, qa);
      ldsm4(al, qa + QL);
#pragma unroll
      for (int p = 0; p < 4; p++) {
        uint32_t bh[4], bl[4];
        uint32_t ka = sb + KB + (p * 16 + brow) * 144 + (s * 16 + boff8) * 2;
        ldsm4(bh, ka);
        ldsm4(bl, ka + 9216);
        mma16816(sa[2*p],   ah, bh[0], bh[1]);
        mma16816(sa[2*p],   al, bh[0], bh[1]);
        mma16816(sa[2*p],   ah, bl[0], bl[1]);
        mma16816(sa[2*p+1], ah, bh[2], bh[3]);
        mma16816(sa[2*p+1], al, bh[2], bh[3]);
        mma16816(sa[2*p+1], ah, bl[2], bl[3]);
      }
    }

    // ---- epilogue: exp + ALiBi + causal mask; write unnormalized att ----
#pragma unroll
    for (int nf = 0; nf < 8; nf++) {
      int j = j0 + nf * 8 + tq * 2;
      float p00 = (j     <= ia) ? __expf((sa[nf][0] + (float)(j     - ia)) * SCALEF) : 0.0f;
      float p01 = (j + 1 <= ia) ? __expf((sa[nf][1] + (float)(j + 1 - ia)) * SCALEF) : 0.0f;
      float p10 = (j     <= ib) ? __expf((sa[nf][2] + (float)(j     - ib)) * SCALEF) : 0.0f;
      float p11 = (j + 1 <= ib) ? __expf((sa[nf][3] + (float)(j + 1 - ib)) * SCALEF) : 0.0f;
      *(float2*)(att + (size_t)ia * TT + j) = make_float2(p00, p01);
      *(float2*)(att + (size_t)ib * TT + j) = make_float2(p10, p11);
      la += p00 + p01;
      lb += p10 + p11;
      sa[nf][0] = p00; sa[nf][1] = p01; sa[nf][2] = p10; sa[nf][3] = p11;
    }

    // ---- O += P V (P fragments built in registers) ----
#pragma unroll
    for (int s2 = 0; s2 < 4; s2++) {
      uint32_t ah[4], al[4];
      split_pack(sa[2*s2][0],   sa[2*s2][1],   ah[0], al[0]);
      split_pack(sa[2*s2][2],   sa[2*s2][3],   ah[1], al[1]);
      split_pack(sa[2*s2+1][0], sa[2*s2+1][1], ah[2], al[2]);
      split_pack(sa[2*s2+1][2], sa[2*s2+1][3], ah[3], al[3]);
#pragma unroll
      for (int p = 0; p < 4; p++) {
        uint32_t bh[4], bl[4];
        uint32_t va = sb + VB + (s2 * 16 + vrow) * 144 + (p * 16 + voff8) * 2;
        ldsm4t(bh, va);
        ldsm4t(bl, va + 9216);
        mma16816(oa[2*p],   ah, bh[0], bh[1]);
        mma16816(oa[2*p],   al, bh[0], bh[1]);
        mma16816(oa[2*p],   ah, bl[0], bl[1]);
        mma16816(oa[2*p+1], ah, bh[2], bh[3]);
        mma16816(oa[2*p+1], al, bh[2], bh[3]);
        mma16816(oa[2*p+1], ah, bl[2], bl[3]);
      }
    }
  }

  // quad-reduce row sums (tq lanes 0..3 share a row)
  la += __shfl_xor_sync(0xffffffffu, la, 1);
  la += __shfl_xor_sync(0xffffffffu, la, 2);
  lb += __shfl_xor_sync(0xffffffffu, lb, 1);
  lb += __shfl_xor_sync(0xffffffffu, lb, 2);
  if (tq == 0) {
    g_lpar[chunk * BB * TT + b * TT + ia] = la;
    g_lpar[chunk * BB * TT + b * TT + ib] = lb;
  }
  float* op = g_opar + (size_t)chunk * BB * TT * HH;
#pragma unroll
  for (int nf = 0; nf < 8; nf++) {
    int c = nf * 8 + tq * 2;
    *(float2*)(op + ((size_t)b * TT + ia) * HH + c) = make_float2(oa[nf][0], oa[nf][1]);
    *(float2*)(op + ((size_t)b * TT + ib) * HH + c) = make_float2(oa[nf][2], oa[nf][3]);
  }
}

// ---------------- Kc: combine live chunk slots, normalize O, emit l ---------
__global__ void kc(float* __restrict__ out) {
  int idx = blockIdx.x * 256 + threadIdx.x;   // float4 index < 262144
  int row = idx >> 4;
  int i = row & (TT - 1);
  int nc = (2 * (i >> 7) + 9) >> 3;           // live slots for this row-tile
  float l = 0.0f;
  float4 s = make_float4(0, 0, 0, 0);
  for (int c = 0; c < nc; c++) {
    l += g_lpar[c * BB * TT + row];
    float4 a = ((const float4*)g_opar)[(size_t)c * (BB * TT * HH / 4) + idx];
    s.x += a.x; s.y += a.y; s.z += a.z; s.w += a.w;
  }
  float inv = 1.0f / l;
  ((float4*)out)[idx] = make_float4(s.x * inv, s.y * inv, s.z * inv, s.w * inv);
  if ((idx & 15) == 0) g_l[row] = l;
}

// ---------------- K3: normalize att lower triangle, zero upper --------------
__global__ __launch_bounds__(256) void k3(float* __restrict__ out) {
  const int rt = 15 - (int)(blockIdx.x >> 2), sl = blockIdx.x & 3, b = blockIdx.y;
  __shared__ float linv[128];
  if (threadIdx.x < 128)
    linv[threadIdx.x] = 1.0f / g_l[b * TT + rt * 128 + threadIdx.x];
  __syncthreads();
  float4* att = (float4*)(out + (size_t)BB * TT * HH + (size_t)b * TT * TT);
  const int cend = (rt + 1) * 32;             // f4 columns that were written
  for (int idx = threadIdx.x; idx < 128 * 128; idx += 256) {
    int r = idx >> 7, c = (idx & 127) + sl * 128;
    size_t gi = (size_t)(rt * 128 + r) * 512 + c;
    float4 v;
    if (c < cend) {
      v = att[gi];
      float iv = linv[r];
      v.x *= iv; v.y *= iv; v.z *= iv; v.w *= iv;
    } else {
      v = make_float4(0, 0, 0, 0);
    }
    att[gi] = v;
  }
}

// ---------------------------------------------------------------------------
extern "C" void kernel_launch(void* const* d_in, const int* in_sizes, int n_in,
                              void* d_out, int out_size) {
  const float* x  = (const float*)d_in[0];
  const float* Wq = (const float*)d_in[1];
  const float* Wk = (const float*)d_in[2];
  const float* Wv = (const float*)d_in[3];
  float* out = (float*)d_out;

  k0<<<384, 256>>>(Wq, Wk, Wv);

  cudaFuncSetAttribute(qkv, cudaFuncAttributeMaxDynamicSharedMemorySize, 92160);
  qkv<<<128, 256, 92160>>>(x);

  cudaFuncSetAttribute(attn, cudaFuncAttributeMaxDynamicSharedMemorySize, 110592);
  cudaFuncSetAttribute(attn, cudaFuncAttributePreferredSharedMemoryCarveout,
                       cudaSharedmemCarveoutMaxShared);
  attn<<<dim3(40, 8), 256, 110592>>>(out);

  kc<<<1024, 256>>>(out);
  k3<<<dim3(64, 8), 256>>>(out);
}

// round 7
// speedup vs baseline: 2.8842x; 1.0517x over previous
#include <cuda_runtime.h>
#include <cuda_bf16.h>
#include <cuda_fp16.h>
#include <stdint.h>

#define BB 8
#define TT 2048
#define CC 512
#define HH 64
#define SCALEF 0.044194173824159216f   // 512^-0.5

// ---------------- scratch (device globals: allocation-free) ----------------
__device__ __half g_qhi[BB*TT*HH], g_qlo[BB*TT*HH];   // fp16 (2-term S)
__device__ __half g_khi[BB*TT*HH];                    // fp16, hi only
__device__ __nv_bfloat16 g_vhi[BB*TT*HH], g_vlo[BB*TT*HH];
__device__ __nv_bfloat16 g_wthi[3*HH*CC], g_wtlo[3*HH*CC];   // [w][h][c]
__device__ float g_opar[4ll*BB*TT*HH];
__device__ float g_lpar[4*BB*TT];
__device__ float g_l[BB*TT];

// ---------------- helpers ----------------
__device__ __forceinline__ uint32_t su(const void* p) {
  uint32_t a;
  asm("{ .reg .u64 t; cvta.to.shared.u64 t, %1; cvt.u32.u64 %0, t; }" : "=r"(a) : "l"(p));
  return a;
}
__device__ __forceinline__ void ldsm4(uint32_t* r, uint32_t a) {
  asm volatile("ldmatrix.sync.aligned.m8n8.x4.shared.b16 {%0,%1,%2,%3}, [%4];"
    : "=r"(r[0]), "=r"(r[1]), "=r"(r[2]), "=r"(r[3]) : "r"(a));
}
__device__ __forceinline__ void ldsm4t(uint32_t* r, uint32_t a) {
  asm volatile("ldmatrix.sync.aligned.m8n8.x4.trans.shared.b16 {%0,%1,%2,%3}, [%4];"
    : "=r"(r[0]), "=r"(r[1]), "=r"(r[2]), "=r"(r[3]) : "r"(a));
}
__device__ __forceinline__ void mma16816(float* d, const uint32_t* a, uint32_t b0, uint32_t b1) {
  asm volatile("mma.sync.aligned.m16n8k16.row.col.f32.bf16.bf16.f32 "
    "{%0,%1,%2,%3}, {%4,%5,%6,%7}, {%8,%9}, {%0,%1,%2,%3};"
    : "+f"(d[0]), "+f"(d[1]), "+f"(d[2]), "+f"(d[3])
    : "r"(a[0]), "r"(a[1]), "r"(a[2]), "r"(a[3]), "r"(b0), "r"(b1));
}
__device__ __forceinline__ void mma16816h(float* d, const uint32_t* a, uint32_t b0, uint32_t b1) {
  asm volatile("mma.sync.aligned.m16n8k16.row.col.f32.f16.f16.f32 "
    "{%0,%1,%2,%3}, {%4,%5,%6,%7}, {%8,%9}, {%0,%1,%2,%3};"
    : "+f"(d[0]), "+f"(d[1]), "+f"(d[2]), "+f"(d[3])
    : "r"(a[0]), "r"(a[1]), "r"(a[2]), "r"(a[3]), "r"(b0), "r"(b1));
}
__device__ __forceinline__ void split_pack(float a, float b, uint32_t& hi, uint32_t& lo) {
  __nv_bfloat162 h = __floats2bfloat162_rn(a, b);
  __nv_bfloat162 l = __floats2bfloat162_rn(a - __bfloat162float(h.x),
                                           b - __bfloat162float(h.y));
  hi = *reinterpret_cast<uint32_t*>(&h);
  lo = *reinterpret_cast<uint32_t*>(&l);
}
__device__ __forceinline__ void split_packh(float a, float b, uint32_t& hi, uint32_t& lo) {
  __half2 h = __floats2half2_rn(a, b);
  __half2 l = __floats2half2_rn(a - __half2float(h.x), b - __half2float(h.y));
  hi = *reinterpret_cast<uint32_t*>(&h);
  lo = *reinterpret_cast<uint32_t*>(&l);
}
__device__ __forceinline__ uint32_t packh(float a, float b) {
  __half2 h = __floats2half2_rn(a, b);
  return *reinterpret_cast<uint32_t*>(&h);
}
__device__ __forceinline__ void cpa16(uint32_t s, const void* g) {
  asm volatile("cp.async.cg.shared.global [%0], [%1], 16;" :: "r"(s), "l"(g) : "memory");
}
#define CP_COMMIT() asm volatile("cp.async.commit_group;" ::: "memory")
#define CP_WAIT0()  asm volatile("cp.async.wait_group 0;" ::: "memory")

// ---------------- K0: weight transpose + split ----------------
__global__ void k0(const float* __restrict__ Wq, const float* __restrict__ Wk,
                   const float* __restrict__ Wv) {
  int idx = blockIdx.x * 256 + threadIdx.x;          // < 3*64*512
  int w = idx >> 15, rem = idx & 32767, h = rem >> 9, c = rem & 511;
  const float* W = (w == 0) ? Wq : ((w == 1) ? Wk : Wv);
  float v = W[(size_t)c * HH + h];
  __nv_bfloat16 hi = __float2bfloat16(v);
  g_wthi[idx] = hi;
  g_wtlo[idx] = __float2bfloat16(v - __bfloat162float(hi));
}

// ---------------- K1: fused QKV on HMMA. grid=128, block=256 ----------------
__global__ __launch_bounds__(256, 1) void qkv(const float* __restrict__ x) {
  extern __shared__ char S[];
  const uint32_t XH = 0, XL = 18432, WB = 36864;
  const int t = threadIdx.x, w = t >> 5, lane = t & 31;
  const int g = lane >> 2, tq = lane & 3;
  const int row0 = blockIdx.x * 128;
  const uint32_t sb = su(S);
  const uint32_t arow = 16 * w + (lane & 15), aoff8 = (lane >> 4) * 8;
  const uint32_t brow = (lane & 7) + ((lane >> 4) & 1) * 8;
  const uint32_t boff8 = ((lane >> 3) & 1) * 8;

  float acc[3][8][4] = {};

  for (int kci = 0; kci < 8; kci++) {
    __syncthreads();
#pragma unroll
    for (int e = 0; e < 16; e++) {
      int idx = t + e * 256, r = idx >> 5, cp = idx & 31;
      float2 xv = *(const float2*)(x + (size_t)(row0 + r) * CC + kci * 64 + cp * 2);
      uint32_t hi, lo; split_pack(xv.x, xv.y, hi, lo);
      uint32_t off = (uint32_t)(r * 144 + cp * 4);
      *(uint32_t*)(S + XH + off) = hi;
      *(uint32_t*)(S + XL + off) = lo;
    }
#pragma unroll
    for (int e = 0; e < 24; e++) {
      int idx = t + e * 256;                 // < 6144
      int o = idx >> 11, r2 = idx & 2047, h = r2 >> 5, cp = r2 & 31;
      uint32_t gi = (uint32_t)(o * 16384 + h * 256 + kci * 32 + cp);
      uint32_t off = WB + o * 18432 + h * 144 + cp * 4;
      *(uint32_t*)(S + off)        = ((const uint32_t*)g_wthi)[gi];
      *(uint32_t*)(S + off + 9216) = ((const uint32_t*)g_wtlo)[gi];
    }
    __syncthreads();

#pragma unroll
    for (int s = 0; s < 4; s++) {
      uint32_t ah[4], al[4];
      uint32_t qa = sb + XH + arow * 144 + (s * 16 + aoff8) * 2;
      ldsm4(ah, qa);
      ldsm4(al, qa + XL);
#pragma unroll
      for (int o = 0; o < 3; o++) {
        uint32_t base = sb + WB + o * 18432;
#pragma unroll
        for (int p = 0; p < 4; p++) {
          uint32_t bh[4], bl[4];
          uint32_t ka = base + (p * 16 + brow) * 144 + (s * 16 + boff8) * 2;
          ldsm4(bh, ka);
          ldsm4(bl, ka + 9216);
          mma16816(acc[o][2*p],   ah, bh[0], bh[1]);
          mma16816(acc[o][2*p],   al, bh[0], bh[1]);
          mma16816(acc[o][2*p],   ah, bl[0], bl[1]);
          mma16816(acc[o][2*p+1], ah, bh[2], bh[3]);
          mma16816(acc[o][2*p+1], al, bh[2], bh[3]);
          mma16816(acc[o][2*p+1], ah, bl[2], bl[3]);
        }
      }
    }
  }

  const size_t ra = (size_t)(row0 + 16 * w + g), rb = ra + 8;
  // o=0: Q -> fp16 hi/lo
  {
    uint32_t* dh = (uint32_t*)g_qhi;
    uint32_t* dl = (uint32_t*)g_qlo;
#pragma unroll
    for (int nf = 0; nf < 8; nf++) {
      uint32_t hi, lo;
      split_packh(acc[0][nf][0], acc[0][nf][1], hi, lo);
      dh[ra * 32 + nf * 4 + tq] = hi;
      dl[ra * 32 + nf * 4 + tq] = lo;
      split_packh(acc[0][nf][2], acc[0][nf][3], hi, lo);
      dh[rb * 32 + nf * 4 + tq] = hi;
      dl[rb * 32 + nf * 4 + tq] = lo;
    }
  }
  // o=1: K -> fp16 hi only
  {
    uint32_t* dh = (uint32_t*)g_khi;
#pragma unroll
    for (int nf = 0; nf < 8; nf++) {
      dh[ra * 32 + nf * 4 + tq] = packh(acc[1][nf][0], acc[1][nf][1]);
      dh[rb * 32 + nf * 4 + tq] = packh(acc[1][nf][2], acc[1][nf][3]);
    }
  }
  // o=2: V -> bf16 hi/lo
  {
    uint32_t* dh = (uint32_t*)g_vhi;
    uint32_t* dl = (uint32_t*)g_vlo;
#pragma unroll
    for (int nf = 0; nf < 8; nf++) {
      uint32_t hi, lo;
      split_pack(acc[2][nf][0], acc[2][nf][1], hi, lo);
      dh[ra * 32 + nf * 4 + tq] = hi;
      dl[ra * 32 + nf * 4 + tq] = lo;
      split_pack(acc[2][nf][2], acc[2][nf][3], hi, lo);
      dh[rb * 32 + nf * 4 + tq] = hi;
      dl[rb * 32 + nf * 4 + tq] = lo;
    }
  }
}

// ---------------- K2: attention core. grid=(40,8), block=256 ----------------
// Chunked causal work: block -> (rt, chunk of <=8 jt tiles); heavy rt first.
// smem: Qh[128][72]@0 Ql@18432 | KV buf0@36864 buf1@64512 (92160 B total)
//   each KV buf: Kh@+0 Vh@+9216 Vl@+18432  (64 rows x 144B each)
__global__ __launch_bounds__(256, 2) void attn(float* __restrict__ out) {
  extern __shared__ char S[];
  const uint32_t QH = 0, QL = 18432, KV0 = 36864, KVSZ = 27648;
  const int t = threadIdx.x, w = t >> 5, lane = t & 31;
  const int g = lane >> 2, tq = lane & 3;
  const int b = blockIdx.y;

  // map blockIdx.x -> (rt, chunk), rt=15 first
  int bx = blockIdx.x, rt = 15;
  for (;; rt--) { int nc = (2 * rt + 9) >> 3; if (bx < nc) break; bx -= nc; }
  const int chunk = bx;
  const int jt0 = chunk * 8;
  const int ntiles = min(8, 2 * rt + 2 - jt0);
  const int i0 = rt * 128;
  const uint32_t sb = su(S);

  // async-load Q tile
#pragma unroll
  for (int e = 0; e < 4; e++) {
    int idx = t + e * 256, r = idx >> 3, c8 = idx & 7;   // idx < 1024
    size_t gb = ((size_t)(b * TT + i0 + r) * 64 + c8 * 8) * 2;
    uint32_t off = (uint32_t)(r * 144 + c8 * 16);
    cpa16(sb + QH + off, (const char*)g_qhi + gb);
    cpa16(sb + QL + off, (const char*)g_qlo + gb);
  }
  // prefetch first KV tile into buf0
  {
    const int j0 = jt0 * 64;
#pragma unroll
    for (int e = 0; e < 2; e++) {
      int idx = t + e * 256, r = idx >> 3, c8 = idx & 7;  // idx < 512
      size_t gb = ((size_t)(b * TT + j0 + r) * 64 + c8 * 8) * 2;
      uint32_t off = KV0 + (uint32_t)(r * 144 + c8 * 16);
      cpa16(sb + off,         (const char*)g_khi + gb);
      cpa16(sb + off + 9216,  (const char*)g_vhi + gb);
      cpa16(sb + off + 18432, (const char*)g_vlo + gb);
    }
  }
  CP_COMMIT();

  float oa[8][4] = {};
  float la = 0.0f, lb = 0.0f;
  const int ia = i0 + 16 * w + g, ib = ia + 8;
  float* att = out + (size_t)BB * TT * HH + (size_t)b * TT * TT;

  const uint32_t arow = 16 * w + (lane & 15), aoff8 = (lane >> 4) * 8;
  const uint32_t brow = (lane & 7) + ((lane >> 4) & 1) * 8;   // non-trans B
  const uint32_t boff8 = ((lane >> 3) & 1) * 8;
  const uint32_t vrow = (lane & 7) + ((lane >> 3) & 1) * 8;   // trans B
  const uint32_t voff8 = ((lane >> 4) & 1) * 8;

  for (int ti = 0; ti < ntiles; ti++) {
    const int j0 = (jt0 + ti) * 64;
    CP_WAIT0();
    __syncthreads();

    // prefetch next tile into other buffer
    if (ti + 1 < ntiles) {
      const int jn = (jt0 + ti + 1) * 64;
      const uint32_t nb = KV0 + ((ti + 1) & 1) * KVSZ;
#pragma unroll
      for (int e = 0; e < 2; e++) {
        int idx = t + e * 256, r = idx >> 3, c8 = idx & 7;
        size_t gb = ((size_t)(b * TT + jn + r) * 64 + c8 * 8) * 2;
        uint32_t off = nb + (uint32_t)(r * 144 + c8 * 16);
        cpa16(sb + off,         (const char*)g_khi + gb);
        cpa16(sb + off + 9216,  (const char*)g_vhi + gb);
        cpa16(sb + off + 18432, (const char*)g_vlo + gb);
      }
    }
    CP_COMMIT();

    const uint32_t KB = KV0 + (ti & 1) * KVSZ;        // Khi base
    const uint32_t VB = KB + 9216;                     // Vhi base

    // ---- S = Q K^T (fp16 2-term split: qh*kh + ql*kh) ----
    float sa[8][4] = {};
#pragma unroll
    for (int s = 0; s < 4; s++) {
      uint32_t ah[4], al[4];
      uint32_t qa = sb + QH + arow * 144 + (s * 16 + aoff8) * 2;
      ldsm4(ah, qa);
      ldsm4(al, qa + QL);
#pragma unroll
      for (int p = 0; p < 4; p++) {
        uint32_t bh[4];
        uint32_t ka = sb + KB + (p * 16 + brow) * 144 + (s * 16 + boff8) * 2;
        ldsm4(bh, ka);
        mma16816h(sa[2*p],   ah, bh[0], bh[1]);
        mma16816h(sa[2*p],   al, bh[0], bh[1]);
        mma16816h(sa[2*p+1], ah, bh[2], bh[3]);
        mma16816h(sa[2*p+1], al, bh[2], bh[3]);
      }
    }

    // ---- epilogue: exp + ALiBi + causal mask; write unnormalized att ----
#pragma unroll
    for (int nf = 0; nf < 8; nf++) {
      int j = j0 + nf * 8 + tq * 2;
      float p00 = (j     <= ia) ? __expf((sa[nf][0] + (float)(j     - ia)) * SCALEF) : 0.0f;
      float p01 = (j + 1 <= ia) ? __expf((sa[nf][1] + (float)(j + 1 - ia)) * SCALEF) : 0.0f;
      float p10 = (j     <= ib) ? __expf((sa[nf][2] + (float)(j     - ib)) * SCALEF) : 0.0f;
      float p11 = (j + 1 <= ib) ? __expf((sa[nf][3] + (float)(j + 1 - ib)) * SCALEF) : 0.0f;
      *(float2*)(att + (size_t)ia * TT + j) = make_float2(p00, p01);
      *(float2*)(att + (size_t)ib * TT + j) = make_float2(p10, p11);
      la += p00 + p01;
      lb += p10 + p11;
      sa[nf][0] = p00; sa[nf][1] = p01; sa[nf][2] = p10; sa[nf][3] = p11;
    }

    // ---- O += P V (bf16 3-term; P fragments built in registers) ----
#pragma unroll
    for (int s2 = 0; s2 < 4; s2++) {
      uint32_t ah[4], al[4];
      split_pack(sa[2*s2][0],   sa[2*s2][1],   ah[0], al[0]);
      split_pack(sa[2*s2][2],   sa[2*s2][3],   ah[1], al[1]);
      split_pack(sa[2*s2+1][0], sa[2*s2+1][1], ah[2], al[2]);
      split_pack(sa[2*s2+1][2], sa[2*s2+1][3], ah[3], al[3]);
#pragma unroll
      for (int p = 0; p < 4; p++) {
        uint32_t bh[4], bl[4];
        uint32_t va = sb + VB + (s2 * 16 + vrow) * 144 + (p * 16 + voff8) * 2;
        ldsm4t(bh, va);
        ldsm4t(bl, va + 9216);
        mma16816(oa[2*p],   ah, bh[0], bh[1]);
        mma16816(oa[2*p],   al, bh[0], bh[1]);
        mma16816(oa[2*p],   ah, bl[0], bl[1]);
        mma16816(oa[2*p+1], ah, bh[2], bh[3]);
        mma16816(oa[2*p+1], al, bh[2], bh[3]);
        mma16816(oa[2*p+1], ah, bl[2], bl[3]);
      }
    }
  }

  // quad-reduce row sums (tq lanes 0..3 share a row)
  la += __shfl_xor_sync(0xffffffffu, la, 1);
  la += __shfl_xor_sync(0xffffffffu, la, 2);
  lb += __shfl_xor_sync(0xffffffffu, lb, 1);
  lb += __shfl_xor_sync(0xffffffffu, lb, 2);
  if (tq == 0) {
    g_lpar[chunk * BB * TT + b * TT + ia] = la;
    g_lpar[chunk * BB * TT + b * TT + ib] = lb;
  }
  float* op = g_opar + (size_t)chunk * BB * TT * HH;
#pragma unroll
  for (int nf = 0; nf < 8; nf++) {
    int c = nf * 8 + tq * 2;
    *(float2*)(op + ((size_t)b * TT + ia) * HH + c) = make_float2(oa[nf][0], oa[nf][1]);
    *(float2*)(op + ((size_t)b * TT + ib) * HH + c) = make_float2(oa[nf][2], oa[nf][3]);
  }
}

// ---------------- Kc: combine live chunk slots, normalize O, emit l ---------
__global__ void kc(float* __restrict__ out) {
  int idx = blockIdx.x * 256 + threadIdx.x;   // float4 index < 262144
  int row = idx >> 4;
  int i = row & (TT - 1);
  int nc = (2 * (i >> 7) + 9) >> 3;           // live slots for this row-tile
  float l = 0.0f;
  float4 s = make_float4(0, 0, 0, 0);
  for (int c = 0; c < nc; c++) {
    l += g_lpar[c * BB * TT + row];
    float4 a = ((const float4*)g_opar)[(size_t)c * (BB * TT * HH / 4) + idx];
    s.x += a.x; s.y += a.y; s.z += a.z; s.w += a.w;
  }
  float inv = 1.0f / l;
  ((float4*)out)[idx] = make_float4(s.x * inv, s.y * inv, s.z * inv, s.w * inv);
  if ((idx & 15) == 0) g_l[row] = l;
}

// ---------------- K3: normalize att lower triangle, zero upper --------------
__global__ __launch_bounds__(256) void k3(float* __restrict__ out) {
  const int rt = 15 - (int)(blockIdx.x >> 2), sl = blockIdx.x & 3, b = blockIdx.y;
  __shared__ float linv[128];
  if (threadIdx.x < 128)
    linv[threadIdx.x] = 1.0f / g_l[b * TT + rt * 128 + threadIdx.x];
  __syncthreads();
  float4* att = (float4*)(out + (size_t)BB * TT * HH + (size_t)b * TT * TT);
  const int cend = (rt + 1) * 32;             // f4 columns that were written
  for (int idx = threadIdx.x; idx < 128 * 128; idx += 256) {
    int r = idx >> 7, c = (idx & 127) + sl * 128;
    size_t gi = (size_t)(rt * 128 + r) * 512 + c;
    float4 v;
    if (c < cend) {
      v = att[gi];
      float iv = linv[r];
      v.x *= iv; v.y *= iv; v.z *= iv; v.w *= iv;
    } else {
      v = make_float4(0, 0, 0, 0);
    }
    att[gi] = v;
  }
}

// ---------------------------------------------------------------------------
extern "C" void kernel_launch(void* const* d_in, const int* in_sizes, int n_in,
                              void* d_out, int out_size) {
  const float* x  = (const float*)d_in[0];
  const float* Wq = (const float*)d_in[1];
  const float* Wk = (const float*)d_in[2];
  const float* Wv = (const float*)d_in[3];
  float* out = (float*)d_out;

  k0<<<384, 256>>>(Wq, Wk, Wv);

  cudaFuncSetAttribute(qkv, cudaFuncAttributeMaxDynamicSharedMemorySize, 92160);
  qkv<<<128, 256, 92160>>>(x);

  cudaFuncSetAttribute(attn, cudaFuncAttributeMaxDynamicSharedMemorySize, 92160);
  cudaFuncSetAttribute(attn, cudaFuncAttributePreferredSharedMemoryCarveout,
                       cudaSharedmemCarveoutMaxShared);
  attn<<<dim3(40, 8), 256, 92160>>>(out);

  kc<<<1024, 256>>>(out);
  k3<<<dim3(64, 8), 256>>>(out);
}

// round 8
// speedup vs baseline: 3.0156x; 1.0456x over previous
#include <cuda_runtime.h>
#include <cuda_bf16.h>
#include <cuda_fp16.h>
#include <stdint.h>

#define BB 8
#define TT 2048
#define CC 512
#define HH 64
#define SCALEF 0.044194173824159216f   // 512^-0.5

// ---------------- scratch (device globals: allocation-free) ----------------
__device__ __half g_qhi[BB*TT*HH], g_qlo[BB*TT*HH];   // fp16 (2-term S)
__device__ __half g_khi[BB*TT*HH];                    // fp16, hi only
__device__ __half g_vhi[BB*TT*HH];                    // fp16, hi only
__device__ __nv_bfloat16 g_wthi[3*HH*CC], g_wtlo[3*HH*CC];   // [w][h][c]
__device__ float g_opar[4ll*BB*TT*HH];
__device__ float g_lpar[4*BB*TT];
__device__ float g_l[BB*TT];

// ---------------- helpers ----------------
__device__ __forceinline__ uint32_t su(const void* p) {
  uint32_t a;
  asm("{ .reg .u64 t; cvta.to.shared.u64 t, %1; cvt.u32.u64 %0, t; }" : "=r"(a) : "l"(p));
  return a;
}
__device__ __forceinline__ void ldsm4(uint32_t* r, uint32_t a) {
  asm volatile("ldmatrix.sync.aligned.m8n8.x4.shared.b16 {%0,%1,%2,%3}, [%4];"
    : "=r"(r[0]), "=r"(r[1]), "=r"(r[2]), "=r"(r[3]) : "r"(a));
}
__device__ __forceinline__ void ldsm4t(uint32_t* r, uint32_t a) {
  asm volatile("ldmatrix.sync.aligned.m8n8.x4.trans.shared.b16 {%0,%1,%2,%3}, [%4];"
    : "=r"(r[0]), "=r"(r[1]), "=r"(r[2]), "=r"(r[3]) : "r"(a));
}
__device__ __forceinline__ void mma16816(float* d, const uint32_t* a, uint32_t b0, uint32_t b1) {
  asm volatile("mma.sync.aligned.m16n8k16.row.col.f32.bf16.bf16.f32 "
    "{%0,%1,%2,%3}, {%4,%5,%6,%7}, {%8,%9}, {%0,%1,%2,%3};"
    : "+f"(d[0]), "+f"(d[1]), "+f"(d[2]), "+f"(d[3])
    : "r"(a[0]), "r"(a[1]), "r"(a[2]), "r"(a[3]), "r"(b0), "r"(b1));
}
__device__ __forceinline__ void mma16816h(float* d, const uint32_t* a, uint32_t b0, uint32_t b1) {
  asm volatile("mma.sync.aligned.m16n8k16.row.col.f32.f16.f16.f32 "
    "{%0,%1,%2,%3}, {%4,%5,%6,%7}, {%8,%9}, {%0,%1,%2,%3};"
    : "+f"(d[0]), "+f"(d[1]), "+f"(d[2]), "+f"(d[3])
    : "r"(a[0]), "r"(a[1]), "r"(a[2]), "r"(a[3]), "r"(b0), "r"(b1));
}
__device__ __forceinline__ void split_pack(float a, float b, uint32_t& hi, uint32_t& lo) {
  __nv_bfloat162 h = __floats2bfloat162_rn(a, b);
  __nv_bfloat162 l = __floats2bfloat162_rn(a - __bfloat162float(h.x),
                                           b - __bfloat162float(h.y));
  hi = *reinterpret_cast<uint32_t*>(&h);
  lo = *reinterpret_cast<uint32_t*>(&l);
}
__device__ __forceinline__ void split_packh(float a, float b, uint32_t& hi, uint32_t& lo) {
  __half2 h = __floats2half2_rn(a, b);
  __half2 l = __floats2half2_rn(a - __half2float(h.x), b - __half2float(h.y));
  hi = *reinterpret_cast<uint32_t*>(&h);
  lo = *reinterpret_cast<uint32_t*>(&l);
}
__device__ __forceinline__ uint32_t packh(float a, float b) {
  __half2 h = __floats2half2_rn(a, b);
  return *reinterpret_cast<uint32_t*>(&h);
}
__device__ __forceinline__ void cpa16(uint32_t s, const void* g) {
  asm volatile("cp.async.cg.shared.global [%0], [%1], 16;" :: "r"(s), "l"(g) : "memory");
}
#define CP_COMMIT() asm volatile("cp.async.commit_group;" ::: "memory")
#define CP_WAIT0()  asm volatile("cp.async.wait_group 0;" ::: "memory")

// ---------------- K0: weight transpose + split ----------------
__global__ void k0(const float* __restrict__ Wq, const float* __restrict__ Wk,
                   const float* __restrict__ Wv) {
  int idx = blockIdx.x * 256 + threadIdx.x;          // < 3*64*512
  int w = idx >> 15, rem = idx & 32767, h = rem >> 9, c = rem & 511;
  const float* W = (w == 0) ? Wq : ((w == 1) ? Wk : Wv);
  float v = W[(size_t)c * HH + h];
  __nv_bfloat16 hi = __float2bfloat16(v);
  g_wthi[idx] = hi;
  g_wtlo[idx] = __float2bfloat16(v - __bfloat162float(hi));
}

// ---------------- K1: fused QKV on HMMA. grid=128, block=256 ----------------
__global__ __launch_bounds__(256, 1) void qkv(const float* __restrict__ x) {
  extern __shared__ char S[];
  const uint32_t XH = 0, XL = 18432, WB = 36864;
  const int t = threadIdx.x, w = t >> 5, lane = t & 31;
  const int g = lane >> 2, tq = lane & 3;
  const int row0 = blockIdx.x * 128;
  const uint32_t sb = su(S);
  const uint32_t arow = 16 * w + (lane & 15), aoff8 = (lane >> 4) * 8;
  const uint32_t brow = (lane & 7) + ((lane >> 4) & 1) * 8;
  const uint32_t boff8 = ((lane >> 3) & 1) * 8;

  float acc[3][8][4] = {};

  for (int kci = 0; kci < 8; kci++) {
    __syncthreads();
#pragma unroll
    for (int e = 0; e < 16; e++) {
      int idx = t + e * 256, r = idx >> 5, cp = idx & 31;
      float2 xv = *(const float2*)(x + (size_t)(row0 + r) * CC + kci * 64 + cp * 2);
      uint32_t hi, lo; split_pack(xv.x, xv.y, hi, lo);
      uint32_t off = (uint32_t)(r * 144 + cp * 4);
      *(uint32_t*)(S + XH + off) = hi;
      *(uint32_t*)(S + XL + off) = lo;
    }
#pragma unroll
    for (int e = 0; e < 24; e++) {
      int idx = t + e * 256;                 // < 6144
      int o = idx >> 11, r2 = idx & 2047, h = r2 >> 5, cp = r2 & 31;
      uint32_t gi = (uint32_t)(o * 16384 + h * 256 + kci * 32 + cp);
      uint32_t off = WB + o * 18432 + h * 144 + cp * 4;
      *(uint32_t*)(S + off)        = ((const uint32_t*)g_wthi)[gi];
      *(uint32_t*)(S + off + 9216) = ((const uint32_t*)g_wtlo)[gi];
    }
    __syncthreads();

#pragma unroll
    for (int s = 0; s < 4; s++) {
      uint32_t ah[4], al[4];
      uint32_t qa = sb + XH + arow * 144 + (s * 16 + aoff8) * 2;
      ldsm4(ah, qa);
      ldsm4(al, qa + XL);
#pragma unroll
      for (int o = 0; o < 3; o++) {
        uint32_t base = sb + WB + o * 18432;
#pragma unroll
        for (int p = 0; p < 4; p++) {
          uint32_t bh[4], bl[4];
          uint32_t ka = base + (p * 16 + brow) * 144 + (s * 16 + boff8) * 2;
          ldsm4(bh, ka);
          ldsm4(bl, ka + 9216);
          mma16816(acc[o][2*p],   ah, bh[0], bh[1]);
          mma16816(acc[o][2*p],   al, bh[0], bh[1]);
          mma16816(acc[o][2*p],   ah, bl[0], bl[1]);
          mma16816(acc[o][2*p+1], ah, bh[2], bh[3]);
          mma16816(acc[o][2*p+1], al, bh[2], bh[3]);
          mma16816(acc[o][2*p+1], ah, bl[2], bl[3]);
        }
      }
    }
  }

  const size_t ra = (size_t)(row0 + 16 * w + g), rb = ra + 8;
  // o=0: Q -> fp16 hi/lo
  {
    uint32_t* dh = (uint32_t*)g_qhi;
    uint32_t* dl = (uint32_t*)g_qlo;
#pragma unroll
    for (int nf = 0; nf < 8; nf++) {
      uint32_t hi, lo;
      split_packh(acc[0][nf][0], acc[0][nf][1], hi, lo);
      dh[ra * 32 + nf * 4 + tq] = hi;
      dl[ra * 32 + nf * 4 + tq] = lo;
      split_packh(acc[0][nf][2], acc[0][nf][3], hi, lo);
      dh[rb * 32 + nf * 4 + tq] = hi;
      dl[rb * 32 + nf * 4 + tq] = lo;
    }
  }
  // o=1: K -> fp16 hi only;  o=2: V -> fp16 hi only
  {
    uint32_t* dk = (uint32_t*)g_khi;
    uint32_t* dv = (uint32_t*)g_vhi;
#pragma unroll
    for (int nf = 0; nf < 8; nf++) {
      dk[ra * 32 + nf * 4 + tq] = packh(acc[1][nf][0], acc[1][nf][1]);
      dk[rb * 32 + nf * 4 + tq] = packh(acc[1][nf][2], acc[1][nf][3]);
      dv[ra * 32 + nf * 4 + tq] = packh(acc[2][nf][0], acc[2][nf][1]);
      dv[rb * 32 + nf * 4 + tq] = packh(acc[2][nf][2], acc[2][nf][3]);
    }
  }
}

// ---------------- K2: attention core. grid=(40,8), block=256 ----------------
// Chunked causal work: block -> (rt, chunk of <=8 jt tiles); heavy rt first.
// smem: Qh[128][72]@0 Ql@18432 | KV buf0@36864 buf1@55296 (73728 B total)
//   each KV buf: Kh@+0 Vh@+9216  (64 rows x 144B each)
__global__ __launch_bounds__(256, 2) void attn(float* __restrict__ out) {
  extern __shared__ char S[];
  const uint32_t QH = 0, QL = 18432, KV0 = 36864, KVSZ = 18432;
  const int t = threadIdx.x, w = t >> 5, lane = t & 31;
  const int g = lane >> 2, tq = lane & 3;
  const int b = blockIdx.y;

  // map blockIdx.x -> (rt, chunk), rt=15 first
  int bx = blockIdx.x, rt = 15;
  for (;; rt--) { int nc = (2 * rt + 9) >> 3; if (bx < nc) break; bx -= nc; }
  const int chunk = bx;
  const int jt0 = chunk * 8;
  const int ntiles = min(8, 2 * rt + 2 - jt0);
  const int i0 = rt * 128;
  const uint32_t sb = su(S);

  // async-load Q tile
#pragma unroll
  for (int e = 0; e < 4; e++) {
    int idx = t + e * 256, r = idx >> 3, c8 = idx & 7;   // idx < 1024
    size_t gb = ((size_t)(b * TT + i0 + r) * 64 + c8 * 8) * 2;
    uint32_t off = (uint32_t)(r * 144 + c8 * 16);
    cpa16(sb + QH + off, (const char*)g_qhi + gb);
    cpa16(sb + QL + off, (const char*)g_qlo + gb);
  }
  // prefetch first KV tile into buf0
  {
    const int j0 = jt0 * 64;
#pragma unroll
    for (int e = 0; e < 2; e++) {
      int idx = t + e * 256, r = idx >> 3, c8 = idx & 7;  // idx < 512
      size_t gb = ((size_t)(b * TT + j0 + r) * 64 + c8 * 8) * 2;
      uint32_t off = KV0 + (uint32_t)(r * 144 + c8 * 16);
      cpa16(sb + off,        (const char*)g_khi + gb);
      cpa16(sb + off + 9216, (const char*)g_vhi + gb);
    }
  }
  CP_COMMIT();

  float oa[8][4] = {};
  float la = 0.0f, lb = 0.0f;
  const int ia = i0 + 16 * w + g, ib = ia + 8;
  float* att = out + (size_t)BB * TT * HH + (size_t)b * TT * TT;

  const uint32_t arow = 16 * w + (lane & 15), aoff8 = (lane >> 4) * 8;
  const uint32_t brow = (lane & 7) + ((lane >> 4) & 1) * 8;   // non-trans B
  const uint32_t boff8 = ((lane >> 3) & 1) * 8;
  const uint32_t vrow = (lane & 7) + ((lane >> 3) & 1) * 8;   // trans B
  const uint32_t voff8 = ((lane >> 4) & 1) * 8;

  for (int ti = 0; ti < ntiles; ti++) {
    const int j0 = (jt0 + ti) * 64;
    CP_WAIT0();
    __syncthreads();

    // prefetch next tile into other buffer
    if (ti + 1 < ntiles) {
      const int jn = (jt0 + ti + 1) * 64;
      const uint32_t nb = KV0 + ((ti + 1) & 1) * KVSZ;
#pragma unroll
      for (int e = 0; e < 2; e++) {
        int idx = t + e * 256, r = idx >> 3, c8 = idx & 7;
        size_t gb = ((size_t)(b * TT + jn + r) * 64 + c8 * 8) * 2;
        uint32_t off = nb + (uint32_t)(r * 144 + c8 * 16);
        cpa16(sb + off,        (const char*)g_khi + gb);
        cpa16(sb + off + 9216, (const char*)g_vhi + gb);
      }
    }
    CP_COMMIT();

    const uint32_t KB = KV0 + (ti & 1) * KVSZ;        // Khi base
    const uint32_t VB = KB + 9216;                     // Vhi base

    // ---- S = Q K^T (fp16 2-term split: qh*kh + ql*kh) ----
    float sa[8][4] = {};
#pragma unroll
    for (int s = 0; s < 4; s++) {
      uint32_t ah[4], al[4];
      uint32_t qa = sb + QH + arow * 144 + (s * 16 + aoff8) * 2;
      ldsm4(ah, qa);
      ldsm4(al, qa + QL);
#pragma unroll
      for (int p = 0; p < 4; p++) {
        uint32_t bh[4];
        uint32_t ka = sb + KB + (p * 16 + brow) * 144 + (s * 16 + boff8) * 2;
        ldsm4(bh, ka);
        mma16816h(sa[2*p],   ah, bh[0], bh[1]);
        mma16816h(sa[2*p],   al, bh[0], bh[1]);
        mma16816h(sa[2*p+1], ah, bh[2], bh[3]);
        mma16816h(sa[2*p+1], al, bh[2], bh[3]);
      }
    }

    // ---- epilogue: exp + ALiBi + causal mask; write unnormalized att ----
#pragma unroll
    for (int nf = 0; nf < 8; nf++) {
      int j = j0 + nf * 8 + tq * 2;
      float p00 = (j     <= ia) ? __expf((sa[nf][0] + (float)(j     - ia)) * SCALEF) : 0.0f;
      float p01 = (j + 1 <= ia) ? __expf((sa[nf][1] + (float)(j + 1 - ia)) * SCALEF) : 0.0f;
      float p10 = (j     <= ib) ? __expf((sa[nf][2] + (float)(j     - ib)) * SCALEF) : 0.0f;
      float p11 = (j + 1 <= ib) ? __expf((sa[nf][3] + (float)(j + 1 - ib)) * SCALEF) : 0.0f;
      *(float2*)(att + (size_t)ia * TT + j) = make_float2(p00, p01);
      *(float2*)(att + (size_t)ib * TT + j) = make_float2(p10, p11);
      la += p00 + p01;
      lb += p10 + p11;
      sa[nf][0] = p00; sa[nf][1] = p01; sa[nf][2] = p10; sa[nf][3] = p11;
    }

    // ---- O += P V (fp16: exact 2-term P split x fp16 V) ----
#pragma unroll
    for (int s2 = 0; s2 < 4; s2++) {
      uint32_t ah[4], al[4];
      split_packh(sa[2*s2][0],   sa[2*s2][1],   ah[0], al[0]);
      split_packh(sa[2*s2][2],   sa[2*s2][3],   ah[1], al[1]);
      split_packh(sa[2*s2+1][0], sa[2*s2+1][1], ah[2], al[2]);
      split_packh(sa[2*s2+1][2], sa[2*s2+1][3], ah[3], al[3]);
#pragma unroll
      for (int p = 0; p < 4; p++) {
        uint32_t bh[4];
        uint32_t va = sb + VB + (s2 * 16 + vrow) * 144 + (p * 16 + voff8) * 2;
        ldsm4t(bh, va);
        mma16816h(oa[2*p],   ah, bh[0], bh[1]);
        mma16816h(oa[2*p],   al, bh[0], bh[1]);
        mma16816h(oa[2*p+1], ah, bh[2], bh[3]);
        mma16816h(oa[2*p+1], al, bh[2], bh[3]);
      }
    }
  }

  // quad-reduce row sums (tq lanes 0..3 share a row)
  la += __shfl_xor_sync(0xffffffffu, la, 1);
  la += __shfl_xor_sync(0xffffffffu, la, 2);
  lb += __shfl_xor_sync(0xffffffffu, lb, 1);
  lb += __shfl_xor_sync(0xffffffffu, lb, 2);
  if (tq == 0) {
    g_lpar[chunk * BB * TT + b * TT + ia] = la;
    g_lpar[chunk * BB * TT + b * TT + ib] = lb;
  }
  float* op = g_opar + (size_t)chunk * BB * TT * HH;
#pragma unroll
  for (int nf = 0; nf < 8; nf++) {
    int c = nf * 8 + tq * 2;
    *(float2*)(op + ((size_t)b * TT + ia) * HH + c) = make_float2(oa[nf][0], oa[nf][1]);
    *(float2*)(op + ((size_t)b * TT + ib) * HH + c) = make_float2(oa[nf][2], oa[nf][3]);
  }
}

// ---------------- Kc: combine live chunk slots, normalize O, emit l ---------
__global__ void kc(float* __restrict__ out) {
  int idx = blockIdx.x * 256 + threadIdx.x;   // float4 index < 262144
  int row = idx >> 4;
  int i = row & (TT - 1);
  int nc = (2 * (i >> 7) + 9) >> 3;           // live slots for this row-tile
  float l = 0.0f;
  float4 s = make_float4(0, 0, 0, 0);
  for (int c = 0; c < nc; c++) {
    l += g_lpar[c * BB * TT + row];
    float4 a = ((const float4*)g_opar)[(size_t)c * (BB * TT * HH / 4) + idx];
    s.x += a.x; s.y += a.y; s.z += a.z; s.w += a.w;
  }
  float inv = 1.0f / l;
  ((float4*)out)[idx] = make_float4(s.x * inv, s.y * inv, s.z * inv, s.w * inv);
  if ((idx & 15) == 0) g_l[row] = l;
}

// ---------------- K3: normalize att lower triangle, zero upper --------------
__global__ __launch_bounds__(256) void k3(float* __restrict__ out) {
  const int rt = 15 - (int)(blockIdx.x >> 2), sl = blockIdx.x & 3, b = blockIdx.y;
  __shared__ float linv[128];
  if (threadIdx.x < 128)
    linv[threadIdx.x] = 1.0f / g_l[b * TT + rt * 128 + threadIdx.x];
  __syncthreads();
  float4* att = (float4*)(out + (size_t)BB * TT * HH + (size_t)b * TT * TT);
  const int cend = (rt + 1) * 32;             // f4 columns that were written
  for (int idx = threadIdx.x; idx < 128 * 128; idx += 256) {
    int r = idx >> 7, c = (idx & 127) + sl * 128;
    size_t gi = (size_t)(rt * 128 + r) * 512 + c;
    float4 v;
    if (c < cend) {
      v = att[gi];
      float iv = linv[r];
      v.x *= iv; v.y *= iv; v.z *= iv; v.w *= iv;
    } else {
      v = make_float4(0, 0, 0, 0);
    }
    att[gi] = v;
  }
}

// ---------------------------------------------------------------------------
extern "C" void kernel_launch(void* const* d_in, const int* in_sizes, int n_in,
                              void* d_out, int out_size) {
  const float* x  = (const float*)d_in[0];
  const float* Wq = (const float*)d_in[1];
  const float* Wk = (const float*)d_in[2];
  const float* Wv = (const float*)d_in[3];
  float* out = (float*)d_out;

  k0<<<384, 256>>>(Wq, Wk, Wv);

  cudaFuncSetAttribute(qkv, cudaFuncAttributeMaxDynamicSharedMemorySize, 92160);
  qkv<<<128, 256, 92160>>>(x);

  cudaFuncSetAttribute(attn, cudaFuncAttributeMaxDynamicSharedMemorySize, 73728);
  cudaFuncSetAttribute(attn, cudaFuncAttributePreferredSharedMemoryCarveout,
                       cudaSharedmemCarveoutMaxShared);
  attn<<<dim3(40, 8), 256, 73728>>>(out);

  kc<<<1024, 256>>>(out);
  k3<<<dim3(64, 8), 256>>>(out);
}

// round 9
// speedup vs baseline: 3.1066x; 1.0302x over previous
#include <cuda_runtime.h>
#include <cuda_bf16.h>
#include <cuda_fp16.h>
#include <stdint.h>

#define BB 8
#define TT 2048
#define CC 512
#define HH 64
#define SCALEF 0.044194173824159216f   // 512^-0.5

// ---------------- scratch (device globals: allocation-free) ----------------
__device__ __half g_qhi[BB*TT*HH];                    // fp16 (1-term S)
__device__ __half g_khi[BB*TT*HH];                    // fp16, hi only
__device__ __half g_vhi[BB*TT*HH];                    // fp16, hi only
__device__ __nv_bfloat16 g_wthi[3*HH*CC], g_wtlo[3*HH*CC];   // [w][h][c]
__device__ float g_opar[4ll*BB*TT*HH];
__device__ float g_lpar[4*BB*TT];
__device__ float g_l[BB*TT];

// ---------------- helpers ----------------
__device__ __forceinline__ uint32_t su(const void* p) {
  uint32_t a;
  asm("{ .reg .u64 t; cvta.to.shared.u64 t, %1; cvt.u32.u64 %0, t; }" : "=r"(a) : "l"(p));
  return a;
}
__device__ __forceinline__ void ldsm4(uint32_t* r, uint32_t a) {
  asm volatile("ldmatrix.sync.aligned.m8n8.x4.shared.b16 {%0,%1,%2,%3}, [%4];"
    : "=r"(r[0]), "=r"(r[1]), "=r"(r[2]), "=r"(r[3]) : "r"(a));
}
__device__ __forceinline__ void ldsm4t(uint32_t* r, uint32_t a) {
  asm volatile("ldmatrix.sync.aligned.m8n8.x4.trans.shared.b16 {%0,%1,%2,%3}, [%4];"
    : "=r"(r[0]), "=r"(r[1]), "=r"(r[2]), "=r"(r[3]) : "r"(a));
}
__device__ __forceinline__ void mma16816(float* d, const uint32_t* a, uint32_t b0, uint32_t b1) {
  asm volatile("mma.sync.aligned.m16n8k16.row.col.f32.bf16.bf16.f32 "
    "{%0,%1,%2,%3}, {%4,%5,%6,%7}, {%8,%9}, {%0,%1,%2,%3};"
    : "+f"(d[0]), "+f"(d[1]), "+f"(d[2]), "+f"(d[3])
    : "r"(a[0]), "r"(a[1]), "r"(a[2]), "r"(a[3]), "r"(b0), "r"(b1));
}
__device__ __forceinline__ void mma16816h(float* d, const uint32_t* a, uint32_t b0, uint32_t b1) {
  asm volatile("mma.sync.aligned.m16n8k16.row.col.f32.f16.f16.f32 "
    "{%0,%1,%2,%3}, {%4,%5,%6,%7}, {%8,%9}, {%0,%1,%2,%3};"
    : "+f"(d[0]), "+f"(d[1]), "+f"(d[2]), "+f"(d[3])
    : "r"(a[0]), "r"(a[1]), "r"(a[2]), "r"(a[3]), "r"(b0), "r"(b1));
}
__device__ __forceinline__ void split_pack(float a, float b, uint32_t& hi, uint32_t& lo) {
  __nv_bfloat162 h = __floats2bfloat162_rn(a, b);
  __nv_bfloat162 l = __floats2bfloat162_rn(a - __bfloat162float(h.x),
                                           b - __bfloat162float(h.y));
  hi = *reinterpret_cast<uint32_t*>(&h);
  lo = *reinterpret_cast<uint32_t*>(&l);
}
__device__ __forceinline__ void split_packh(float a, float b, uint32_t& hi, uint32_t& lo) {
  __half2 h = __floats2half2_rn(a, b);
  __half2 l = __floats2half2_rn(a - __half2float(h.x), b - __half2float(h.y));
  hi = *reinterpret_cast<uint32_t*>(&h);
  lo = *reinterpret_cast<uint32_t*>(&l);
}
__device__ __forceinline__ uint32_t packh(float a, float b) {
  __half2 h = __floats2half2_rn(a, b);
  return *reinterpret_cast<uint32_t*>(&h);
}
__device__ __forceinline__ void cpa16(uint32_t s, const void* g) {
  asm volatile("cp.async.cg.shared.global [%0], [%1], 16;" :: "r"(s), "l"(g) : "memory");
}
#define CP_COMMIT() asm volatile("cp.async.commit_group;" ::: "memory")
#define CP_WAIT0()  asm volatile("cp.async.wait_group 0;" ::: "memory")

// ---------------- K0: weight transpose + split ----------------
__global__ void k0(const float* __restrict__ Wq, const float* __restrict__ Wk,
                   const float* __restrict__ Wv) {
  int idx = blockIdx.x * 256 + threadIdx.x;          // < 3*64*512
  int w = idx >> 15, rem = idx & 32767, h = rem >> 9, c = rem & 511;
  const float* W = (w == 0) ? Wq : ((w == 1) ? Wk : Wv);
  float v = W[(size_t)c * HH + h];
  __nv_bfloat16 hi = __float2bfloat16(v);
  g_wthi[idx] = hi;
  g_wtlo[idx] = __float2bfloat16(v - __bfloat162float(hi));
}

// ---------------- K1: fused QKV on HMMA. grid=128, block=256 ----------------
__global__ __launch_bounds__(256, 1) void qkv(const float* __restrict__ x) {
  extern __shared__ char S[];
  const uint32_t XH = 0, XL = 18432, WB = 36864;
  const int t = threadIdx.x, w = t >> 5, lane = t & 31;
  const int g = lane >> 2, tq = lane & 3;
  const int row0 = blockIdx.x * 128;
  const uint32_t sb = su(S);
  const uint32_t arow = 16 * w + (lane & 15), aoff8 = (lane >> 4) * 8;
  const uint32_t brow = (lane & 7) + ((lane >> 4) & 1) * 8;
  const uint32_t boff8 = ((lane >> 3) & 1) * 8;

  float acc[3][8][4] = {};

  for (int kci = 0; kci < 8; kci++) {
    __syncthreads();
#pragma unroll
    for (int e = 0; e < 16; e++) {
      int idx = t + e * 256, r = idx >> 5, cp = idx & 31;
      float2 xv = *(const float2*)(x + (size_t)(row0 + r) * CC + kci * 64 + cp * 2);
      uint32_t hi, lo; split_pack(xv.x, xv.y, hi, lo);
      uint32_t off = (uint32_t)(r * 144 + cp * 4);
      *(uint32_t*)(S + XH + off) = hi;
      *(uint32_t*)(S + XL + off) = lo;
    }
#pragma unroll
    for (int e = 0; e < 24; e++) {
      int idx = t + e * 256;                 // < 6144
      int o = idx >> 11, r2 = idx & 2047, h = r2 >> 5, cp = r2 & 31;
      uint32_t gi = (uint32_t)(o * 16384 + h * 256 + kci * 32 + cp);
      uint32_t off = WB + o * 18432 + h * 144 + cp * 4;
      *(uint32_t*)(S + off)        = ((const uint32_t*)g_wthi)[gi];
      *(uint32_t*)(S + off + 9216) = ((const uint32_t*)g_wtlo)[gi];
    }
    __syncthreads();

#pragma unroll
    for (int s = 0; s < 4; s++) {
      uint32_t ah[4], al[4];
      uint32_t qa = sb + XH + arow * 144 + (s * 16 + aoff8) * 2;
      ldsm4(ah, qa);
      ldsm4(al, qa + XL);
#pragma unroll
      for (int o = 0; o < 3; o++) {
        uint32_t base = sb + WB + o * 18432;
#pragma unroll
        for (int p = 0; p < 4; p++) {
          uint32_t bh[4], bl[4];
          uint32_t ka = base + (p * 16 + brow) * 144 + (s * 16 + boff8) * 2;
          ldsm4(bh, ka);
          ldsm4(bl, ka + 9216);
          mma16816(acc[o][2*p],   ah, bh[0], bh[1]);
          mma16816(acc[o][2*p],   al, bh[0], bh[1]);
          mma16816(acc[o][2*p],   ah, bl[0], bl[1]);
          mma16816(acc[o][2*p+1], ah, bh[2], bh[3]);
          mma16816(acc[o][2*p+1], al, bh[2], bh[3]);
          mma16816(acc[o][2*p+1], ah, bl[2], bl[3]);
        }
      }
    }
  }

  const size_t ra = (size_t)(row0 + 16 * w + g), rb = ra + 8;
  // Q, K, V -> fp16 hi only
  {
    uint32_t* dq = (uint32_t*)g_qhi;
    uint32_t* dk = (uint32_t*)g_khi;
    uint32_t* dv = (uint32_t*)g_vhi;
#pragma unroll
    for (int nf = 0; nf < 8; nf++) {
      dq[ra * 32 + nf * 4 + tq] = packh(acc[0][nf][0], acc[0][nf][1]);
      dq[rb * 32 + nf * 4 + tq] = packh(acc[0][nf][2], acc[0][nf][3]);
      dk[ra * 32 + nf * 4 + tq] = packh(acc[1][nf][0], acc[1][nf][1]);
      dk[rb * 32 + nf * 4 + tq] = packh(acc[1][nf][2], acc[1][nf][3]);
      dv[ra * 32 + nf * 4 + tq] = packh(acc[2][nf][0], acc[2][nf][1]);
      dv[rb * 32 + nf * 4 + tq] = packh(acc[2][nf][2], acc[2][nf][3]);
    }
  }
}

// ---------------- K2: attention core. grid=(40,8), block=256 ----------------
// Chunked causal work: block -> (rt, chunk of <=8 jt tiles); heavy rt first.
// smem: Qh[128][72]@0 | KV buf0@18432 buf1@36864 (55296 B total)
//   each KV buf: Kh@+0 Vh@+9216  (64 rows x 144B each)
__global__ __launch_bounds__(256, 2) void attn(float* __restrict__ out) {
  extern __shared__ char S[];
  const uint32_t QH = 0, KV0 = 18432, KVSZ = 18432;
  const int t = threadIdx.x, w = t >> 5, lane = t & 31;
  const int g = lane >> 2, tq = lane & 3;
  const int b = blockIdx.y;

  // map blockIdx.x -> (rt, chunk), rt=15 first
  int bx = blockIdx.x, rt = 15;
  for (;; rt--) { int nc = (2 * rt + 9) >> 3; if (bx < nc) break; bx -= nc; }
  const int chunk = bx;
  const int jt0 = chunk * 8;
  const int ntiles = min(8, 2 * rt + 2 - jt0);
  const int i0 = rt * 128;
  const uint32_t sb = su(S);

  // async-load Q tile (1024 x 16B chunks)
#pragma unroll
  for (int e = 0; e < 4; e++) {
    int idx = t + e * 256, r = idx >> 3, c8 = idx & 7;   // idx < 1024
    size_t gb = ((size_t)(b * TT + i0 + r) * 64 + c8 * 8) * 2;
    uint32_t off = (uint32_t)(r * 144 + c8 * 16);
    cpa16(sb + QH + off, (const char*)g_qhi + gb);
  }
  // prefetch first KV tile into buf0
  {
    const int j0 = jt0 * 64;
#pragma unroll
    for (int e = 0; e < 2; e++) {
      int idx = t + e * 256, r = idx >> 3, c8 = idx & 7;  // idx < 512
      size_t gb = ((size_t)(b * TT + j0 + r) * 64 + c8 * 8) * 2;
      uint32_t off = KV0 + (uint32_t)(r * 144 + c8 * 16);
      cpa16(sb + off,        (const char*)g_khi + gb);
      cpa16(sb + off + 9216, (const char*)g_vhi + gb);
    }
  }
  CP_COMMIT();

  float oa[8][4] = {};
  float la = 0.0f, lb = 0.0f;
  const int ia = i0 + 16 * w + g, ib = ia + 8;
  float* att = out + (size_t)BB * TT * HH + (size_t)b * TT * TT;

  const uint32_t arow = 16 * w + (lane & 15), aoff8 = (lane >> 4) * 8;
  const uint32_t brow = (lane & 7) + ((lane >> 4) & 1) * 8;   // non-trans B
  const uint32_t boff8 = ((lane >> 3) & 1) * 8;
  const uint32_t vrow = (lane & 7) + ((lane >> 3) & 1) * 8;   // trans B
  const uint32_t voff8 = ((lane >> 4) & 1) * 8;

  for (int ti = 0; ti < ntiles; ti++) {
    const int j0 = (jt0 + ti) * 64;
    CP_WAIT0();
    __syncthreads();

    // prefetch next tile into other buffer
    if (ti + 1 < ntiles) {
      const int jn = (jt0 + ti + 1) * 64;
      const uint32_t nb = KV0 + ((ti + 1) & 1) * KVSZ;
#pragma unroll
      for (int e = 0; e < 2; e++) {
        int idx = t + e * 256, r = idx >> 3, c8 = idx & 7;
        size_t gb = ((size_t)(b * TT + jn + r) * 64 + c8 * 8) * 2;
        uint32_t off = nb + (uint32_t)(r * 144 + c8 * 16);
        cpa16(sb + off,        (const char*)g_khi + gb);
        cpa16(sb + off + 9216, (const char*)g_vhi + gb);
      }
    }
    CP_COMMIT();

    const uint32_t KB = KV0 + (ti & 1) * KVSZ;        // Khi base
    const uint32_t VB = KB + 9216;                     // Vhi base

    // ---- S = Q K^T (1-term fp16: qh*kh) ----
    float sa[8][4] = {};
#pragma unroll
    for (int s = 0; s < 4; s++) {
      uint32_t ah[4];
      uint32_t qa = sb + QH + arow * 144 + (s * 16 + aoff8) * 2;
      ldsm4(ah, qa);
#pragma unroll
      for (int p = 0; p < 4; p++) {
        uint32_t bh[4];
        uint32_t ka = sb + KB + (p * 16 + brow) * 144 + (s * 16 + boff8) * 2;
        ldsm4(bh, ka);
        mma16816h(sa[2*p],   ah, bh[0], bh[1]);
        mma16816h(sa[2*p+1], ah, bh[2], bh[3]);
      }
    }

    // ---- epilogue: exp + ALiBi + causal mask; write unnormalized att ----
#pragma unroll
    for (int nf = 0; nf < 8; nf++) {
      int j = j0 + nf * 8 + tq * 2;
      float p00 = (j     <= ia) ? __expf((sa[nf][0] + (float)(j     - ia)) * SCALEF) : 0.0f;
      float p01 = (j + 1 <= ia) ? __expf((sa[nf][1] + (float)(j + 1 - ia)) * SCALEF) : 0.0f;
      float p10 = (j     <= ib) ? __expf((sa[nf][2] + (float)(j     - ib)) * SCALEF) : 0.0f;
      float p11 = (j + 1 <= ib) ? __expf((sa[nf][3] + (float)(j + 1 - ib)) * SCALEF) : 0.0f;
      *(float2*)(att + (size_t)ia * TT + j) = make_float2(p00, p01);
      *(float2*)(att + (size_t)ib * TT + j) = make_float2(p10, p11);
      la += p00 + p01;
      lb += p10 + p11;
      sa[nf][0] = p00; sa[nf][1] = p01; sa[nf][2] = p10; sa[nf][3] = p11;
    }

    // ---- O += P V (fp16: exact 2-term P split x fp16 V) ----
#pragma unroll
    for (int s2 = 0; s2 < 4; s2++) {
      uint32_t ah[4], al[4];
      split_packh(sa[2*s2][0],   sa[2*s2][1],   ah[0], al[0]);
      split_packh(sa[2*s2][2],   sa[2*s2][3],   ah[1], al[1]);
      split_packh(sa[2*s2+1][0], sa[2*s2+1][1], ah[2], al[2]);
      split_packh(sa[2*s2+1][2], sa[2*s2+1][3], ah[3], al[3]);
#pragma unroll
      for (int p = 0; p < 4; p++) {
        uint32_t bh[4];
        uint32_t va = sb + VB + (s2 * 16 + vrow) * 144 + (p * 16 + voff8) * 2;
        ldsm4t(bh, va);
        mma16816h(oa[2*p],   ah, bh[0], bh[1]);
        mma16816h(oa[2*p],   al, bh[0], bh[1]);
        mma16816h(oa[2*p+1], ah, bh[2], bh[3]);
        mma16816h(oa[2*p+1], al, bh[2], bh[3]);
      }
    }
  }

  // quad-reduce row sums (tq lanes 0..3 share a row)
  la += __shfl_xor_sync(0xffffffffu, la, 1);
  la += __shfl_xor_sync(0xffffffffu, la, 2);
  lb += __shfl_xor_sync(0xffffffffu, lb, 1);
  lb += __shfl_xor_sync(0xffffffffu, lb, 2);
  if (tq == 0) {
    g_lpar[chunk * BB * TT + b * TT + ia] = la;
    g_lpar[chunk * BB * TT + b * TT + ib] = lb;
  }
  float* op = g_opar + (size_t)chunk * BB * TT * HH;
#pragma unroll
  for (int nf = 0; nf < 8; nf++) {
    int c = nf * 8 + tq * 2;
    *(float2*)(op + ((size_t)b * TT + ia) * HH + c) = make_float2(oa[nf][0], oa[nf][1]);
    *(float2*)(op + ((size_t)b * TT + ib) * HH + c) = make_float2(oa[nf][2], oa[nf][3]);
  }
}

// ---------------- Kc: combine live chunk slots, normalize O, emit l ---------
__global__ void kc(float* __restrict__ out) {
  int idx = blockIdx.x * 256 + threadIdx.x;   // float4 index < 262144
  int row = idx >> 4;
  int i = row & (TT - 1);
  int nc = (2 * (i >> 7) + 9) >> 3;           // live slots for this row-tile
  float l = 0.0f;
  float4 s = make_float4(0, 0, 0, 0);
  for (int c = 0; c < nc; c++) {
    l += g_lpar[c * BB * TT + row];
    float4 a = ((const float4*)g_opar)[(size_t)c * (BB * TT * HH / 4) + idx];
    s.x += a.x; s.y += a.y; s.z += a.z; s.w += a.w;
  }
  float inv = 1.0f / l;
  ((float4*)out)[idx] = make_float4(s.x * inv, s.y * inv, s.z * inv, s.w * inv);
  if ((idx & 15) == 0) g_l[row] = l;
}

// ---------------- K3: normalize att lower triangle, zero upper --------------
__global__ __launch_bounds__(256) void k3(float* __restrict__ out) {
  const int rt = 15 - (int)(blockIdx.x >> 2), sl = blockIdx.x & 3, b = blockIdx.y;
  __shared__ float linv[128];
  if (threadIdx.x < 128)
    linv[threadIdx.x] = 1.0f / g_l[b * TT + rt * 128 + threadIdx.x];
  __syncthreads();
  float4* att = (float4*)(out + (size_t)BB * TT * HH + (size_t)b * TT * TT);
  const int cend = (rt + 1) * 32;             // f4 columns that were written
  for (int idx = threadIdx.x; idx < 128 * 128; idx += 256) {
    int r = idx >> 7, c = (idx & 127) + sl * 128;
    size_t gi = (size_t)(rt * 128 + r) * 512 + c;
    float4 v;
    if (c < cend) {
      v = att[gi];
      float iv = linv[r];
      v.x *= iv; v.y *= iv; v.z *= iv; v.w *= iv;
    } else {
      v = make_float4(0, 0, 0, 0);
    }
    att[gi] = v;
  }
}

// ---------------------------------------------------------------------------
extern "C" void kernel_launch(void* const* d_in, const int* in_sizes, int n_in,
                              void* d_out, int out_size) {
  const float* x  = (const float*)d_in[0];
  const float* Wq = (const float*)d_in[1];
  const float* Wk = (const float*)d_in[2];
  const float* Wv = (const float*)d_in[3];
  float* out = (float*)d_out;

  k0<<<384, 256>>>(Wq, Wk, Wv);

  cudaFuncSetAttribute(qkv, cudaFuncAttributeMaxDynamicSharedMemorySize, 92160);
  qkv<<<128, 256, 92160>>>(x);

  cudaFuncSetAttribute(attn, cudaFuncAttributeMaxDynamicSharedMemorySize, 55296);
  cudaFuncSetAttribute(attn, cudaFuncAttributePreferredSharedMemoryCarveout,
                       cudaSharedmemCarveoutMaxShared);
  attn<<<dim3(40, 8), 256, 55296>>>(out);

  kc<<<1024, 256>>>(out);
  k3<<<dim3(64, 8), 256>>>(out);
}

// round 10
// speedup vs baseline: 3.2388x; 1.0425x over previous
#include <cuda_runtime.h>
#include <cuda_bf16.h>
#include <cuda_fp16.h>
#include <stdint.h>

#define BB 8
#define TT 2048
#define CC 512
#define HH 64
#define SCALEF 0.044194173824159216f   // 512^-0.5

// ---------------- scratch (device globals: allocation-free) ----------------
__device__ __half g_qhi[BB*TT*HH];                    // fp16 (1-term S)
__device__ __half g_khi[BB*TT*HH];                    // fp16, hi only
__device__ __half g_vhi[BB*TT*HH];                    // fp16, hi only
__device__ __nv_bfloat16 g_wthi[3*HH*CC], g_wtlo[3*HH*CC];   // [w][h][c]
__device__ float g_opar[4ll*BB*TT*HH];
__device__ float g_lpar[4*BB*TT];
__device__ float g_l[BB*TT];

// ---------------- helpers ----------------
__device__ __forceinline__ uint32_t su(const void* p) {
  uint32_t a;
  asm("{ .reg .u64 t; cvta.to.shared.u64 t, %1; cvt.u32.u64 %0, t; }" : "=r"(a) : "l"(p));
  return a;
}
__device__ __forceinline__ void ldsm4(uint32_t* r, uint32_t a) {
  asm volatile("ldmatrix.sync.aligned.m8n8.x4.shared.b16 {%0,%1,%2,%3}, [%4];"
    : "=r"(r[0]), "=r"(r[1]), "=r"(r[2]), "=r"(r[3]) : "r"(a));
}
__device__ __forceinline__ void ldsm4t(uint32_t* r, uint32_t a) {
  asm volatile("ldmatrix.sync.aligned.m8n8.x4.trans.shared.b16 {%0,%1,%2,%3}, [%4];"
    : "=r"(r[0]), "=r"(r[1]), "=r"(r[2]), "=r"(r[3]) : "r"(a));
}
__device__ __forceinline__ void mma16816(float* d, const uint32_t* a, uint32_t b0, uint32_t b1) {
  asm volatile("mma.sync.aligned.m16n8k16.row.col.f32.bf16.bf16.f32 "
    "{%0,%1,%2,%3}, {%4,%5,%6,%7}, {%8,%9}, {%0,%1,%2,%3};"
    : "+f"(d[0]), "+f"(d[1]), "+f"(d[2]), "+f"(d[3])
    : "r"(a[0]), "r"(a[1]), "r"(a[2]), "r"(a[3]), "r"(b0), "r"(b1));
}
__device__ __forceinline__ void mma16816h(float* d, const uint32_t* a, uint32_t b0, uint32_t b1) {
  asm volatile("mma.sync.aligned.m16n8k16.row.col.f32.f16.f16.f32 "
    "{%0,%1,%2,%3}, {%4,%5,%6,%7}, {%8,%9}, {%0,%1,%2,%3};"
    : "+f"(d[0]), "+f"(d[1]), "+f"(d[2]), "+f"(d[3])
    : "r"(a[0]), "r"(a[1]), "r"(a[2]), "r"(a[3]), "r"(b0), "r"(b1));
}
__device__ __forceinline__ void split_pack(float a, float b, uint32_t& hi, uint32_t& lo) {
  __nv_bfloat162 h = __floats2bfloat162_rn(a, b);
  __nv_bfloat162 l = __floats2bfloat162_rn(a - __bfloat162float(h.x),
                                           b - __bfloat162float(h.y));
  hi = *reinterpret_cast<uint32_t*>(&h);
  lo = *reinterpret_cast<uint32_t*>(&l);
}
__device__ __forceinline__ uint32_t packh(float a, float b) {
  __half2 h = __floats2half2_rn(a, b);
  return *reinterpret_cast<uint32_t*>(&h);
}
__device__ __forceinline__ void cpa16(uint32_t s, const void* g) {
  asm volatile("cp.async.cg.shared.global [%0], [%1], 16;" :: "r"(s), "l"(g) : "memory");
}
#define CP_COMMIT() asm volatile("cp.async.commit_group;" ::: "memory")
#define CP_WAIT0()  asm volatile("cp.async.wait_group 0;" ::: "memory")

// ---------------- K0: weight transpose + split ----------------
__global__ void k0(const float* __restrict__ Wq, const float* __restrict__ Wk,
                   const float* __restrict__ Wv) {
  int idx = blockIdx.x * 256 + threadIdx.x;          // < 3*64*512
  int w = idx >> 15, rem = idx & 32767, h = rem >> 9, c = rem & 511;
  const float* W = (w == 0) ? Wq : ((w == 1) ? Wk : Wv);
  float v = W[(size_t)c * HH + h];
  __nv_bfloat16 hi = __float2bfloat16(v);
  g_wthi[idx] = hi;
  g_wtlo[idx] = __float2bfloat16(v - __bfloat162float(hi));
}

// ---------------- K1: fused QKV on HMMA. grid=128, block=256 ----------------
__global__ __launch_bounds__(256, 1) void qkv(const float* __restrict__ x) {
  extern __shared__ char S[];
  const uint32_t XH = 0, XL = 18432, WB = 36864;
  const int t = threadIdx.x, w = t >> 5, lane = t & 31;
  const int g = lane >> 2, tq = lane & 3;
  const int row0 = blockIdx.x * 128;
  const uint32_t sb = su(S);
  const uint32_t arow = 16 * w + (lane & 15), aoff8 = (lane >> 4) * 8;
  const uint32_t brow = (lane & 7) + ((lane >> 4) & 1) * 8;
  const uint32_t boff8 = ((lane >> 3) & 1) * 8;

  float acc[3][8][4] = {};

  for (int kci = 0; kci < 8; kci++) {
    __syncthreads();
#pragma unroll
    for (int e = 0; e < 16; e++) {
      int idx = t + e * 256, r = idx >> 5, cp = idx & 31;
      float2 xv = *(const float2*)(x + (size_t)(row0 + r) * CC + kci * 64 + cp * 2);
      uint32_t hi, lo; split_pack(xv.x, xv.y, hi, lo);
      uint32_t off = (uint32_t)(r * 144 + cp * 4);
      *(uint32_t*)(S + XH + off) = hi;
      *(uint32_t*)(S + XL + off) = lo;
    }
#pragma unroll
    for (int e = 0; e < 24; e++) {
      int idx = t + e * 256;                 // < 6144
      int o = idx >> 11, r2 = idx & 2047, h = r2 >> 5, cp = r2 & 31;
      uint32_t gi = (uint32_t)(o * 16384 + h * 256 + kci * 32 + cp);
      uint32_t off = WB + o * 18432 + h * 144 + cp * 4;
      *(uint32_t*)(S + off)        = ((const uint32_t*)g_wthi)[gi];
      *(uint32_t*)(S + off + 9216) = ((const uint32_t*)g_wtlo)[gi];
    }
    __syncthreads();

#pragma unroll
    for (int s = 0; s < 4; s++) {
      uint32_t ah[4], al[4];
      uint32_t qa = sb + XH + arow * 144 + (s * 16 + aoff8) * 2;
      ldsm4(ah, qa);
      ldsm4(al, qa + XL);
#pragma unroll
      for (int o = 0; o < 3; o++) {
        uint32_t base = sb + WB + o * 18432;
#pragma unroll
        for (int p = 0; p < 4; p++) {
          uint32_t bh[4], bl[4];
          uint32_t ka = base + (p * 16 + brow) * 144 + (s * 16 + boff8) * 2;
          ldsm4(bh, ka);
          ldsm4(bl, ka + 9216);
          mma16816(acc[o][2*p],   ah, bh[0], bh[1]);
          mma16816(acc[o][2*p],   al, bh[0], bh[1]);
          mma16816(acc[o][2*p],   ah, bl[0], bl[1]);
          mma16816(acc[o][2*p+1], ah, bh[2], bh[3]);
          mma16816(acc[o][2*p+1], al, bh[2], bh[3]);
          mma16816(acc[o][2*p+1], ah, bl[2], bl[3]);
        }
      }
    }
  }

  const size_t ra = (size_t)(row0 + 16 * w + g), rb = ra + 8;
  // Q, K, V -> fp16 hi only
  {
    uint32_t* dq = (uint32_t*)g_qhi;
    uint32_t* dk = (uint32_t*)g_khi;
    uint32_t* dv = (uint32_t*)g_vhi;
#pragma unroll
    for (int nf = 0; nf < 8; nf++) {
      dq[ra * 32 + nf * 4 + tq] = packh(acc[0][nf][0], acc[0][nf][1]);
      dq[rb * 32 + nf * 4 + tq] = packh(acc[0][nf][2], acc[0][nf][3]);
      dk[ra * 32 + nf * 4 + tq] = packh(acc[1][nf][0], acc[1][nf][1]);
      dk[rb * 32 + nf * 4 + tq] = packh(acc[1][nf][2], acc[1][nf][3]);
      dv[ra * 32 + nf * 4 + tq] = packh(acc[2][nf][0], acc[2][nf][1]);
      dv[rb * 32 + nf * 4 + tq] = packh(acc[2][nf][2], acc[2][nf][3]);
    }
  }
}

// ---------------- K2: attention core. grid=(8,64), block=256 ----------------
// blockIdx.x = batch, blockIdx.y -> (rt, chunk of 8 jt tiles), heavy rt first.
// Chunks past the causal frontier only zero-fill their 512-col strip.
// smem: Qh[128][72]@0 | KV buf0@18432 buf1@36864 (55296 B total)
__global__ __launch_bounds__(256, 2) void attn(float* __restrict__ out) {
  extern __shared__ char S[];
  const uint32_t QH = 0, KV0 = 18432, KVSZ = 18432;
  const int t = threadIdx.x, w = t >> 5, lane = t & 31;
  const int g = lane >> 2, tq = lane & 3;
  const int b = blockIdx.x;
  const int rt = 15 - ((int)blockIdx.y >> 2), chunk = blockIdx.y & 3;
  const int jt0 = chunk * 8;
  const int ntiles = min(8, 2 * rt + 2 - jt0);   // may be <= 0 (pure fill)
  const int i0 = rt * 128;
  const uint32_t sb = su(S);

  float oa[8][4] = {};
  float la = 0.0f, lb = 0.0f;
  const int ia = i0 + 16 * w + g, ib = ia + 8;
  float* att = out + (size_t)BB * TT * HH + (size_t)b * TT * TT;

  if (ntiles > 0) {
    // async-load Q tile (1024 x 16B chunks)
#pragma unroll
    for (int e = 0; e < 4; e++) {
      int idx = t + e * 256, r = idx >> 3, c8 = idx & 7;   // idx < 1024
      size_t gb = ((size_t)(b * TT + i0 + r) * 64 + c8 * 8) * 2;
      uint32_t off = (uint32_t)(r * 144 + c8 * 16);
      cpa16(sb + QH + off, (const char*)g_qhi + gb);
    }
    // prefetch first KV tile into buf0
    {
      const int j0 = jt0 * 64;
#pragma unroll
      for (int e = 0; e < 2; e++) {
        int idx = t + e * 256, r = idx >> 3, c8 = idx & 7;  // idx < 512
        size_t gb = ((size_t)(b * TT + j0 + r) * 64 + c8 * 8) * 2;
        uint32_t off = KV0 + (uint32_t)(r * 144 + c8 * 16);
        cpa16(sb + off,        (const char*)g_khi + gb);
        cpa16(sb + off + 9216, (const char*)g_vhi + gb);
      }
    }
    CP_COMMIT();

    const uint32_t arow = 16 * w + (lane & 15), aoff8 = (lane >> 4) * 8;
    const uint32_t brow = (lane & 7) + ((lane >> 4) & 1) * 8;   // non-trans B
    const uint32_t boff8 = ((lane >> 3) & 1) * 8;
    const uint32_t vrow = (lane & 7) + ((lane >> 3) & 1) * 8;   // trans B
    const uint32_t voff8 = ((lane >> 4) & 1) * 8;

    for (int ti = 0; ti < ntiles; ti++) {
      const int j0 = (jt0 + ti) * 64;
      CP_WAIT0();
      __syncthreads();

      // prefetch next tile into other buffer
      if (ti + 1 < ntiles) {
        const int jn = (jt0 + ti + 1) * 64;
        const uint32_t nb = KV0 + ((ti + 1) & 1) * KVSZ;
#pragma unroll
        for (int e = 0; e < 2; e++) {
          int idx = t + e * 256, r = idx >> 3, c8 = idx & 7;
          size_t gb = ((size_t)(b * TT + jn + r) * 64 + c8 * 8) * 2;
          uint32_t off = nb + (uint32_t)(r * 144 + c8 * 16);
          cpa16(sb + off,        (const char*)g_khi + gb);
          cpa16(sb + off + 9216, (const char*)g_vhi + gb);
        }
      }
      CP_COMMIT();

      const uint32_t KB = KV0 + (ti & 1) * KVSZ;        // Khi base
      const uint32_t VB = KB + 9216;                     // Vhi base

      // ---- S = Q K^T (1-term fp16: qh*kh) ----
      float sa[8][4] = {};
#pragma unroll
      for (int s = 0; s < 4; s++) {
        uint32_t ah[4];
        uint32_t qa = sb + QH + arow * 144 + (s * 16 + aoff8) * 2;
        ldsm4(ah, qa);
#pragma unroll
        for (int p = 0; p < 4; p++) {
          uint32_t bh[4];
          uint32_t ka = sb + KB + (p * 16 + brow) * 144 + (s * 16 + boff8) * 2;
          ldsm4(bh, ka);
          mma16816h(sa[2*p],   ah, bh[0], bh[1]);
          mma16816h(sa[2*p+1], ah, bh[2], bh[3]);
        }
      }

      // ---- epilogue: exp + ALiBi + causal mask; write unnormalized att ----
#pragma unroll
      for (int nf = 0; nf < 8; nf++) {
        int j = j0 + nf * 8 + tq * 2;
        float p00 = (j     <= ia) ? __expf((sa[nf][0] + (float)(j     - ia)) * SCALEF) : 0.0f;
        float p01 = (j + 1 <= ia) ? __expf((sa[nf][1] + (float)(j + 1 - ia)) * SCALEF) : 0.0f;
        float p10 = (j     <= ib) ? __expf((sa[nf][2] + (float)(j     - ib)) * SCALEF) : 0.0f;
        float p11 = (j + 1 <= ib) ? __expf((sa[nf][3] + (float)(j + 1 - ib)) * SCALEF) : 0.0f;
        *(float2*)(att + (size_t)ia * TT + j) = make_float2(p00, p01);
        *(float2*)(att + (size_t)ib * TT + j) = make_float2(p10, p11);
        la += p00 + p01;
        lb += p10 + p11;
        sa[nf][0] = p00; sa[nf][1] = p01; sa[nf][2] = p10; sa[nf][3] = p11;
      }

      // ---- O += P V (1-term fp16: P rounded once) ----
#pragma unroll
      for (int s2 = 0; s2 < 4; s2++) {
        uint32_t ah[4];
        ah[0] = packh(sa[2*s2][0],   sa[2*s2][1]);
        ah[1] = packh(sa[2*s2][2],   sa[2*s2][3]);
        ah[2] = packh(sa[2*s2+1][0], sa[2*s2+1][1]);
        ah[3] = packh(sa[2*s2+1][2], sa[2*s2+1][3]);
#pragma unroll
        for (int p = 0; p < 4; p++) {
          uint32_t bh[4];
          uint32_t va = sb + VB + (s2 * 16 + vrow) * 144 + (p * 16 + voff8) * 2;
          ldsm4t(bh, va);
          mma16816h(oa[2*p],   ah, bh[0], bh[1]);
          mma16816h(oa[2*p+1], ah, bh[2], bh[3]);
        }
      }
    }
  }

  // ---- zero-fill the strictly-upper part of this block's 512-col strip ----
  {
    const int jf0 = max(jt0, 2 * rt + 2);           // first all-zero tile
    const int nf4 = (jt0 + 8 - jf0) * 16;           // f4 columns to fill
    if (nf4 > 0) {
      const float4 z = make_float4(0, 0, 0, 0);
      float4* a4 = (float4*)att;
      for (int r = w; r < 128; r += 8)
        for (int c = lane; c < nf4; c += 32)
          a4[(size_t)(i0 + r) * 512 + jf0 * 16 + c] = z;
    }
  }

  // quad-reduce row sums (tq lanes 0..3 share a row)
  la += __shfl_xor_sync(0xffffffffu, la, 1);
  la += __shfl_xor_sync(0xffffffffu, la, 2);
  lb += __shfl_xor_sync(0xffffffffu, lb, 1);
  lb += __shfl_xor_sync(0xffffffffu, lb, 2);
  if (tq == 0) {
    g_lpar[chunk * BB * TT + b * TT + ia] = la;
    g_lpar[chunk * BB * TT + b * TT + ib] = lb;
  }
  float* op = g_opar + (size_t)chunk * BB * TT * HH;
#pragma unroll
  for (int nf = 0; nf < 8; nf++) {
    int c = nf * 8 + tq * 2;
    *(float2*)(op + ((size_t)b * TT + ia) * HH + c) = make_float2(oa[nf][0], oa[nf][1]);
    *(float2*)(op + ((size_t)b * TT + ib) * HH + c) = make_float2(oa[nf][2], oa[nf][3]);
  }
}

// ---------------- Kc: combine 4 chunk slots, normalize O, emit l ------------
__global__ void kc(float* __restrict__ out) {
  int idx = blockIdx.x * 256 + threadIdx.x;   // float4 index < 262144
  int row = idx >> 4;
  float l = 0.0f;
  float4 s = make_float4(0, 0, 0, 0);
#pragma unroll
  for (int c = 0; c < 4; c++) {
    l += g_lpar[c * BB * TT + row];
    float4 a = ((const float4*)g_opar)[(size_t)c * (BB * TT * HH / 4) + idx];
    s.x += a.x; s.y += a.y; s.z += a.z; s.w += a.w;
  }
  float inv = 1.0f / l;
  ((float4*)out)[idx] = make_float4(s.x * inv, s.y * inv, s.z * inv, s.w * inv);
  if ((idx & 15) == 0) g_l[row] = l;
}

// ---------------- K3: normalize att lower triangle only ---------------------
__global__ __launch_bounds__(256) void k3(float* __restrict__ out) {
  const int b = blockIdx.x;
  const int rt = 15 - ((int)blockIdx.y >> 2), sl = blockIdx.y & 3;
  const int cend = (rt + 1) * 32;             // f4 columns that were written
  const int c0 = sl * 128;
  if (c0 >= cend) return;
  __shared__ float linv[128];
  if (threadIdx.x < 128)
    linv[threadIdx.x] = 1.0f / g_l[b * TT + rt * 128 + threadIdx.x];
  __syncthreads();
  float4* att = (float4*)(out + (size_t)BB * TT * HH + (size_t)b * TT * TT);
  for (int idx = threadIdx.x; idx < 128 * 128; idx += 256) {
    int r = idx >> 7, c = (idx & 127) + c0;
    if (c >= cend) continue;
    size_t gi = (size_t)(rt * 128 + r) * 512 + c;
    float4 v = att[gi];
    float iv = linv[r];
    v.x *= iv; v.y *= iv; v.z *= iv; v.w *= iv;
    att[gi] = v;
  }
}

// ---------------------------------------------------------------------------
extern "C" void kernel_launch(void* const* d_in, const int* in_sizes, int n_in,
                              void* d_out, int out_size) {
  const float* x  = (const float*)d_in[0];
  const float* Wq = (const float*)d_in[1];
  const float* Wk = (const float*)d_in[2];
  const float* Wv = (const float*)d_in[3];
  float* out = (float*)d_out;

  k0<<<384, 256>>>(Wq, Wk, Wv);

  cudaFuncSetAttribute(qkv, cudaFuncAttributeMaxDynamicSharedMemorySize, 92160);
  qkv<<<128, 256, 92160>>>(x);

  cudaFuncSetAttribute(attn, cudaFuncAttributeMaxDynamicSharedMemorySize, 55296);
  cudaFuncSetAttribute(attn, cudaFuncAttributePreferredSharedMemoryCarveout,
                       cudaSharedmemCarveoutMaxShared);
  attn<<<dim3(8, 64), 256, 55296>>>(out);

  kc<<<1024, 256>>>(out);
  k3<<<dim3(8, 64), 256>>>(out);
}

// round 11
// speedup vs baseline: 3.3305x; 1.0283x over previous
#include <cuda_runtime.h>
#include <cuda_bf16.h>
#include <cuda_fp16.h>
#include <stdint.h>

#define BB 8
#define TT 2048
#define CC 512
#define HH 64
#define SCALEF 0.044194173824159216f   // 512^-0.5

// ---------------- scratch (device globals: allocation-free) ----------------
__device__ __half g_qhi[BB*TT*HH];                    // fp16 (1-term S)
__device__ __half g_khi[BB*TT*HH];                    // fp16, hi only
__device__ __half g_vhi[BB*TT*HH];                    // fp16, hi only
__device__ __nv_bfloat16 g_wthi[3*HH*CC], g_wtlo[3*HH*CC];   // [w][h][c]
__device__ float g_opar[4ll*BB*TT*HH];
__device__ float g_lpar[4*BB*TT];
__device__ float g_l[BB*TT];

// ---------------- helpers ----------------
__device__ __forceinline__ uint32_t su(const void* p) {
  uint32_t a;
  asm("{ .reg .u64 t; cvta.to.shared.u64 t, %1; cvt.u32.u64 %0, t; }" : "=r"(a) : "l"(p));
  return a;
}
__device__ __forceinline__ void ldsm4(uint32_t* r, uint32_t a) {
  asm volatile("ldmatrix.sync.aligned.m8n8.x4.shared.b16 {%0,%1,%2,%3}, [%4];"
    : "=r"(r[0]), "=r"(r[1]), "=r"(r[2]), "=r"(r[3]) : "r"(a));
}
__device__ __forceinline__ void ldsm4t(uint32_t* r, uint32_t a) {
  asm volatile("ldmatrix.sync.aligned.m8n8.x4.trans.shared.b16 {%0,%1,%2,%3}, [%4];"
    : "=r"(r[0]), "=r"(r[1]), "=r"(r[2]), "=r"(r[3]) : "r"(a));
}
__device__ __forceinline__ void mma16816(float* d, const uint32_t* a, uint32_t b0, uint32_t b1) {
  asm volatile("mma.sync.aligned.m16n8k16.row.col.f32.bf16.bf16.f32 "
    "{%0,%1,%2,%3}, {%4,%5,%6,%7}, {%8,%9}, {%0,%1,%2,%3};"
    : "+f"(d[0]), "+f"(d[1]), "+f"(d[2]), "+f"(d[3])
    : "r"(a[0]), "r"(a[1]), "r"(a[2]), "r"(a[3]), "r"(b0), "r"(b1));
}
__device__ __forceinline__ void mma16816h(float* d, const uint32_t* a, uint32_t b0, uint32_t b1) {
  asm volatile("mma.sync.aligned.m16n8k16.row.col.f32.f16.f16.f32 "
    "{%0,%1,%2,%3}, {%4,%5,%6,%7}, {%8,%9}, {%0,%1,%2,%3};"
    : "+f"(d[0]), "+f"(d[1]), "+f"(d[2]), "+f"(d[3])
    : "r"(a[0]), "r"(a[1]), "r"(a[2]), "r"(a[3]), "r"(b0), "r"(b1));
}
__device__ __forceinline__ void split_pack(float a, float b, uint32_t& hi, uint32_t& lo) {
  __nv_bfloat162 h = __floats2bfloat162_rn(a, b);
  __nv_bfloat162 l = __floats2bfloat162_rn(a - __bfloat162float(h.x),
                                           b - __bfloat162float(h.y));
  hi = *reinterpret_cast<uint32_t*>(&h);
  lo = *reinterpret_cast<uint32_t*>(&l);
}
__device__ __forceinline__ uint32_t packh(float a, float b) {
  __half2 h = __floats2half2_rn(a, b);
  return *reinterpret_cast<uint32_t*>(&h);
}
__device__ __forceinline__ void cpa16(uint32_t s, const void* g) {
  asm volatile("cp.async.cg.shared.global [%0], [%1], 16;" :: "r"(s), "l"(g) : "memory");
}
__device__ __forceinline__ void stg2cs(float* p, float x, float y) {
  asm volatile("st.global.cs.v2.f32 [%0], {%1, %2};" :: "l"(p), "f"(x), "f"(y) : "memory");
}
#define CP_COMMIT() asm volatile("cp.async.commit_group;" ::: "memory")
#define CP_WAIT0()  asm volatile("cp.async.wait_group 0;" ::: "memory")

// ---------------- K0: weight transpose + split ----------------
__global__ void k0(const float* __restrict__ Wq, const float* __restrict__ Wk,
                   const float* __restrict__ Wv) {
  int idx = blockIdx.x * 256 + threadIdx.x;          // < 3*64*512
  int w = idx >> 15, rem = idx & 32767, h = rem >> 9, c = rem & 511;
  const float* W = (w == 0) ? Wq : ((w == 1) ? Wk : Wv);
  float v = W[(size_t)c * HH + h];
  __nv_bfloat16 hi = __float2bfloat16(v);
  g_wthi[idx] = hi;
  g_wtlo[idx] = __float2bfloat16(v - __bfloat162float(hi));
}

// ---------------- K1: fused QKV on HMMA. grid=128, block=256 ----------------
__global__ __launch_bounds__(256, 1) void qkv(const float* __restrict__ x) {
  extern __shared__ char S[];
  const uint32_t XH = 0, XL = 18432, WB = 36864;
  const int t = threadIdx.x, w = t >> 5, lane = t & 31;
  const int g = lane >> 2, tq = lane & 3;
  const int row0 = blockIdx.x * 128;
  const uint32_t sb = su(S);
  const uint32_t arow = 16 * w + (lane & 15), aoff8 = (lane >> 4) * 8;
  const uint32_t brow = (lane & 7) + ((lane >> 4) & 1) * 8;
  const uint32_t boff8 = ((lane >> 3) & 1) * 8;

  float acc[3][8][4] = {};

  for (int kci = 0; kci < 8; kci++) {
    __syncthreads();
#pragma unroll
    for (int e = 0; e < 16; e++) {
      int idx = t + e * 256, r = idx >> 5, cp = idx & 31;
      float2 xv = *(const float2*)(x + (size_t)(row0 + r) * CC + kci * 64 + cp * 2);
      uint32_t hi, lo; split_pack(xv.x, xv.y, hi, lo);
      uint32_t off = (uint32_t)(r * 144 + cp * 4);
      *(uint32_t*)(S + XH + off) = hi;
      *(uint32_t*)(S + XL + off) = lo;
    }
#pragma unroll
    for (int e = 0; e < 24; e++) {
      int idx = t + e * 256;                 // < 6144
      int o = idx >> 11, r2 = idx & 2047, h = r2 >> 5, cp = r2 & 31;
      uint32_t gi = (uint32_t)(o * 16384 + h * 256 + kci * 32 + cp);
      uint32_t off = WB + o * 18432 + h * 144 + cp * 4;
      *(uint32_t*)(S + off)        = ((const uint32_t*)g_wthi)[gi];
      *(uint32_t*)(S + off + 9216) = ((const uint32_t*)g_wtlo)[gi];
    }
    __syncthreads();

#pragma unroll
    for (int s = 0; s < 4; s++) {
      uint32_t ah[4], al[4];
      uint32_t qa = sb + XH + arow * 144 + (s * 16 + aoff8) * 2;
      ldsm4(ah, qa);
      ldsm4(al, qa + XL);
#pragma unroll
      for (int o = 0; o < 3; o++) {
        uint32_t base = sb + WB + o * 18432;
#pragma unroll
        for (int p = 0; p < 4; p++) {
          uint32_t bh[4], bl[4];
          uint32_t ka = base + (p * 16 + brow) * 144 + (s * 16 + boff8) * 2;
          ldsm4(bh, ka);
          ldsm4(bl, ka + 9216);
          mma16816(acc[o][2*p],   ah, bh[0], bh[1]);
          mma16816(acc[o][2*p],   al, bh[0], bh[1]);
          mma16816(acc[o][2*p],   ah, bl[0], bl[1]);
          mma16816(acc[o][2*p+1], ah, bh[2], bh[3]);
          mma16816(acc[o][2*p+1], al, bh[2], bh[3]);
          mma16816(acc[o][2*p+1], ah, bl[2], bl[3]);
        }
      }
    }
  }

  const size_t ra = (size_t)(row0 + 16 * w + g), rb = ra + 8;
  // Q, K, V -> fp16 hi only
  {
    uint32_t* dq = (uint32_t*)g_qhi;
    uint32_t* dk = (uint32_t*)g_khi;
    uint32_t* dv = (uint32_t*)g_vhi;
#pragma unroll
    for (int nf = 0; nf < 8; nf++) {
      dq[ra * 32 + nf * 4 + tq] = packh(acc[0][nf][0], acc[0][nf][1]);
      dq[rb * 32 + nf * 4 + tq] = packh(acc[0][nf][2], acc[0][nf][3]);
      dk[ra * 32 + nf * 4 + tq] = packh(acc[1][nf][0], acc[1][nf][1]);
      dk[rb * 32 + nf * 4 + tq] = packh(acc[1][nf][2], acc[1][nf][3]);
      dv[ra * 32 + nf * 4 + tq] = packh(acc[2][nf][0], acc[2][nf][1]);
      dv[rb * 32 + nf * 4 + tq] = packh(acc[2][nf][2], acc[2][nf][3]);
    }
  }
}

// ---------------- K2: attention core. grid=(8,64), block=256 ----------------
// blockIdx.x = batch, blockIdx.y -> (rt, chunk of 8 jt tiles), heavy rt first.
// Pair-tile iterations: 128 keys per sync (two 64-key sub-tiles, no barrier
// between). Chunks past the causal frontier only zero-fill their strip.
// smem: Qh[128][72]@0 | KV buf0@18432 buf1@55296 (92160 B total)
//   each KV buf: Kh[128][144]@+0, Vh[128][144]@+18432
__global__ __launch_bounds__(256, 2) void attn(float* __restrict__ out) {
  extern __shared__ char S[];
  const uint32_t QH = 0, KV0 = 18432, KVSZ = 36864;
  const int t = threadIdx.x, w = t >> 5, lane = t & 31;
  const int g = lane >> 2, tq = lane & 3;
  const int b = blockIdx.x;
  const int rt = 15 - ((int)blockIdx.y >> 2), chunk = blockIdx.y & 3;
  const int jt0 = chunk * 8;
  const int ntiles = min(8, 2 * rt + 2 - jt0);   // may be <= 0 (pure fill)
  const int i0 = rt * 128;
  const uint32_t sb = su(S);

  float oa[8][4] = {};
  float la = 0.0f, lb = 0.0f;
  const int ia = i0 + 16 * w + g, ib = ia + 8;
  float* att = out + (size_t)BB * TT * HH + (size_t)b * TT * TT;

  if (ntiles > 0) {
    const int npairs = ntiles >> 1;            // ntiles is always even
    // async-load Q tile (1024 x 16B chunks)
#pragma unroll
    for (int e = 0; e < 4; e++) {
      int idx = t + e * 256, r = idx >> 3, c8 = idx & 7;   // idx < 1024
      size_t gb = ((size_t)(b * TT + i0 + r) * 64 + c8 * 8) * 2;
      uint32_t off = (uint32_t)(r * 144 + c8 * 16);
      cpa16(sb + QH + off, (const char*)g_qhi + gb);
    }
    // prefetch first KV pair (128 keys) into buf0
    {
      const int j0 = jt0 * 64;
#pragma unroll
      for (int e = 0; e < 4; e++) {
        int idx = t + e * 256, r = idx >> 3, c8 = idx & 7;  // idx < 1024
        size_t gb = ((size_t)(b * TT + j0 + r) * 64 + c8 * 8) * 2;
        uint32_t off = KV0 + (uint32_t)(r * 144 + c8 * 16);
        cpa16(sb + off,         (const char*)g_khi + gb);
        cpa16(sb + off + 18432, (const char*)g_vhi + gb);
      }
    }
    CP_COMMIT();

    const uint32_t arow = 16 * w + (lane & 15), aoff8 = (lane >> 4) * 8;
    const uint32_t brow = (lane & 7) + ((lane >> 4) & 1) * 8;   // non-trans B
    const uint32_t boff8 = ((lane >> 3) & 1) * 8;
    const uint32_t vrow = (lane & 7) + ((lane >> 3) & 1) * 8;   // trans B
    const uint32_t voff8 = ((lane >> 4) & 1) * 8;

    for (int it = 0; it < npairs; it++) {
      CP_WAIT0();
      __syncthreads();

      // prefetch next pair into other buffer
      if (it + 1 < npairs) {
        const int jn = (jt0 + 2 * (it + 1)) * 64;
        const uint32_t nb = KV0 + ((it + 1) & 1) * KVSZ;
#pragma unroll
        for (int e = 0; e < 4; e++) {
          int idx = t + e * 256, r = idx >> 3, c8 = idx & 7;
          size_t gb = ((size_t)(b * TT + jn + r) * 64 + c8 * 8) * 2;
          uint32_t off = nb + (uint32_t)(r * 144 + c8 * 16);
          cpa16(sb + off,         (const char*)g_khi + gb);
          cpa16(sb + off + 18432, (const char*)g_vhi + gb);
        }
      }
      CP_COMMIT();

      const uint32_t buf = KV0 + (it & 1) * KVSZ;

#pragma unroll
      for (int half = 0; half < 2; half++) {
        const int j0 = (jt0 + 2 * it + half) * 64;
        const uint32_t KB = buf + half * 9216;           // Khi rows 64*half..
        const uint32_t VB = buf + 18432 + half * 9216;   // Vhi rows 64*half..

        // ---- S = Q K^T (1-term fp16: qh*kh) ----
        float sa[8][4] = {};
#pragma unroll
        for (int s = 0; s < 4; s++) {
          uint32_t ah[4];
          uint32_t qa = sb + QH + arow * 144 + (s * 16 + aoff8) * 2;
          ldsm4(ah, qa);
#pragma unroll
          for (int p = 0; p < 4; p++) {
            uint32_t bh[4];
            uint32_t ka = sb + KB + (p * 16 + brow) * 144 + (s * 16 + boff8) * 2;
            ldsm4(bh, ka);
            mma16816h(sa[2*p],   ah, bh[0], bh[1]);
            mma16816h(sa[2*p+1], ah, bh[2], bh[3]);
          }
        }

        // ---- epilogue: exp(fma) + causal mask; streamed att stores ----
#pragma unroll
        for (int nf = 0; nf < 8; nf++) {
          int j = j0 + nf * 8 + tq * 2;
          float ca0 = (float)(j - ia) * SCALEF, cb0 = (float)(j - ib) * SCALEF;
          float p00 = (j     <= ia) ? __expf(fmaf(sa[nf][0], SCALEF, ca0)) : 0.0f;
          float p01 = (j + 1 <= ia) ? __expf(fmaf(sa[nf][1], SCALEF, ca0 + SCALEF)) : 0.0f;
          float p10 = (j     <= ib) ? __expf(fmaf(sa[nf][2], SCALEF, cb0)) : 0.0f;
          float p11 = (j + 1 <= ib) ? __expf(fmaf(sa[nf][3], SCALEF, cb0 + SCALEF)) : 0.0f;
          stg2cs(att + (size_t)ia * TT + j, p00, p01);
          stg2cs(att + (size_t)ib * TT + j, p10, p11);
          la += p00 + p01;
          lb += p10 + p11;
          sa[nf][0] = p00; sa[nf][1] = p01; sa[nf][2] = p10; sa[nf][3] = p11;
        }

        // ---- O += P V (1-term fp16: P rounded once) ----
#pragma unroll
        for (int s2 = 0; s2 < 4; s2++) {
          uint32_t ah[4];
          ah[0] = packh(sa[2*s2][0],   sa[2*s2][1]);
          ah[1] = packh(sa[2*s2][2],   sa[2*s2][3]);
          ah[2] = packh(sa[2*s2+1][0], sa[2*s2+1][1]);
          ah[3] = packh(sa[2*s2+1][2], sa[2*s2+1][3]);
#pragma unroll
          for (int p = 0; p < 4; p++) {
            uint32_t bh[4];
            uint32_t va = sb + VB + (s2 * 16 + vrow) * 144 + (p * 16 + voff8) * 2;
            ldsm4t(bh, va);
            mma16816h(oa[2*p],   ah, bh[0], bh[1]);
            mma16816h(oa[2*p+1], ah, bh[2], bh[3]);
          }
        }
      }
    }
  }

  // ---- zero-fill the strictly-upper part of this block's 512-col strip ----
  {
    const int jf0 = max(jt0, 2 * rt + 2);           // first all-zero tile
    const int nf4 = (jt0 + 8 - jf0) * 16;           // f4 columns to fill
    if (nf4 > 0) {
      const float4 z = make_float4(0, 0, 0, 0);
      float4* a4 = (float4*)att;
      for (int r = w; r < 128; r += 8)
        for (int c = lane; c < nf4; c += 32)
          __stcs(&a4[(size_t)(i0 + r) * 512 + jf0 * 16 + c], z);
    }
  }

  // quad-reduce row sums (tq lanes 0..3 share a row)
  la += __shfl_xor_sync(0xffffffffu, la, 1);
  la += __shfl_xor_sync(0xffffffffu, la, 2);
  lb += __shfl_xor_sync(0xffffffffu, lb, 1);
  lb += __shfl_xor_sync(0xffffffffu, lb, 2);
  if (tq == 0) {
    g_lpar[chunk * BB * TT + b * TT + ia] = la;
    g_lpar[chunk * BB * TT + b * TT + ib] = lb;
  }
  float* op = g_opar + (size_t)chunk * BB * TT * HH;
#pragma unroll
  for (int nf = 0; nf < 8; nf++) {
    int c = nf * 8 + tq * 2;
    stg2cs(op + ((size_t)b * TT + ia) * HH + c, oa[nf][0], oa[nf][1]);
    stg2cs(op + ((size_t)b * TT + ib) * HH + c, oa[nf][2], oa[nf][3]);
  }
}

// ---------------- Kc: combine 4 chunk slots, normalize O, emit l ------------
__global__ void kc(float* __restrict__ out) {
  int idx = blockIdx.x * 256 + threadIdx.x;   // float4 index < 262144
  int row = idx >> 4;
  float l = 0.0f;
  float4 s = make_float4(0, 0, 0, 0);
#pragma unroll
  for (int c = 0; c < 4; c++) {
    l += g_lpar[c * BB * TT + row];
    float4 a = __ldcs(((const float4*)g_opar) + (size_t)c * (BB * TT * HH / 4) + idx);
    s.x += a.x; s.y += a.y; s.z += a.z; s.w += a.w;
  }
  float inv = 1.0f / l;
  __stcs(((float4*)out) + idx,
         make_float4(s.x * inv, s.y * inv, s.z * inv, s.w * inv));
  if ((idx & 15) == 0) g_l[row] = l;
}

// ---------------- K3: normalize att lower triangle only ---------------------
__global__ __launch_bounds__(256) void k3(float* __restrict__ out) {
  const int b = blockIdx.x;
  const int rt = 15 - ((int)blockIdx.y >> 2), sl = blockIdx.y & 3;
  const int cend = (rt + 1) * 32;             // f4 columns that were written
  const int c0 = sl * 128;
  if (c0 >= cend) return;
  __shared__ float linv[128];
  if (threadIdx.x < 128)
    linv[threadIdx.x] = 1.0f / g_l[b * TT + rt * 128 + threadIdx.x];
  __syncthreads();
  float4* att = (float4*)(out + (size_t)BB * TT * HH + (size_t)b * TT * TT);
  for (int idx = threadIdx.x; idx < 128 * 128; idx += 256) {
    int r = idx >> 7, c = (idx & 127) + c0;
    if (c >= cend) continue;
    size_t gi = (size_t)(rt * 128 + r) * 512 + c;
    float4 v = __ldcs(&att[gi]);
    float iv = linv[r];
    v.x *= iv; v.y *= iv; v.z *= iv; v.w *= iv;
    __stcs(&att[gi], v);
  }
}

// ---------------------------------------------------------------------------
extern "C" void kernel_launch(void* const* d_in, const int* in_sizes, int n_in,
                              void* d_out, int out_size) {
  const float* x  = (const float*)d_in[0];
  const float* Wq = (const float*)d_in[1];
  const float* Wk = (const float*)d_in[2];
  const float* Wv = (const float*)d_in[3];
  float* out = (float*)d_out;

  k0<<<384, 256>>>(Wq, Wk, Wv);

  cudaFuncSetAttribute(qkv, cudaFuncAttributeMaxDynamicSharedMemorySize, 92160);
  qkv<<<128, 256, 92160>>>(x);

  cudaFuncSetAttribute(attn, cudaFuncAttributeMaxDynamicSharedMemorySize, 92160);
  cudaFuncSetAttribute(attn, cudaFuncAttributePreferredSharedMemoryCarveout,
                       cudaSharedmemCarveoutMaxShared);
  attn<<<dim3(8, 64), 256, 92160>>>(out);

  kc<<<1024, 256>>>(out);
  k3<<<dim3(8, 64), 256>>>(out);
}

// round 12
// speedup vs baseline: 3.8810x; 1.1653x over previous
#include <cuda_runtime.h>
#include <cuda_bf16.h>
#include <cuda_fp16.h>
#include <stdint.h>

#define BB 8
#define TT 2048
#define CC 512
#define HH 64
#define SCALEF 0.044194173824159216f   // 512^-0.5

// ---------------- scratch (device globals: allocation-free) ----------------
__device__ __half g_qhi[BB*TT*HH];                    // fp16 (1-term S)
__device__ __half g_khi[BB*TT*HH];                    // fp16, hi only
__device__ __half g_vhi[BB*TT*HH];                    // fp16, hi only
__device__ __nv_bfloat16 g_wthi[3*HH*CC], g_wtlo[3*HH*CC];   // [w][h][c]
__device__ float g_lpar[4*BB*TT];

// ---------------- helpers ----------------
__device__ __forceinline__ uint32_t su(const void* p) {
  uint32_t a;
  asm("{ .reg .u64 t; cvta.to.shared.u64 t, %1; cvt.u32.u64 %0, t; }" : "=r"(a) : "l"(p));
  return a;
}
__device__ __forceinline__ void ldsm4(uint32_t* r, uint32_t a) {
  asm volatile("ldmatrix.sync.aligned.m8n8.x4.shared.b16 {%0,%1,%2,%3}, [%4];"
    : "=r"(r[0]), "=r"(r[1]), "=r"(r[2]), "=r"(r[3]) : "r"(a));
}
__device__ __forceinline__ void ldsm4t(uint32_t* r, uint32_t a) {
  asm volatile("ldmatrix.sync.aligned.m8n8.x4.trans.shared.b16 {%0,%1,%2,%3}, [%4];"
    : "=r"(r[0]), "=r"(r[1]), "=r"(r[2]), "=r"(r[3]) : "r"(a));
}
__device__ __forceinline__ void mma16816(float* d, const uint32_t* a, uint32_t b0, uint32_t b1) {
  asm volatile("mma.sync.aligned.m16n8k16.row.col.f32.bf16.bf16.f32 "
    "{%0,%1,%2,%3}, {%4,%5,%6,%7}, {%8,%9}, {%0,%1,%2,%3};"
    : "+f"(d[0]), "+f"(d[1]), "+f"(d[2]), "+f"(d[3])
    : "r"(a[0]), "r"(a[1]), "r"(a[2]), "r"(a[3]), "r"(b0), "r"(b1));
}
__device__ __forceinline__ void mma16816h(float* d, const uint32_t* a, uint32_t b0, uint32_t b1) {
  asm volatile("mma.sync.aligned.m16n8k16.row.col.f32.f16.f16.f32 "
    "{%0,%1,%2,%3}, {%4,%5,%6,%7}, {%8,%9}, {%0,%1,%2,%3};"
    : "+f"(d[0]), "+f"(d[1]), "+f"(d[2]), "+f"(d[3])
    : "r"(a[0]), "r"(a[1]), "r"(a[2]), "r"(a[3]), "r"(b0), "r"(b1));
}
__device__ __forceinline__ void split_pack(float a, float b, uint32_t& hi, uint32_t& lo) {
  __nv_bfloat162 h = __floats2bfloat162_rn(a, b);
  __nv_bfloat162 l = __floats2bfloat162_rn(a - __bfloat162float(h.x),
                                           b - __bfloat162float(h.y));
  hi = *reinterpret_cast<uint32_t*>(&h);
  lo = *reinterpret_cast<uint32_t*>(&l);
}
__device__ __forceinline__ uint32_t packh(float a, float b) {
  __half2 h = __floats2half2_rn(a, b);
  return *reinterpret_cast<uint32_t*>(&h);
}
__device__ __forceinline__ void cpa16(uint32_t s, const void* g) {
  asm volatile("cp.async.cg.shared.global [%0], [%1], 16;" :: "r"(s), "l"(g) : "memory");
}
__device__ __forceinline__ void stg2cs(float* p, float x, float y) {
  asm volatile("st.global.cs.v2.f32 [%0], {%1, %2};" :: "l"(p), "f"(x), "f"(y) : "memory");
}
#define CP_COMMIT() asm volatile("cp.async.commit_group;" ::: "memory")
#define CP_WAIT0()  asm volatile("cp.async.wait_group 0;" ::: "memory")

// ---------------- K0: weight transpose + split ----------------
__global__ void k0(const float* __restrict__ Wq, const float* __restrict__ Wk,
                   const float* __restrict__ Wv) {
  int idx = blockIdx.x * 256 + threadIdx.x;          // < 3*64*512
  int w = idx >> 15, rem = idx & 32767, h = rem >> 9, c = rem & 511;
  const float* W = (w == 0) ? Wq : ((w == 1) ? Wk : Wv);
  float v = W[(size_t)c * HH + h];
  __nv_bfloat16 hi = __float2bfloat16(v);
  g_wthi[idx] = hi;
  g_wtlo[idx] = __float2bfloat16(v - __bfloat162float(hi));
}

// ---------------- Kz: zero the output head region ----------------
__global__ void kz(float* __restrict__ out) {
  ((float4*)out)[blockIdx.x * 256 + threadIdx.x] = make_float4(0, 0, 0, 0);
}

// ---------------- K1: fused QKV on HMMA. grid=128, block=256 ----------------
__global__ __launch_bounds__(256, 1) void qkv(const float* __restrict__ x) {
  extern __shared__ char S[];
  const uint32_t XH = 0, XL = 18432, WB = 36864;
  const int t = threadIdx.x, w = t >> 5, lane = t & 31;
  const int g = lane >> 2, tq = lane & 3;
  const int row0 = blockIdx.x * 128;
  const uint32_t sb = su(S);
  const uint32_t arow = 16 * w + (lane & 15), aoff8 = (lane >> 4) * 8;
  const uint32_t brow = (lane & 7) + ((lane >> 4) & 1) * 8;
  const uint32_t boff8 = ((lane >> 3) & 1) * 8;

  float acc[3][8][4] = {};

  for (int kci = 0; kci < 8; kci++) {
    __syncthreads();
#pragma unroll
    for (int e = 0; e < 16; e++) {
      int idx = t + e * 256, r = idx >> 5, cp = idx & 31;
      float2 xv = *(const float2*)(x + (size_t)(row0 + r) * CC + kci * 64 + cp * 2);
      uint32_t hi, lo; split_pack(xv.x, xv.y, hi, lo);
      uint32_t off = (uint32_t)(r * 144 + cp * 4);
      *(uint32_t*)(S + XH + off) = hi;
      *(uint32_t*)(S + XL + off) = lo;
    }
#pragma unroll
    for (int e = 0; e < 24; e++) {
      int idx = t + e * 256;                 // < 6144
      int o = idx >> 11, r2 = idx & 2047, h = r2 >> 5, cp = r2 & 31;
      uint32_t gi = (uint32_t)(o * 16384 + h * 256 + kci * 32 + cp);
      uint32_t off = WB + o * 18432 + h * 144 + cp * 4;
      *(uint32_t*)(S + off)        = ((const uint32_t*)g_wthi)[gi];
      *(uint32_t*)(S + off + 9216) = ((const uint32_t*)g_wtlo)[gi];
    }
    __syncthreads();

#pragma unroll
    for (int s = 0; s < 4; s++) {
      uint32_t ah[4], al[4];
      uint32_t qa = sb + XH + arow * 144 + (s * 16 + aoff8) * 2;
      ldsm4(ah, qa);
      ldsm4(al, qa + XL);
#pragma unroll
      for (int o = 0; o < 3; o++) {
        uint32_t base = sb + WB + o * 18432;
#pragma unroll
        for (int p = 0; p < 4; p++) {
          uint32_t bh[4], bl[4];
          uint32_t ka = base + (p * 16 + brow) * 144 + (s * 16 + boff8) * 2;
          ldsm4(bh, ka);
          ldsm4(bl, ka + 9216);
          mma16816(acc[o][2*p],   ah, bh[0], bh[1]);
          mma16816(acc[o][2*p],   al, bh[0], bh[1]);
          mma16816(acc[o][2*p],   ah, bl[0], bl[1]);
          mma16816(acc[o][2*p+1], ah, bh[2], bh[3]);
          mma16816(acc[o][2*p+1], al, bh[2], bh[3]);
          mma16816(acc[o][2*p+1], ah, bl[2], bl[3]);
        }
      }
    }
  }

  const size_t ra = (size_t)(row0 + 16 * w + g), rb = ra + 8;
  {
    uint32_t* dq = (uint32_t*)g_qhi;
    uint32_t* dk = (uint32_t*)g_khi;
    uint32_t* dv = (uint32_t*)g_vhi;
#pragma unroll
    for (int nf = 0; nf < 8; nf++) {
      dq[ra * 32 + nf * 4 + tq] = packh(acc[0][nf][0], acc[0][nf][1]);
      dq[rb * 32 + nf * 4 + tq] = packh(acc[0][nf][2], acc[0][nf][3]);
      dk[ra * 32 + nf * 4 + tq] = packh(acc[1][nf][0], acc[1][nf][1]);
      dk[rb * 32 + nf * 4 + tq] = packh(acc[1][nf][2], acc[1][nf][3]);
      dv[ra * 32 + nf * 4 + tq] = packh(acc[2][nf][0], acc[2][nf][1]);
      dv[rb * 32 + nf * 4 + tq] = packh(acc[2][nf][2], acc[2][nf][3]);
    }
  }
}

// ---------------- K2a: row-sum pass. grid=(8,64), block=256 ----------------
// smem: Qh[128][72]@0 | K buf0@18432 buf1@27648 (36864 B total)
__global__ __launch_bounds__(256, 3) void attnA() {
  extern __shared__ char S[];
  const uint32_t QH = 0, KBASE = 18432, KSZ = 9216;
  const int t = threadIdx.x, w = t >> 5, lane = t & 31;
  const int g = lane >> 2, tq = lane & 3;
  const int b = blockIdx.x;
  const int rt = 15 - ((int)blockIdx.y >> 2), chunk = blockIdx.y & 3;
  const int jt0 = chunk * 8;
  const int ntiles = min(8, 2 * rt + 2 - jt0);
  const int i0 = rt * 128;
  const uint32_t sb = su(S);

  float la = 0.0f, lb = 0.0f;
  const int ia = i0 + 16 * w + g, ib = ia + 8;

  if (ntiles > 0) {
#pragma unroll
    for (int e = 0; e < 4; e++) {
      int idx = t + e * 256, r = idx >> 3, c8 = idx & 7;   // idx < 1024
      size_t gb = ((size_t)(b * TT + i0 + r) * 64 + c8 * 8) * 2;
      cpa16(sb + QH + (uint32_t)(r * 144 + c8 * 16), (const char*)g_qhi + gb);
    }
    {
      const int j0 = jt0 * 64;
#pragma unroll
      for (int e = 0; e < 2; e++) {
        int idx = t + e * 256, r = idx >> 3, c8 = idx & 7;  // idx < 512
        size_t gb = ((size_t)(b * TT + j0 + r) * 64 + c8 * 8) * 2;
        cpa16(sb + KBASE + (uint32_t)(r * 144 + c8 * 16), (const char*)g_khi + gb);
      }
    }
    CP_COMMIT();

    const uint32_t arow = 16 * w + (lane & 15), aoff8 = (lane >> 4) * 8;
    const uint32_t brow = (lane & 7) + ((lane >> 4) & 1) * 8;
    const uint32_t boff8 = ((lane >> 3) & 1) * 8;

    for (int ti = 0; ti < ntiles; ti++) {
      const int j0 = (jt0 + ti) * 64;
      CP_WAIT0();
      __syncthreads();

      if (ti + 1 < ntiles) {
        const int jn = (jt0 + ti + 1) * 64;
        const uint32_t nb = KBASE + ((ti + 1) & 1) * KSZ;
#pragma unroll
        for (int e = 0; e < 2; e++) {
          int idx = t + e * 256, r = idx >> 3, c8 = idx & 7;
          size_t gb = ((size_t)(b * TT + jn + r) * 64 + c8 * 8) * 2;
          cpa16(sb + nb + (uint32_t)(r * 144 + c8 * 16), (const char*)g_khi + gb);
        }
      }
      CP_COMMIT();

      const uint32_t KB = KBASE + (ti & 1) * KSZ;

      float sa[8][4] = {};
#pragma unroll
      for (int s = 0; s < 4; s++) {
        uint32_t ah[4];
        ldsm4(ah, sb + QH + arow * 144 + (s * 16 + aoff8) * 2);
#pragma unroll
        for (int p = 0; p < 4; p++) {
          uint32_t bh[4];
          ldsm4(bh, sb + KB + (p * 16 + brow) * 144 + (s * 16 + boff8) * 2);
          mma16816h(sa[2*p],   ah, bh[0], bh[1]);
          mma16816h(sa[2*p+1], ah, bh[2], bh[3]);
        }
      }

#pragma unroll
      for (int nf = 0; nf < 8; nf++) {
        int j = j0 + nf * 8 + tq * 2;
        float ca0 = (float)(j - ia) * SCALEF, cb0 = (float)(j - ib) * SCALEF;
        if (j     <= ia) la += __expf(fmaf(sa[nf][0], SCALEF, ca0));
        if (j + 1 <= ia) la += __expf(fmaf(sa[nf][1], SCALEF, ca0 + SCALEF));
        if (j     <= ib) lb += __expf(fmaf(sa[nf][2], SCALEF, cb0));
        if (j + 1 <= ib) lb += __expf(fmaf(sa[nf][3], SCALEF, cb0 + SCALEF));
      }
    }
  }

  la += __shfl_xor_sync(0xffffffffu, la, 1);
  la += __shfl_xor_sync(0xffffffffu, la, 2);
  lb += __shfl_xor_sync(0xffffffffu, lb, 1);
  lb += __shfl_xor_sync(0xffffffffu, lb, 2);
  if (tq == 0) {
    g_lpar[chunk * BB * TT + b * TT + ia] = la;
    g_lpar[chunk * BB * TT + b * TT + ib] = lb;
  }
}

// ---------------- K2b: main pass. grid=(8,64), block=256 ----------------
// Writes FINAL normalized attention (ln(1/l) folded into the exponent),
// accumulates normalized O, atomicAdds into the pre-zeroed out head.
// smem: Qh[128][72]@0 | KV buf0@18432 buf1@55296 (92160 B total)
__global__ __launch_bounds__(256, 2) void attnB(float* __restrict__ out) {
  extern __shared__ char S[];
  const uint32_t QH = 0, KV0 = 18432, KVSZ = 36864;
  const int t = threadIdx.x, w = t >> 5, lane = t & 31;
  const int g = lane >> 2, tq = lane & 3;
  const int b = blockIdx.x;
  const int rt = 15 - ((int)blockIdx.y >> 2), chunk = blockIdx.y & 3;
  const int jt0 = chunk * 8;
  const int ntiles = min(8, 2 * rt + 2 - jt0);
  const int i0 = rt * 128;
  const uint32_t sb = su(S);

  float oa[8][4] = {};
  const int ia = i0 + 16 * w + g, ib = ia + 8;
  float* att = out + (size_t)BB * TT * HH + (size_t)b * TT * TT;

  if (ntiles > 0) {
    float lA = 0.0f, lB = 0.0f;
#pragma unroll
    for (int c = 0; c < 4; c++) {
      lA += g_lpar[c * BB * TT + b * TT + ia];
      lB += g_lpar[c * BB * TT + b * TT + ib];
    }
    const float lna = -__logf(lA), lnb = -__logf(lB);

    const int npairs = ntiles >> 1;
#pragma unroll
    for (int e = 0; e < 4; e++) {
      int idx = t + e * 256, r = idx >> 3, c8 = idx & 7;   // idx < 1024
      size_t gb = ((size_t)(b * TT + i0 + r) * 64 + c8 * 8) * 2;
      cpa16(sb + QH + (uint32_t)(r * 144 + c8 * 16), (const char*)g_qhi + gb);
    }
    {
      const int j0 = jt0 * 64;
#pragma unroll
      for (int e = 0; e < 4; e++) {
        int idx = t + e * 256, r = idx >> 3, c8 = idx & 7;  // idx < 1024
        size_t gb = ((size_t)(b * TT + j0 + r) * 64 + c8 * 8) * 2;
        uint32_t off = KV0 + (uint32_t)(r * 144 + c8 * 16);
        cpa16(sb + off,         (const char*)g_khi + gb);
        cpa16(sb + off + 18432, (const char*)g_vhi + gb);
      }
    }
    CP_COMMIT();

    const uint32_t arow = 16 * w + (lane & 15), aoff8 = (lane >> 4) * 8;
    const uint32_t brow = (lane & 7) + ((lane >> 4) & 1) * 8;
    const uint32_t boff8 = ((lane >> 3) & 1) * 8;
    const uint32_t vrow = (lane & 7) + ((lane >> 3) & 1) * 8;
    const uint32_t voff8 = ((lane >> 4) & 1) * 8;

    for (int it = 0; it < npairs; it++) {
      CP_WAIT0();
      __syncthreads();

      if (it + 1 < npairs) {
        const int jn = (jt0 + 2 * (it + 1)) * 64;
        const uint32_t nb = KV0 + ((it + 1) & 1) * KVSZ;
#pragma unroll
        for (int e = 0; e < 4; e++) {
          int idx = t + e * 256, r = idx >> 3, c8 = idx & 7;
          size_t gb = ((size_t)(b * TT + jn + r) * 64 + c8 * 8) * 2;
          uint32_t off = nb + (uint32_t)(r * 144 + c8 * 16);
          cpa16(sb + off,         (const char*)g_khi + gb);
          cpa16(sb + off + 18432, (const char*)g_vhi + gb);
        }
      }
      CP_COMMIT();

      const uint32_t buf = KV0 + (it & 1) * KVSZ;

#pragma unroll
      for (int half = 0; half < 2; half++) {
        const int j0 = (jt0 + 2 * it + half) * 64;
        const uint32_t KB = buf + half * 9216;
        const uint32_t VB = buf + 18432 + half * 9216;

        float sa[8][4] = {};
#pragma unroll
        for (int s = 0; s < 4; s++) {
          uint32_t ah[4];
          ldsm4(ah, sb + QH + arow * 144 + (s * 16 + aoff8) * 2);
#pragma unroll
          for (int p = 0; p < 4; p++) {
            uint32_t bh[4];
            ldsm4(bh, sb + KB + (p * 16 + brow) * 144 + (s * 16 + boff8) * 2);
            mma16816h(sa[2*p],   ah, bh[0], bh[1]);
            mma16816h(sa[2*p+1], ah, bh[2], bh[3]);
          }
        }

#pragma unroll
        for (int nf = 0; nf < 8; nf++) {
          int j = j0 + nf * 8 + tq * 2;
          float ca0 = fmaf((float)(j - ia), SCALEF, lna);
          float cb0 = fmaf((float)(j - ib), SCALEF, lnb);
          float p00 = (j     <= ia) ? __expf(fmaf(sa[nf][0], SCALEF, ca0)) : 0.0f;
          float p01 = (j + 1 <= ia) ? __expf(fmaf(sa[nf][1], SCALEF, ca0 + SCALEF)) : 0.0f;
          float p10 = (j     <= ib) ? __expf(fmaf(sa[nf][2], SCALEF, cb0)) : 0.0f;
          float p11 = (j + 1 <= ib) ? __expf(fmaf(sa[nf][3], SCALEF, cb0 + SCALEF)) : 0.0f;
          stg2cs(att + (size_t)ia * TT + j, p00, p01);
          stg2cs(att + (size_t)ib * TT + j, p10, p11);
          sa[nf][0] = p00; sa[nf][1] = p01; sa[nf][2] = p10; sa[nf][3] = p11;
        }

#pragma unroll
        for (int s2 = 0; s2 < 4; s2++) {
          uint32_t ah[4];
          ah[0] = packh(sa[2*s2][0],   sa[2*s2][1]);
          ah[1] = packh(sa[2*s2][2],   sa[2*s2][3]);
          ah[2] = packh(sa[2*s2+1][0], sa[2*s2+1][1]);
          ah[3] = packh(sa[2*s2+1][2], sa[2*s2+1][3]);
#pragma unroll
          for (int p = 0; p < 4; p++) {
            uint32_t bh[4];
            ldsm4t(bh, sb + VB + (s2 * 16 + vrow) * 144 + (p * 16 + voff8) * 2);
            mma16816h(oa[2*p],   ah, bh[0], bh[1]);
            mma16816h(oa[2*p+1], ah, bh[2], bh[3]);
          }
        }
      }
    }

    float* opA = out + ((size_t)b * TT + ia) * HH;
    float* opB = out + ((size_t)b * TT + ib) * HH;
#pragma unroll
    for (int nf = 0; nf < 8; nf++) {
      int c = nf * 8 + tq * 2;
      atomicAdd(opA + c,     oa[nf][0]);
      atomicAdd(opA + c + 1, oa[nf][1]);
      atomicAdd(opB + c,     oa[nf][2]);
      atomicAdd(opB + c + 1, oa[nf][3]);
    }
  }

  // ---- zero-fill the strictly-upper part of this block's 512-col strip ----
  {
    const int jf0 = max(jt0, 2 * rt + 2);
    const int nf4 = (jt0 + 8 - jf0) * 16;
    if (nf4 > 0) {
      const float4 z = make_float4(0, 0, 0, 0);
      float4* a4 = (float4*)att;
      for (int r = w; r < 128; r += 8)
        for (int c = lane; c < nf4; c += 32)
          __stcs(&a4[(size_t)(i0 + r) * 512 + jf0 * 16 + c], z);
    }
  }
}

// ---------------------------------------------------------------------------
extern "C" void kernel_launch(void* const* d_in, const int* in_sizes, int n_in,
                              void* d_out, int out_size) {
  const float* x  = (const float*)d_in[0];
  const float* Wq = (const float*)d_in[1];
  const float* Wk = (const float*)d_in[2];
  const float* Wv = (const float*)d_in[3];
  float* out = (float*)d_out;

  k0<<<384, 256>>>(Wq, Wk, Wv);
  kz<<<1024, 256>>>(out);   // zero out-head (atomicAdd target)

  cudaFuncSetAttribute(qkv, cudaFuncAttributeMaxDynamicSharedMemorySize, 92160);
  qkv<<<128, 256, 92160>>>(x);

  cudaFuncSetAttribute(attnA, cudaFuncAttributeMaxDynamicSharedMemorySize, 36864);
  attnA<<<dim3(8, 64), 256, 36864>>>();

  cudaFuncSetAttribute(attnB, cudaFuncAttributeMaxDynamicSharedMemorySize, 92160);
  cudaFuncSetAttribute(attnB, cudaFuncAttributePreferredSharedMemoryCarveout,
                       cudaSharedmemCarveoutMaxShared);
  attnB<<<dim3(8, 64), 256, 92160>>>(out);
}

// round 13
// speedup vs baseline: 4.0343x; 1.0395x over previous
#include <cuda_runtime.h>
#include <cuda_bf16.h>
#include <cuda_fp16.h>
#include <stdint.h>

#define BB 8
#define TT 2048
#define CC 512
#define HH 64
#define SCALEF 0.044194173824159216f   // 512^-0.5

// ---------------- scratch (device globals: allocation-free) ----------------
__device__ __half g_qhi[BB*TT*HH];                    // fp16 (1-term S)
__device__ __half g_khi[BB*TT*HH];                    // fp16, hi only
__device__ __half g_vhi[BB*TT*HH];                    // fp16, hi only
__device__ __nv_bfloat16 g_wthi[3*HH*CC], g_wtlo[3*HH*CC];   // [w][h][c]
__device__ float g_lpar[8*BB*TT];

// ---------------- helpers ----------------
__device__ __forceinline__ uint32_t su(const void* p) {
  uint32_t a;
  asm("{ .reg .u64 t; cvta.to.shared.u64 t, %1; cvt.u32.u64 %0, t; }" : "=r"(a) : "l"(p));
  return a;
}
__device__ __forceinline__ void ldsm4(uint32_t* r, uint32_t a) {
  asm volatile("ldmatrix.sync.aligned.m8n8.x4.shared.b16 {%0,%1,%2,%3}, [%4];"
    : "=r"(r[0]), "=r"(r[1]), "=r"(r[2]), "=r"(r[3]) : "r"(a));
}
__device__ __forceinline__ void ldsm4t(uint32_t* r, uint32_t a) {
  asm volatile("ldmatrix.sync.aligned.m8n8.x4.trans.shared.b16 {%0,%1,%2,%3}, [%4];"
    : "=r"(r[0]), "=r"(r[1]), "=r"(r[2]), "=r"(r[3]) : "r"(a));
}
__device__ __forceinline__ void mma16816(float* d, const uint32_t* a, uint32_t b0, uint32_t b1) {
  asm volatile("mma.sync.aligned.m16n8k16.row.col.f32.bf16.bf16.f32 "
    "{%0,%1,%2,%3}, {%4,%5,%6,%7}, {%8,%9}, {%0,%1,%2,%3};"
    : "+f"(d[0]), "+f"(d[1]), "+f"(d[2]), "+f"(d[3])
    : "r"(a[0]), "r"(a[1]), "r"(a[2]), "r"(a[3]), "r"(b0), "r"(b1));
}
__device__ __forceinline__ void mma16816h(float* d, const uint32_t* a, uint32_t b0, uint32_t b1) {
  asm volatile("mma.sync.aligned.m16n8k16.row.col.f32.f16.f16.f32 "
    "{%0,%1,%2,%3}, {%4,%5,%6,%7}, {%8,%9}, {%0,%1,%2,%3};"
    : "+f"(d[0]), "+f"(d[1]), "+f"(d[2]), "+f"(d[3])
    : "r"(a[0]), "r"(a[1]), "r"(a[2]), "r"(a[3]), "r"(b0), "r"(b1));
}
__device__ __forceinline__ void split_pack(float a, float b, uint32_t& hi, uint32_t& lo) {
  __nv_bfloat162 h = __floats2bfloat162_rn(a, b);
  __nv_bfloat162 l = __floats2bfloat162_rn(a - __bfloat162float(h.x),
                                           b - __bfloat162float(h.y));
  hi = *reinterpret_cast<uint32_t*>(&h);
  lo = *reinterpret_cast<uint32_t*>(&l);
}
__device__ __forceinline__ uint32_t packh(float a, float b) {
  __half2 h = __floats2half2_rn(a, b);
  return *reinterpret_cast<uint32_t*>(&h);
}
__device__ __forceinline__ void cpa16(uint32_t s, const void* g) {
  asm volatile("cp.async.cg.shared.global [%0], [%1], 16;" :: "r"(s), "l"(g) : "memory");
}
__device__ __forceinline__ void stg2cs(float* p, float x, float y) {
  asm volatile("st.global.cs.v2.f32 [%0], {%1, %2};" :: "l"(p), "f"(x), "f"(y) : "memory");
}
#define CP_COMMIT() asm volatile("cp.async.commit_group;" ::: "memory")
#define CP_WAIT0()  asm volatile("cp.async.wait_group 0;" ::: "memory")

// ---------------- K0: weight transpose + split ----------------
__global__ void k0(const float* __restrict__ Wq, const float* __restrict__ Wk,
                   const float* __restrict__ Wv) {
  int idx = blockIdx.x * 256 + threadIdx.x;          // < 3*64*512
  int w = idx >> 15, rem = idx & 32767, h = rem >> 9, c = rem & 511;
  const float* W = (w == 0) ? Wq : ((w == 1) ? Wk : Wv);
  float v = W[(size_t)c * HH + h];
  __nv_bfloat16 hi = __float2bfloat16(v);
  g_wthi[idx] = hi;
  g_wtlo[idx] = __float2bfloat16(v - __bfloat162float(hi));
}

// ---------------- Kz: zero the output head region ----------------
__global__ void kz(float* __restrict__ out) {
  ((float4*)out)[blockIdx.x * 256 + threadIdx.x] = make_float4(0, 0, 0, 0);
}

// ---------------- K1: fused QKV on HMMA. grid=128, block=256 ----------------
__global__ __launch_bounds__(256, 1) void qkv(const float* __restrict__ x) {
  extern __shared__ char S[];
  const uint32_t XH = 0, XL = 18432, WB = 36864;
  const int t = threadIdx.x, w = t >> 5, lane = t & 31;
  const int g = lane >> 2, tq = lane & 3;
  const int row0 = blockIdx.x * 128;
  const uint32_t sb = su(S);
  const uint32_t arow = 16 * w + (lane & 15), aoff8 = (lane >> 4) * 8;
  const uint32_t brow = (lane & 7) + ((lane >> 4) & 1) * 8;
  const uint32_t boff8 = ((lane >> 3) & 1) * 8;

  float acc[3][8][4] = {};

  for (int kci = 0; kci < 8; kci++) {
    __syncthreads();
#pragma unroll
    for (int e = 0; e < 16; e++) {
      int idx = t + e * 256, r = idx >> 5, cp = idx & 31;
      float2 xv = *(const float2*)(x + (size_t)(row0 + r) * CC + kci * 64 + cp * 2);
      uint32_t hi, lo; split_pack(xv.x, xv.y, hi, lo);
      uint32_t off = (uint32_t)(r * 144 + cp * 4);
      *(uint32_t*)(S + XH + off) = hi;
      *(uint32_t*)(S + XL + off) = lo;
    }
#pragma unroll
    for (int e = 0; e < 24; e++) {
      int idx = t + e * 256;                 // < 6144
      int o = idx >> 11, r2 = idx & 2047, h = r2 >> 5, cp = r2 & 31;
      uint32_t gi = (uint32_t)(o * 16384 + h * 256 + kci * 32 + cp);
      uint32_t off = WB + o * 18432 + h * 144 + cp * 4;
      *(uint32_t*)(S + off)        = ((const uint32_t*)g_wthi)[gi];
      *(uint32_t*)(S + off + 9216) = ((const uint32_t*)g_wtlo)[gi];
    }
    __syncthreads();

#pragma unroll
    for (int s = 0; s < 4; s++) {
      uint32_t ah[4], al[4];
      uint32_t qa = sb + XH + arow * 144 + (s * 16 + aoff8) * 2;
      ldsm4(ah, qa);
      ldsm4(al, qa + XL);
#pragma unroll
      for (int o = 0; o < 3; o++) {
        uint32_t base = sb + WB + o * 18432;
#pragma unroll
        for (int p = 0; p < 4; p++) {
          uint32_t bh[4], bl[4];
          uint32_t ka = base + (p * 16 + brow) * 144 + (s * 16 + boff8) * 2;
          ldsm4(bh, ka);
          ldsm4(bl, ka + 9216);
          mma16816(acc[o][2*p],   ah, bh[0], bh[1]);
          mma16816(acc[o][2*p],   al, bh[0], bh[1]);
          mma16816(acc[o][2*p],   ah, bl[0], bl[1]);
          mma16816(acc[o][2*p+1], ah, bh[2], bh[3]);
          mma16816(acc[o][2*p+1], al, bh[2], bh[3]);
          mma16816(acc[o][2*p+1], ah, bl[2], bl[3]);
        }
      }
    }
  }

  const size_t ra = (size_t)(row0 + 16 * w + g), rb = ra + 8;
  {
    uint32_t* dq = (uint32_t*)g_qhi;
    uint32_t* dk = (uint32_t*)g_khi;
    uint32_t* dv = (uint32_t*)g_vhi;
#pragma unroll
    for (int nf = 0; nf < 8; nf++) {
      dq[ra * 32 + nf * 4 + tq] = packh(acc[0][nf][0], acc[0][nf][1]);
      dq[rb * 32 + nf * 4 + tq] = packh(acc[0][nf][2], acc[0][nf][3]);
      dk[ra * 32 + nf * 4 + tq] = packh(acc[1][nf][0], acc[1][nf][1]);
      dk[rb * 32 + nf * 4 + tq] = packh(acc[1][nf][2], acc[1][nf][3]);
      dv[ra * 32 + nf * 4 + tq] = packh(acc[2][nf][0], acc[2][nf][1]);
      dv[rb * 32 + nf * 4 + tq] = packh(acc[2][nf][2], acc[2][nf][3]);
    }
  }
}

// ---------------- K2a: row-sum pass. grid=(8,128), block=256 ----------------
// blockIdx.y -> (rt desc, chunk of 4 jt tiles). smem: Qh@0 | K buf0/buf1
__global__ __launch_bounds__(256, 3) void attnA() {
  extern __shared__ char S[];
  const uint32_t QH = 0, KBASE = 18432, KSZ = 9216;
  const int t = threadIdx.x, w = t >> 5, lane = t & 31;
  const int g = lane >> 2, tq = lane & 3;
  const int b = blockIdx.x;
  const int rt = 15 - ((int)blockIdx.y >> 3), chunk = blockIdx.y & 7;
  const int jt0 = chunk * 4;
  const int ntiles = min(4, 2 * rt + 2 - jt0);
  const int i0 = rt * 128;
  const uint32_t sb = su(S);

  float la = 0.0f, lb = 0.0f;
  const int ia = i0 + 16 * w + g, ib = ia + 8;

  if (ntiles > 0) {
#pragma unroll
    for (int e = 0; e < 4; e++) {
      int idx = t + e * 256, r = idx >> 3, c8 = idx & 7;   // idx < 1024
      size_t gb = ((size_t)(b * TT + i0 + r) * 64 + c8 * 8) * 2;
      cpa16(sb + QH + (uint32_t)(r * 144 + c8 * 16), (const char*)g_qhi + gb);
    }
    {
      const int j0 = jt0 * 64;
#pragma unroll
      for (int e = 0; e < 2; e++) {
        int idx = t + e * 256, r = idx >> 3, c8 = idx & 7;  // idx < 512
        size_t gb = ((size_t)(b * TT + j0 + r) * 64 + c8 * 8) * 2;
        cpa16(sb + KBASE + (uint32_t)(r * 144 + c8 * 16), (const char*)g_khi + gb);
      }
    }
    CP_COMMIT();

    const uint32_t arow = 16 * w + (lane & 15), aoff8 = (lane >> 4) * 8;
    const uint32_t brow = (lane & 7) + ((lane >> 4) & 1) * 8;
    const uint32_t boff8 = ((lane >> 3) & 1) * 8;

    for (int ti = 0; ti < ntiles; ti++) {
      const int j0 = (jt0 + ti) * 64;
      CP_WAIT0();
      __syncthreads();

      if (ti + 1 < ntiles) {
        const int jn = (jt0 + ti + 1) * 64;
        const uint32_t nb = KBASE + ((ti + 1) & 1) * KSZ;
#pragma unroll
        for (int e = 0; e < 2; e++) {
          int idx = t + e * 256, r = idx >> 3, c8 = idx & 7;
          size_t gb = ((size_t)(b * TT + jn + r) * 64 + c8 * 8) * 2;
          cpa16(sb + nb + (uint32_t)(r * 144 + c8 * 16), (const char*)g_khi + gb);
        }
      }
      CP_COMMIT();

      const uint32_t KB = KBASE + (ti & 1) * KSZ;

      float sa[8][4] = {};
#pragma unroll
      for (int s = 0; s < 4; s++) {
        uint32_t ah[4];
        ldsm4(ah, sb + QH + arow * 144 + (s * 16 + aoff8) * 2);
#pragma unroll
        for (int p = 0; p < 4; p++) {
          uint32_t bh[4];
          ldsm4(bh, sb + KB + (p * 16 + brow) * 144 + (s * 16 + boff8) * 2);
          mma16816h(sa[2*p],   ah, bh[0], bh[1]);
          mma16816h(sa[2*p+1], ah, bh[2], bh[3]);
        }
      }

#pragma unroll
      for (int nf = 0; nf < 8; nf++) {
        int j = j0 + nf * 8 + tq * 2;
        float ca0 = (float)(j - ia) * SCALEF, cb0 = (float)(j - ib) * SCALEF;
        if (j     <= ia) la += __expf(fmaf(sa[nf][0], SCALEF, ca0));
        if (j + 1 <= ia) la += __expf(fmaf(sa[nf][1], SCALEF, ca0 + SCALEF));
        if (j     <= ib) lb += __expf(fmaf(sa[nf][2], SCALEF, cb0));
        if (j + 1 <= ib) lb += __expf(fmaf(sa[nf][3], SCALEF, cb0 + SCALEF));
      }
    }
  }

  la += __shfl_xor_sync(0xffffffffu, la, 1);
  la += __shfl_xor_sync(0xffffffffu, la, 2);
  lb += __shfl_xor_sync(0xffffffffu, lb, 1);
  lb += __shfl_xor_sync(0xffffffffu, lb, 2);
  if (tq == 0) {
    g_lpar[chunk * BB * TT + b * TT + ia] = la;
    g_lpar[chunk * BB * TT + b * TT + ib] = lb;
  }
}

// ---------------- K2b: main pass. grid=(8,128), block=256 ----------------
// Writes FINAL normalized attention (ln(1/l) folded into the exponent),
// accumulates normalized O, atomicAdds into the pre-zeroed out head.
// smem: Qh[128][72]@0 | KV pair buf0@18432 buf1@55296 (92160 B total)
__global__ __launch_bounds__(256, 2) void attnB(float* __restrict__ out) {
  extern __shared__ char S[];
  const uint32_t QH = 0, KV0 = 18432, KVSZ = 36864;
  const int t = threadIdx.x, w = t >> 5, lane = t & 31;
  const int g = lane >> 2, tq = lane & 3;
  const int b = blockIdx.x;
  const int rt = 15 - ((int)blockIdx.y >> 3), chunk = blockIdx.y & 7;
  const int jt0 = chunk * 4;
  const int ntiles = min(4, 2 * rt + 2 - jt0);
  const int i0 = rt * 128;
  const uint32_t sb = su(S);

  float oa[8][4] = {};
  const int ia = i0 + 16 * w + g, ib = ia + 8;
  float* att = out + (size_t)BB * TT * HH + (size_t)b * TT * TT;

  if (ntiles > 0) {
    float lA = 0.0f, lB = 0.0f;
#pragma unroll
    for (int c = 0; c < 8; c++) {
      lA += g_lpar[c * BB * TT + b * TT + ia];
      lB += g_lpar[c * BB * TT + b * TT + ib];
    }
    const float lna = -__logf(lA), lnb = -__logf(lB);

    const int npairs = ntiles >> 1;            // ntiles even (2 or 4)
#pragma unroll
    for (int e = 0; e < 4; e++) {
      int idx = t + e * 256, r = idx >> 3, c8 = idx & 7;   // idx < 1024
      size_t gb = ((size_t)(b * TT + i0 + r) * 64 + c8 * 8) * 2;
      cpa16(sb + QH + (uint32_t)(r * 144 + c8 * 16), (const char*)g_qhi + gb);
    }
    {
      const int j0 = jt0 * 64;
#pragma unroll
      for (int e = 0; e < 4; e++) {
        int idx = t + e * 256, r = idx >> 3, c8 = idx & 7;  // idx < 1024
        size_t gb = ((size_t)(b * TT + j0 + r) * 64 + c8 * 8) * 2;
        uint32_t off = KV0 + (uint32_t)(r * 144 + c8 * 16);
        cpa16(sb + off,         (const char*)g_khi + gb);
        cpa16(sb + off + 18432, (const char*)g_vhi + gb);
      }
    }
    CP_COMMIT();

    const uint32_t arow = 16 * w + (lane & 15), aoff8 = (lane >> 4) * 8;
    const uint32_t brow = (lane & 7) + ((lane >> 4) & 1) * 8;
    const uint32_t boff8 = ((lane >> 3) & 1) * 8;
    const uint32_t vrow = (lane & 7) + ((lane >> 3) & 1) * 8;
    const uint32_t voff8 = ((lane >> 4) & 1) * 8;

    for (int it = 0; it < npairs; it++) {
      CP_WAIT0();
      __syncthreads();

      if (it + 1 < npairs) {
        const int jn = (jt0 + 2 * (it + 1)) * 64;
        const uint32_t nb = KV0 + ((it + 1) & 1) * KVSZ;
#pragma unroll
        for (int e = 0; e < 4; e++) {
          int idx = t + e * 256, r = idx >> 3, c8 = idx & 7;
          size_t gb = ((size_t)(b * TT + jn + r) * 64 + c8 * 8) * 2;
          uint32_t off = nb + (uint32_t)(r * 144 + c8 * 16);
          cpa16(sb + off,         (const char*)g_khi + gb);
          cpa16(sb + off + 18432, (const char*)g_vhi + gb);
        }
      }
      CP_COMMIT();

      const uint32_t buf = KV0 + (it & 1) * KVSZ;

#pragma unroll
      for (int half = 0; half < 2; half++) {
        const int j0 = (jt0 + 2 * it + half) * 64;
        const uint32_t KB = buf + half * 9216;
        const uint32_t VB = buf + 18432 + half * 9216;

        float sa[8][4] = {};
#pragma unroll
        for (int s = 0; s < 4; s++) {
          uint32_t ah[4];
          ldsm4(ah, sb + QH + arow * 144 + (s * 16 + aoff8) * 2);
#pragma unroll
          for (int p = 0; p < 4; p++) {
            uint32_t bh[4];
            ldsm4(bh, sb + KB + (p * 16 + brow) * 144 + (s * 16 + boff8) * 2);
            mma16816h(sa[2*p],   ah, bh[0], bh[1]);
            mma16816h(sa[2*p+1], ah, bh[2], bh[3]);
          }
        }

#pragma unroll
        for (int nf = 0; nf < 8; nf++) {
          int j = j0 + nf * 8 + tq * 2;
          float ca0 = fmaf((float)(j - ia), SCALEF, lna);
          float cb0 = fmaf((float)(j - ib), SCALEF, lnb);
          float p00 = (j     <= ia) ? __expf(fmaf(sa[nf][0], SCALEF, ca0)) : 0.0f;
          float p01 = (j + 1 <= ia) ? __expf(fmaf(sa[nf][1], SCALEF, ca0 + SCALEF)) : 0.0f;
          float p10 = (j     <= ib) ? __expf(fmaf(sa[nf][2], SCALEF, cb0)) : 0.0f;
          float p11 = (j + 1 <= ib) ? __expf(fmaf(sa[nf][3], SCALEF, cb0 + SCALEF)) : 0.0f;
          stg2cs(att + (size_t)ia * TT + j, p00, p01);
          stg2cs(att + (size_t)ib * TT + j, p10, p11);
          sa[nf][0] = p00; sa[nf][1] = p01; sa[nf][2] = p10; sa[nf][3] = p11;
        }

#pragma unroll
        for (int s2 = 0; s2 < 4; s2++) {
          uint32_t ah[4];
          ah[0] = packh(sa[2*s2][0],   sa[2*s2][1]);
          ah[1] = packh(sa[2*s2][2],   sa[2*s2][3]);
          ah[2] = packh(sa[2*s2+1][0], sa[2*s2+1][1]);
          ah[3] = packh(sa[2*s2+1][2], sa[2*s2+1][3]);
#pragma unroll
          for (int p = 0; p < 4; p++) {
            uint32_t bh[4];
            ldsm4t(bh, sb + VB + (s2 * 16 + vrow) * 144 + (p * 16 + voff8) * 2);
            mma16816h(oa[2*p],   ah, bh[0], bh[1]);
            mma16816h(oa[2*p+1], ah, bh[2], bh[3]);
          }
        }
      }
    }

    float* opA = out + ((size_t)b * TT + ia) * HH;
    float* opB = out + ((size_t)b * TT + ib) * HH;
#pragma unroll
    for (int nf = 0; nf < 8; nf++) {
      int c = nf * 8 + tq * 2;
      atomicAdd(opA + c,     oa[nf][0]);
      atomicAdd(opA + c + 1, oa[nf][1]);
      atomicAdd(opB + c,     oa[nf][2]);
      atomicAdd(opB + c + 1, oa[nf][3]);
    }
  }

  // ---- zero-fill the strictly-upper part of this block's 256-col strip ----
  {
    const int jf0 = max(jt0, 2 * rt + 2);
    const int nf4 = (jt0 + 4 - jf0) * 16;
    if (nf4 > 0) {
      const float4 z = make_float4(0, 0, 0, 0);
      float4* a4 = (float4*)att;
      for (int r = w; r < 128; r += 8)
        for (int c = lane; c < nf4; c += 32)
          __stcs(&a4[(size_t)(i0 + r) * 512 + jf0 * 16 + c], z);
    }
  }
}

// ---------------------------------------------------------------------------
extern "C" void kernel_launch(void* const* d_in, const int* in_sizes, int n_in,
                              void* d_out, int out_size) {
  const float* x  = (const float*)d_in[0];
  const float* Wq = (const float*)d_in[1];
  const float* Wk = (const float*)d_in[2];
  const float* Wv = (const float*)d_in[3];
  float* out = (float*)d_out;

  k0<<<384, 256>>>(Wq, Wk, Wv);
  kz<<<1024, 256>>>(out);   // zero out-head (atomicAdd target)

  cudaFuncSetAttribute(qkv, cudaFuncAttributeMaxDynamicSharedMemorySize, 92160);
  qkv<<<128, 256, 92160>>>(x);

  cudaFuncSetAttribute(attnA, cudaFuncAttributeMaxDynamicSharedMemorySize, 36864);
  attnA<<<dim3(8, 128), 256, 36864>>>();

  cudaFuncSetAttribute(attnB, cudaFuncAttributeMaxDynamicSharedMemorySize, 92160);
  cudaFuncSetAttribute(attnB, cudaFuncAttributePreferredSharedMemoryCarveout,
                       cudaSharedmemCarveoutMaxShared);
  attnB<<<dim3(8, 128), 256, 92160>>>(out);
}

// round 14
// speedup vs baseline: 4.2545x; 1.0546x over previous
#include <cuda_runtime.h>
#include <cuda_bf16.h>
#include <cuda_fp16.h>
#include <stdint.h>

#define BB 8
#define TT 2048
#define CC 512
#define HH 64
#define SCALEF 0.044194173824159216f   // 512^-0.5
#define C2F    0.063762484904288f      // SCALEF * log2(e)

// ---------------- scratch (device globals: allocation-free) ----------------
__device__ __half g_qhi[BB*TT*HH];                    // fp16 (1-term S)
__device__ __half g_khi[BB*TT*HH];                    // fp16, hi only
__device__ __half g_vhi[BB*TT*HH];                    // fp16, hi only
__device__ __nv_bfloat16 g_wthi[3*HH*CC], g_wtlo[3*HH*CC];   // [w][h][c]
__device__ float g_lpar[8*BB*TT];

// ---------------- helpers ----------------
__device__ __forceinline__ uint32_t su(const void* p) {
  uint32_t a;
  asm("{ .reg .u64 t; cvta.to.shared.u64 t, %1; cvt.u32.u64 %0, t; }" : "=r"(a) : "l"(p));
  return a;
}
__device__ __forceinline__ void ldsm4(uint32_t* r, uint32_t a) {
  asm volatile("ldmatrix.sync.aligned.m8n8.x4.shared.b16 {%0,%1,%2,%3}, [%4];"
    : "=r"(r[0]), "=r"(r[1]), "=r"(r[2]), "=r"(r[3]) : "r"(a));
}
__device__ __forceinline__ void ldsm4t(uint32_t* r, uint32_t a) {
  asm volatile("ldmatrix.sync.aligned.m8n8.x4.trans.shared.b16 {%0,%1,%2,%3}, [%4];"
    : "=r"(r[0]), "=r"(r[1]), "=r"(r[2]), "=r"(r[3]) : "r"(a));
}
__device__ __forceinline__ void mma16816(float* d, const uint32_t* a, uint32_t b0, uint32_t b1) {
  asm volatile("mma.sync.aligned.m16n8k16.row.col.f32.bf16.bf16.f32 "
    "{%0,%1,%2,%3}, {%4,%5,%6,%7}, {%8,%9}, {%0,%1,%2,%3};"
    : "+f"(d[0]), "+f"(d[1]), "+f"(d[2]), "+f"(d[3])
    : "r"(a[0]), "r"(a[1]), "r"(a[2]), "r"(a[3]), "r"(b0), "r"(b1));
}
__device__ __forceinline__ void mma16816h(float* d, const uint32_t* a, uint32_t b0, uint32_t b1) {
  asm volatile("mma.sync.aligned.m16n8k16.row.col.f32.f16.f16.f32 "
    "{%0,%1,%2,%3}, {%4,%5,%6,%7}, {%8,%9}, {%0,%1,%2,%3};"
    : "+f"(d[0]), "+f"(d[1]), "+f"(d[2]), "+f"(d[3])
    : "r"(a[0]), "r"(a[1]), "r"(a[2]), "r"(a[3]), "r"(b0), "r"(b1));
}
__device__ __forceinline__ void split_pack(float a, float b, uint32_t& hi, uint32_t& lo) {
  __nv_bfloat162 h = __floats2bfloat162_rn(a, b);
  __nv_bfloat162 l = __floats2bfloat162_rn(a - __bfloat162float(h.x),
                                           b - __bfloat162float(h.y));
  hi = *reinterpret_cast<uint32_t*>(&h);
  lo = *reinterpret_cast<uint32_t*>(&l);
}
__device__ __forceinline__ uint32_t packh(float a, float b) {
  __half2 h = __floats2half2_rn(a, b);
  return *reinterpret_cast<uint32_t*>(&h);
}
__device__ __forceinline__ void cpa16(uint32_t s, const void* g) {
  asm volatile("cp.async.cg.shared.global [%0], [%1], 16;" :: "r"(s), "l"(g) : "memory");
}
__device__ __forceinline__ void stg2cs(float* p, float x, float y) {
  asm volatile("st.global.cs.v2.f32 [%0], {%1, %2};" :: "l"(p), "f"(x), "f"(y) : "memory");
}
#define CP_COMMIT() asm volatile("cp.async.commit_group;" ::: "memory")
#define CP_WAIT0()  asm volatile("cp.async.wait_group 0;" ::: "memory")

// ---------------- K0: weight transpose + split ----------------
__global__ void k0(const float* __restrict__ Wq, const float* __restrict__ Wk,
                   const float* __restrict__ Wv) {
  int idx = blockIdx.x * 256 + threadIdx.x;          // < 3*64*512
  int w = idx >> 15, rem = idx & 32767, h = rem >> 9, c = rem & 511;
  const float* W = (w == 0) ? Wq : ((w == 1) ? Wk : Wv);
  float v = W[(size_t)c * HH + h];
  __nv_bfloat16 hi = __float2bfloat16(v);
  g_wthi[idx] = hi;
  g_wtlo[idx] = __float2bfloat16(v - __bfloat162float(hi));
}

// ---------------- Kz: zero the output head region ----------------
__global__ void kz(float* __restrict__ out) {
  ((float4*)out)[blockIdx.x * 256 + threadIdx.x] = make_float4(0, 0, 0, 0);
}

// ---------------- K1: fused QKV on HMMA. grid=128, block=256 ----------------
__global__ __launch_bounds__(256, 1) void qkv(const float* __restrict__ x) {
  extern __shared__ char S[];
  const uint32_t XH = 0, XL = 18432, WB = 36864;
  const int t = threadIdx.x, w = t >> 5, lane = t & 31;
  const int g = lane >> 2, tq = lane & 3;
  const int row0 = blockIdx.x * 128;
  const uint32_t sb = su(S);
  const uint32_t arow = 16 * w + (lane & 15), aoff8 = (lane >> 4) * 8;
  const uint32_t brow = (lane & 7) + ((lane >> 4) & 1) * 8;
  const uint32_t boff8 = ((lane >> 3) & 1) * 8;

  float acc[3][8][4] = {};

  for (int kci = 0; kci < 8; kci++) {
    __syncthreads();
#pragma unroll
    for (int e = 0; e < 16; e++) {
      int idx = t + e * 256, r = idx >> 5, cp = idx & 31;
      float2 xv = *(const float2*)(x + (size_t)(row0 + r) * CC + kci * 64 + cp * 2);
      uint32_t hi, lo; split_pack(xv.x, xv.y, hi, lo);
      uint32_t off = (uint32_t)(r * 144 + cp * 4);
      *(uint32_t*)(S + XH + off) = hi;
      *(uint32_t*)(S + XL + off) = lo;
    }
#pragma unroll
    for (int e = 0; e < 24; e++) {
      int idx = t + e * 256;                 // < 6144
      int o = idx >> 11, r2 = idx & 2047, h = r2 >> 5, cp = r2 & 31;
      uint32_t gi = (uint32_t)(o * 16384 + h * 256 + kci * 32 + cp);
      uint32_t off = WB + o * 18432 + h * 144 + cp * 4;
      *(uint32_t*)(S + off)        = ((const uint32_t*)g_wthi)[gi];
      *(uint32_t*)(S + off + 9216) = ((const uint32_t*)g_wtlo)[gi];
    }
    __syncthreads();

#pragma unroll
    for (int s = 0; s < 4; s++) {
      uint32_t ah[4], al[4];
      uint32_t qa = sb + XH + arow * 144 + (s * 16 + aoff8) * 2;
      ldsm4(ah, qa);
      ldsm4(al, qa + XL);
#pragma unroll
      for (int o = 0; o < 3; o++) {
        uint32_t base = sb + WB + o * 18432;
#pragma unroll
        for (int p = 0; p < 4; p++) {
          uint32_t bh[4], bl[4];
          uint32_t ka = base + (p * 16 + brow) * 144 + (s * 16 + boff8) * 2;
          ldsm4(bh, ka);
          ldsm4(bl, ka + 9216);
          mma16816(acc[o][2*p],   ah, bh[0], bh[1]);
          mma16816(acc[o][2*p],   al, bh[0], bh[1]);
          mma16816(acc[o][2*p],   ah, bl[0], bl[1]);
          mma16816(acc[o][2*p+1], ah, bh[2], bh[3]);
          mma16816(acc[o][2*p+1], al, bh[2], bh[3]);
          mma16816(acc[o][2*p+1], ah, bl[2], bl[3]);
        }
      }
    }
  }

  const size_t ra = (size_t)(row0 + 16 * w + g), rb = ra + 8;
  {
    uint32_t* dq = (uint32_t*)g_qhi;
    uint32_t* dk = (uint32_t*)g_khi;
    uint32_t* dv = (uint32_t*)g_vhi;
#pragma unroll
    for (int nf = 0; nf < 8; nf++) {
      dq[ra * 32 + nf * 4 + tq] = packh(acc[0][nf][0], acc[0][nf][1]);
      dq[rb * 32 + nf * 4 + tq] = packh(acc[0][nf][2], acc[0][nf][3]);
      dk[ra * 32 + nf * 4 + tq] = packh(acc[1][nf][0], acc[1][nf][1]);
      dk[rb * 32 + nf * 4 + tq] = packh(acc[1][nf][2], acc[1][nf][3]);
      dv[ra * 32 + nf * 4 + tq] = packh(acc[2][nf][0], acc[2][nf][1]);
      dv[rb * 32 + nf * 4 + tq] = packh(acc[2][nf][2], acc[2][nf][3]);
    }
  }
}

// ---------------- K2a: row-sum pass. grid=(8,128), block=256 ----------------
// blockIdx.y -> (rt desc, chunk of 4 jt tiles). smem: Qh@0 | K buf0/buf1
__global__ __launch_bounds__(256, 3) void attnA() {
  extern __shared__ char S[];
  const uint32_t QH = 0, KBASE = 18432, KSZ = 9216;
  const int t = threadIdx.x, w = t >> 5, lane = t & 31;
  const int g = lane >> 2, tq = lane & 3;
  const int b = blockIdx.x;
  const int rt = 15 - ((int)blockIdx.y >> 3), chunk = blockIdx.y & 7;
  const int jt0 = chunk * 4;
  const int ntiles = min(4, 2 * rt + 2 - jt0);
  const int i0 = rt * 128;
  const uint32_t sb = su(S);

  float la = 0.0f, lb = 0.0f;
  const int ia = i0 + 16 * w + g, ib = ia + 8;

  if (ntiles > 0) {
#pragma unroll
    for (int e = 0; e < 4; e++) {
      int idx = t + e * 256, r = idx >> 3, c8 = idx & 7;   // idx < 1024
      size_t gb = ((size_t)(b * TT + i0 + r) * 64 + c8 * 8) * 2;
      cpa16(sb + QH + (uint32_t)(r * 144 + c8 * 16), (const char*)g_qhi + gb);
    }
    {
      const int j0 = jt0 * 64;
#pragma unroll
      for (int e = 0; e < 2; e++) {
        int idx = t + e * 256, r = idx >> 3, c8 = idx & 7;  // idx < 512
        size_t gb = ((size_t)(b * TT + j0 + r) * 64 + c8 * 8) * 2;
        cpa16(sb + KBASE + (uint32_t)(r * 144 + c8 * 16), (const char*)g_khi + gb);
      }
    }
    CP_COMMIT();

    const uint32_t arow = 16 * w + (lane & 15), aoff8 = (lane >> 4) * 8;
    const uint32_t brow = (lane & 7) + ((lane >> 4) & 1) * 8;
    const uint32_t boff8 = ((lane >> 3) & 1) * 8;

    for (int ti = 0; ti < ntiles; ti++) {
      const int j0 = (jt0 + ti) * 64;
      CP_WAIT0();
      __syncthreads();

      if (ti + 1 < ntiles) {
        const int jn = (jt0 + ti + 1) * 64;
        const uint32_t nb = KBASE + ((ti + 1) & 1) * KSZ;
#pragma unroll
        for (int e = 0; e < 2; e++) {
          int idx = t + e * 256, r = idx >> 3, c8 = idx & 7;
          size_t gb = ((size_t)(b * TT + jn + r) * 64 + c8 * 8) * 2;
          cpa16(sb + nb + (uint32_t)(r * 144 + c8 * 16), (const char*)g_khi + gb);
        }
      }
      CP_COMMIT();

      const uint32_t KB = KBASE + (ti & 1) * KSZ;

      float sa[8][4] = {};
#pragma unroll
      for (int s = 0; s < 4; s++) {
        uint32_t ah[4];
        ldsm4(ah, sb + QH + arow * 144 + (s * 16 + aoff8) * 2);
#pragma unroll
        for (int p = 0; p < 4; p++) {
          uint32_t bh[4];
          ldsm4(bh, sb + KB + (p * 16 + brow) * 144 + (s * 16 + boff8) * 2);
          mma16816h(sa[2*p],   ah, bh[0], bh[1]);
          mma16816h(sa[2*p+1], ah, bh[2], bh[3]);
        }
      }

      if (j0 + 64 <= i0) {
        // full tile: no causal predicates
#pragma unroll
        for (int nf = 0; nf < 8; nf++) {
          int j = j0 + nf * 8 + tq * 2;
          float ca0 = (float)(j - ia) * C2F, cb0 = (float)(j - ib) * C2F;
          la += exp2f(fmaf(sa[nf][0], C2F, ca0));
          la += exp2f(fmaf(sa[nf][1], C2F, ca0 + C2F));
          lb += exp2f(fmaf(sa[nf][2], C2F, cb0));
          lb += exp2f(fmaf(sa[nf][3], C2F, cb0 + C2F));
        }
      } else {
#pragma unroll
        for (int nf = 0; nf < 8; nf++) {
          int j = j0 + nf * 8 + tq * 2;
          float ca0 = (float)(j - ia) * C2F, cb0 = (float)(j - ib) * C2F;
          if (j     <= ia) la += exp2f(fmaf(sa[nf][0], C2F, ca0));
          if (j + 1 <= ia) la += exp2f(fmaf(sa[nf][1], C2F, ca0 + C2F));
          if (j     <= ib) lb += exp2f(fmaf(sa[nf][2], C2F, cb0));
          if (j + 1 <= ib) lb += exp2f(fmaf(sa[nf][3], C2F, cb0 + C2F));
        }
      }
    }
  }

  la += __shfl_xor_sync(0xffffffffu, la, 1);
  la += __shfl_xor_sync(0xffffffffu, la, 2);
  lb += __shfl_xor_sync(0xffffffffu, lb, 1);
  lb += __shfl_xor_sync(0xffffffffu, lb, 2);
  if (tq == 0) {
    g_lpar[chunk * BB * TT + b * TT + ia] = la;
    g_lpar[chunk * BB * TT + b * TT + ib] = lb;
  }
}

// ---------------- K2b: main pass. grid=(8,128), block=256 ----------------
// Writes FINAL normalized attention (log2(1/l) folded into the exponent),
// accumulates normalized O, atomicAdds into the pre-zeroed out head.
// smem: Qh[128][72]@0 | KV pair buf0@18432 buf1@55296 (92160 B total)
__global__ __launch_bounds__(256, 2) void attnB(float* __restrict__ out) {
  extern __shared__ char S[];
  const uint32_t QH = 0, KV0 = 18432, KVSZ = 36864;
  const int t = threadIdx.x, w = t >> 5, lane = t & 31;
  const int g = lane >> 2, tq = lane & 3;
  const int b = blockIdx.x;
  const int rt = 15 - ((int)blockIdx.y >> 3), chunk = blockIdx.y & 7;
  const int jt0 = chunk * 4;
  const int ntiles = min(4, 2 * rt + 2 - jt0);
  const int i0 = rt * 128;
  const uint32_t sb = su(S);

  float oa[8][4] = {};
  const int ia = i0 + 16 * w + g, ib = ia + 8;
  float* att = out + (size_t)BB * TT * HH + (size_t)b * TT * TT;

  if (ntiles > 0) {
    float lA = 0.0f, lB = 0.0f;
#pragma unroll
    for (int c = 0; c < 8; c++) {
      lA += g_lpar[c * BB * TT + b * TT + ia];
      lB += g_lpar[c * BB * TT + b * TT + ib];
    }
    const float lna = -__log2f(lA), lnb = -__log2f(lB);

    const int npairs = ntiles >> 1;            // ntiles even (2 or 4)
#pragma unroll
    for (int e = 0; e < 4; e++) {
      int idx = t + e * 256, r = idx >> 3, c8 = idx & 7;   // idx < 1024
      size_t gb = ((size_t)(b * TT + i0 + r) * 64 + c8 * 8) * 2;
      cpa16(sb + QH + (uint32_t)(r * 144 + c8 * 16), (const char*)g_qhi + gb);
    }
    {
      const int j0 = jt0 * 64;
#pragma unroll
      for (int e = 0; e < 4; e++) {
        int idx = t + e * 256, r = idx >> 3, c8 = idx & 7;  // idx < 1024
        size_t gb = ((size_t)(b * TT + j0 + r) * 64 + c8 * 8) * 2;
        uint32_t off = KV0 + (uint32_t)(r * 144 + c8 * 16);
        cpa16(sb + off,         (const char*)g_khi + gb);
        cpa16(sb + off + 18432, (const char*)g_vhi + gb);
      }
    }
    CP_COMMIT();

    const uint32_t arow = 16 * w + (lane & 15), aoff8 = (lane >> 4) * 8;
    const uint32_t brow = (lane & 7) + ((lane >> 4) & 1) * 8;
    const uint32_t boff8 = ((lane >> 3) & 1) * 8;
    const uint32_t vrow = (lane & 7) + ((lane >> 3) & 1) * 8;
    const uint32_t voff8 = ((lane >> 4) & 1) * 8;

    for (int it = 0; it < npairs; it++) {
      CP_WAIT0();
      __syncthreads();

      if (it + 1 < npairs) {
        const int jn = (jt0 + 2 * (it + 1)) * 64;
        const uint32_t nb = KV0 + ((it + 1) & 1) * KVSZ;
#pragma unroll
        for (int e = 0; e < 4; e++) {
          int idx = t + e * 256, r = idx >> 3, c8 = idx & 7;
          size_t gb = ((size_t)(b * TT + jn + r) * 64 + c8 * 8) * 2;
          uint32_t off = nb + (uint32_t)(r * 144 + c8 * 16);
          cpa16(sb + off,         (const char*)g_khi + gb);
          cpa16(sb + off + 18432, (const char*)g_vhi + gb);
        }
      }
      CP_COMMIT();

      const uint32_t buf = KV0 + (it & 1) * KVSZ;

#pragma unroll
      for (int half = 0; half < 2; half++) {
        const int j0 = (jt0 + 2 * it + half) * 64;
        const uint32_t KB = buf + half * 9216;
        const uint32_t VB = buf + 18432 + half * 9216;

        float sa[8][4] = {};
#pragma unroll
        for (int s = 0; s < 4; s++) {
          uint32_t ah[4];
          ldsm4(ah, sb + QH + arow * 144 + (s * 16 + aoff8) * 2);
#pragma unroll
          for (int p = 0; p < 4; p++) {
            uint32_t bh[4];
            ldsm4(bh, sb + KB + (p * 16 + brow) * 144 + (s * 16 + boff8) * 2);
            mma16816h(sa[2*p],   ah, bh[0], bh[1]);
            mma16816h(sa[2*p+1], ah, bh[2], bh[3]);
          }
        }

        if (j0 + 64 <= i0) {
          // full tile: no causal predicates
#pragma unroll
          for (int nf = 0; nf < 8; nf++) {
            int j = j0 + nf * 8 + tq * 2;
            float ca0 = fmaf((float)(j - ia), C2F, lna);
            float cb0 = fmaf((float)(j - ib), C2F, lnb);
            float p00 = exp2f(fmaf(sa[nf][0], C2F, ca0));
            float p01 = exp2f(fmaf(sa[nf][1], C2F, ca0 + C2F));
            float p10 = exp2f(fmaf(sa[nf][2], C2F, cb0));
            float p11 = exp2f(fmaf(sa[nf][3], C2F, cb0 + C2F));
            stg2cs(att + (size_t)ia * TT + j, p00, p01);
            stg2cs(att + (size_t)ib * TT + j, p10, p11);
            sa[nf][0] = p00; sa[nf][1] = p01; sa[nf][2] = p10; sa[nf][3] = p11;
          }
        } else {
#pragma unroll
          for (int nf = 0; nf < 8; nf++) {
            int j = j0 + nf * 8 + tq * 2;
            float ca0 = fmaf((float)(j - ia), C2F, lna);
            float cb0 = fmaf((float)(j - ib), C2F, lnb);
            float p00 = (j     <= ia) ? exp2f(fmaf(sa[nf][0], C2F, ca0)) : 0.0f;
            float p01 = (j + 1 <= ia) ? exp2f(fmaf(sa[nf][1], C2F, ca0 + C2F)) : 0.0f;
            float p10 = (j     <= ib) ? exp2f(fmaf(sa[nf][2], C2F, cb0)) : 0.0f;
            float p11 = (j + 1 <= ib) ? exp2f(fmaf(sa[nf][3], C2F, cb0 + C2F)) : 0.0f;
            stg2cs(att + (size_t)ia * TT + j, p00, p01);
            stg2cs(att + (size_t)ib * TT + j, p10, p11);
            sa[nf][0] = p00; sa[nf][1] = p01; sa[nf][2] = p10; sa[nf][3] = p11;
          }
        }

#pragma unroll
        for (int s2 = 0; s2 < 4; s2++) {
          uint32_t ah[4];
          ah[0] = packh(sa[2*s2][0],   sa[2*s2][1]);
          ah[1] = packh(sa[2*s2][2],   sa[2*s2][3]);
          ah[2] = packh(sa[2*s2+1][0], sa[2*s2+1][1]);
          ah[3] = packh(sa[2*s2+1][2], sa[2*s2+1][3]);
#pragma unroll
          for (int p = 0; p < 4; p++) {
            uint32_t bh[4];
            ldsm4t(bh, sb + VB + (s2 * 16 + vrow) * 144 + (p * 16 + voff8) * 2);
            mma16816h(oa[2*p],   ah, bh[0], bh[1]);
            mma16816h(oa[2*p+1], ah, bh[2], bh[3]);
          }
        }
      }
    }

    float* opA = out + ((size_t)b * TT + ia) * HH;
    float* opB = out + ((size_t)b * TT + ib) * HH;
#pragma unroll
    for (int nf = 0; nf < 8; nf++) {
      int c = nf * 8 + tq * 2;
      atomicAdd(opA + c,     oa[nf][0]);
      atomicAdd(opA + c + 1, oa[nf][1]);
      atomicAdd(opB + c,     oa[nf][2]);
      atomicAdd(opB + c + 1, oa[nf][3]);
    }
  }

  // ---- zero-fill the strictly-upper part of this block's 256-col strip ----
  {
    const int jf0 = max(jt0, 2 * rt + 2);
    const int nf4 = (jt0 + 4 - jf0) * 16;
    if (nf4 > 0) {
      const float4 z = make_float4(0, 0, 0, 0);
      float4* a4 = (float4*)att;
      for (int r = w; r < 128; r += 8)
        for (int c = lane; c < nf4; c += 32)
          __stcs(&a4[(size_t)(i0 + r) * 512 + jf0 * 16 + c], z);
    }
  }
}

// ---------------------------------------------------------------------------
extern "C" void kernel_launch(void* const* d_in, const int* in_sizes, int n_in,
                              void* d_out, int out_size) {
  const float* x  = (const float*)d_in[0];
  const float* Wq = (const float*)d_in[1];
  const float* Wk = (const float*)d_in[2];
  const float* Wv = (const float*)d_in[3];
  float* out = (float*)d_out;

  k0<<<384, 256>>>(Wq, Wk, Wv);
  kz<<<1024, 256>>>(out);   // zero out-head (atomicAdd target)

  cudaFuncSetAttribute(qkv, cudaFuncAttributeMaxDynamicSharedMemorySize, 92160);
  qkv<<<128, 256, 92160>>>(x);

  cudaFuncSetAttribute(attnA, cudaFuncAttributeMaxDynamicSharedMemorySize, 36864);
  attnA<<<dim3(8, 128), 256, 36864>>>();

  cudaFuncSetAttribute(attnB, cudaFuncAttributeMaxDynamicSharedMemorySize, 92160);
  cudaFuncSetAttribute(attnB, cudaFuncAttributePreferredSharedMemoryCarveout,
                       cudaSharedmemCarveoutMaxShared);
  attnB<<<dim3(8, 128), 256, 92160>>>(out);
}